// round 2
// baseline (speedup 1.0000x reference)
#include <cuda_runtime.h>
#include <cstdint>
#include <math.h>

#define BB 16
#define NN_ 1024
#define DOUT 64
#define EDIM 16
#define WINDOW 12
#define NNSQ (NN_*NN_)          /* 1048576 */
#define BNN (BB*NNSQ)           /* 16777216 */
#define HALF_BNN (BNN/2)        /* 8388608 */

#define OFF_MASK (BB*NN_*DOUT)          /* 1048576 */
#define OFF_LOSS (OFF_MASK + BNN)       /* 17825792 */

// ---------------- scratch (device globals; no dynamic alloc allowed) -------
__device__ float g_E[NN_*EDIM];
__device__ float g_Et[EDIM*NN_];
__device__ float g_EM[NNSQ];
__device__ float g_supports[NNSQ];
__device__ float g_sup[(size_t)BB*NNSQ];            // 64 MB
__device__ float g_Wn_r[(size_t)NN_*256*128];       // 134 MB
__device__ float g_Wn_u[(size_t)NN_*256*64];        // 67 MB
__device__ float g_bias_r[NN_*128];
__device__ float g_bias_u[NN_*64];
__device__ float g_xb[(size_t)BB*NN_*128];          // sup @ cat(x,state)
__device__ float g_zs[(size_t)BB*NN_*64];           // z * state
__device__ float g_rb[(size_t)BB*NN_*64];           // r gate
__device__ float g_c2[(size_t)BB*NN_*64];           // sup @ (z*state)
__device__ unsigned int g_pos[BB];
__device__ unsigned int g_kept[BB];
__device__ float g_prob[2];                         // prob_removes, loss addend

// ---------------- helpers --------------------------------------------------
__device__ __forceinline__ float warpSum(float v){
  #pragma unroll
  for (int o=16;o;o>>=1) v += __shfl_xor_sync(0xffffffffu, v, o);
  return v;
}
__device__ __forceinline__ float warpMax(float v){
  #pragma unroll
  for (int o=16;o;o>>=1) v = fmaxf(v, __shfl_xor_sync(0xffffffffu, v, o));
  return v;
}
__device__ __forceinline__ float blockSum(float v, float* red){
  int lane = threadIdx.x & 31, w = threadIdx.x >> 5;
  int nw = blockDim.x >> 5;
  v = warpSum(v);
  __syncthreads();
  if (lane==0) red[w] = v;
  __syncthreads();
  float r = (threadIdx.x < (unsigned)nw) ? red[threadIdx.x] : 0.0f;
  if (w==0) r = warpSum(r);
  if (threadIdx.x==0) red[0] = r;
  __syncthreads();
  return red[0];
}
__device__ __forceinline__ float blockMax(float v, float* red){
  int lane = threadIdx.x & 31, w = threadIdx.x >> 5;
  int nw = blockDim.x >> 5;
  v = warpMax(v);
  __syncthreads();
  if (lane==0) red[w] = v;
  __syncthreads();
  float r = (threadIdx.x < (unsigned)nw) ? red[threadIdx.x] : -3.4e38f;
  if (w==0) r = warpMax(r);
  if (threadIdx.x==0) red[0] = r;
  __syncthreads();
  return red[0];
}

__device__ __forceinline__ uint32_t rotl32(uint32_t x, int r){
  return __funnelshift_l(x, x, r);
}
// JAX threefry2x32, key = (k0,k1); 20 rounds, exact reference semantics.
__device__ __forceinline__ void threefry2x32(uint32_t k0, uint32_t k1,
                                             uint32_t& x0, uint32_t& x1){
  uint32_t ks0 = k0, ks1 = k1, ks2 = k0 ^ k1 ^ 0x1BD11BDAu;
  x0 += ks0; x1 += ks1;
  const int R0[4] = {13,15,26,6};
  const int R1[4] = {17,29,16,24};
  uint32_t ks[3] = {ks0, ks1, ks2};
  #pragma unroll
  for (int i=0;i<5;i++){
    #pragma unroll
    for (int j=0;j<4;j++){
      int r = (i & 1) ? R1[j] : R0[j];
      x0 += x1; x1 = rotl32(x1, r); x1 ^= x0;
    }
    x0 += ks[(i+1)%3];
    x1 += ks[(i+2)%3] + (uint32_t)(i+1);
  }
}

// ---------------- kernels --------------------------------------------------

// E = weight_embeddings + positional encoding row(iteration); also E^T; zero counters.
__global__ void k_setup(const float* __restrict__ we, const int* __restrict__ itp){
  int tid = blockIdx.x*blockDim.x + threadIdx.x;
  float it = (float)itp[0];
  if (tid < NN_*EDIM){
    int d = tid & 15;
    int pair = d >> 1;
    float arg = (float)((double)(2*pair) * (-9.210340371976184/16.0)); // -ln(1e4)/16 * (2i)
    float div = expf(arg);
    float pe = (d & 1) ? cosf(it*div) : sinf(it*div);
    float e = we[tid] + pe;
    g_E[tid] = e;
    g_Et[d*NN_ + (tid>>4)] = e;
  }
  if (blockIdx.x==0 && threadIdx.x < 2*BB){
    if (threadIdx.x < BB) g_pos[threadIdx.x] = 0u;
    else                  g_kept[threadIdx.x-BB] = 0u;
  }
}

// bias_r = E @ b_pool_r ; bias_u = E @ b_pool_u
__global__ void k_bias(const float* __restrict__ bpr, const float* __restrict__ bpu){
  int n = blockIdx.x, o = threadIdx.x; // 128 threads
  __shared__ float en[EDIM];
  if (o < EDIM) en[o] = g_E[n*EDIM+o];
  __syncthreads();
  float a = 0.f;
  #pragma unroll
  for (int d=0; d<EDIM; d++) a += en[d]*bpr[d*128+o];
  g_bias_r[n*128+o] = a;
  if (o < 64){
    float b = 0.f;
    #pragma unroll
    for (int d=0; d<EDIM; d++) b += en[d]*bpu[d*64+o];
    g_bias_u[n*64+o] = b;
  }
}

// EM = E @ mask_pool
__global__ void k_em(const float* __restrict__ mp){
  int n = blockIdx.x;
  __shared__ float en[EDIM];
  if (threadIdx.x < EDIM) en[threadIdx.x] = g_E[n*EDIM+threadIdx.x];
  __syncthreads();
  for (int m=threadIdx.x; m<NN_; m+=blockDim.x){
    float a = 0.f;
    #pragma unroll
    for (int d=0; d<EDIM; d++) a += en[d]*mp[d*NN_+m];
    g_EM[n*NN_+m] = a;
  }
}

// supports = softmax(relu(E @ E^T), axis=1)
__global__ void k_supports(){
  int n = blockIdx.x;
  __shared__ float row[NN_];
  __shared__ float red[32];
  float en[EDIM];
  #pragma unroll
  for (int d=0; d<EDIM; d++) en[d] = g_E[n*EDIM+d];
  float vmax = -3.4e38f;
  for (int m=threadIdx.x; m<NN_; m+=blockDim.x){
    float a = 0.f;
    #pragma unroll
    for (int d=0; d<EDIM; d++) a += en[d]*g_Et[d*NN_+m];
    a = fmaxf(a, 0.f);
    row[m] = a;
    vmax = fmaxf(vmax, a);
  }
  vmax = blockMax(vmax, red);
  float s = 0.f;
  for (int m=threadIdx.x; m<NN_; m+=blockDim.x){
    float e = expf(row[m]-vmax);
    row[m] = e; s += e;
  }
  s = blockSum(s, red);
  float inv = 1.0f/s;
  for (int m=threadIdx.x; m<NN_; m+=blockDim.x)
    g_supports[n*NN_+m] = row[m]*inv;
}

// Wn[n,i2,o] = sum_d E[n,d] * W_pool[d,i2,o]
template<int OC, bool IS_R>
__global__ void k_wgen(const float* __restrict__ Wp){
  float* Wn = IS_R ? (float*)g_Wn_r : (float*)g_Wn_u;
  int n0 = blockIdx.y*64;
  int i20 = blockIdx.x*16;
  int o = threadIdx.x; // OC threads
  __shared__ float Esm[64][EDIM];
  for (int t=threadIdx.x; t<64*EDIM; t+=OC)
    Esm[t>>4][t&15] = g_E[(n0 + (t>>4))*EDIM + (t&15)];
  __syncthreads();
  for (int ii=0; ii<16; ii++){
    int i2 = i20+ii;
    float w[EDIM];
    #pragma unroll
    for (int d=0; d<EDIM; d++) w[d] = Wp[((size_t)d*256 + i2)*OC + o];
    #pragma unroll 4
    for (int nn=0; nn<64; nn++){
      float a = 0.f;
      #pragma unroll
      for (int d=0; d<EDIM; d++) a += Esm[nn][d]*w[d];
      Wn[((size_t)(n0+nn)*256 + i2)*OC + o] = a;
    }
  }
}

// Fused: time-gram softmax + raw_mask + BN + hard-concrete mask + sup, per (b, 8 rows).
__global__ void k_supmask(const float* __restrict__ T, const float* __restrict__ TP,
                          const float* __restrict__ gamma, const float* __restrict__ beta,
                          float* __restrict__ out_mask){
  extern __shared__ float sm[];
  float* Tsm  = sm;                    // 12*1024
  float* TPsm = sm + WINDOW*NN_;       // 12*1024
  float* row  = TPsm + WINDOW*NN_;     // 1024
  __shared__ float red[32];
  int b = blockIdx.y;
  int n0 = blockIdx.x*8;
  for (int t=threadIdx.x; t<WINDOW*NN_; t+=blockDim.x){
    Tsm[t]  = T[(size_t)b*WINDOW*NN_ + t];
    TPsm[t] = TP[t];
  }
  __syncthreads();
  const float bnc = sqrtf(1.0f + 1e-5f);
  unsigned int cnt = 0;
  for (int r8=0; r8<8; r8++){
    int n = n0 + r8;
    float tv[WINDOW];
    #pragma unroll
    for (int w=0; w<WINDOW; w++) tv[w] = Tsm[w*NN_+n];
    float vmax = -3.4e38f;
    for (int m=threadIdx.x; m<NN_; m+=blockDim.x){
      float tg = 0.f;
      #pragma unroll
      for (int w=0; w<WINDOW; w++) tg += tv[w]*Tsm[w*NN_+m];
      tg = fmaxf(tg, 0.f);
      row[m] = tg;
      vmax = fmaxf(vmax, tg);
    }
    vmax = blockMax(vmax, red);
    float s = 0.f;
    for (int m=threadIdx.x; m<NN_; m+=blockDim.x){
      float e = expf(row[m]-vmax);
      row[m] = e; s += e;
    }
    s = blockSum(s, red);
    float inv = 1.0f/s;
    float gn = gamma[n], bt = beta[n];
    for (int m=threadIdx.x; m<NN_; m+=blockDim.x){
      float ts = row[m]*inv;
      float rm = g_EM[n*NN_+m];
      #pragma unroll
      for (int w=0; w<WINDOW; w++) rm += tv[w]*TPsm[w*NN_+m];
      rm = rm / bnc * gn + bt;
      float sv = 1.0f/(1.0f+expf(-(rm+3.0f))) * 1.2f - 0.2f;
      sv = fminf(fmaxf(sv, 0.0f), 1.0f);
      float mk = rintf(sv);   // round-half-to-even, matches jnp.round
      size_t idx = (size_t)b*NNSQ + (size_t)n*NN_ + m;
      out_mask[idx] = mk;
      g_sup[idx] = (g_supports[n*NN_+m] + ts)*0.5f*mk;
      cnt += (mk > 0.0f) ? 1u : 0u;
    }
    __syncthreads();
  }
  float fc = blockSum((float)cnt, red);
  if (threadIdx.x==0) atomicAdd(&g_pos[b], (unsigned int)(fc + 0.5f));
}

__global__ void k_prob(){
  unsigned int tot = 0;
  for (int i=0;i<BB;i++) tot += g_pos[i];
  float active = (float)tot / (float)BNN;   // exact (<=2^24)
  float p = 0.05f/active + 1e-8f;
  g_prob[0] = fminf(p, 1.0f);
  g_prob[1] = fmaxf(0.05f/active - 1.0f, 0.0f);
}

// Count reduced_mask>0 per batch using JAX threefry uniform(key=42).
__global__ void k_kept(const float* __restrict__ out_mask){
  __shared__ unsigned int cnt[BB];
  if (threadIdx.x < BB) cnt[threadIdx.x] = 0u;
  __syncthreads();
  float prob = g_prob[0];
  int lane = threadIdx.x & 31;
  unsigned int base = blockIdx.x*1024u + threadIdx.x;
  #pragma unroll
  for (int k=0;k<4;k++){
    unsigned int t = base + (unsigned)k*256u;
    uint32_t x0 = t, x1 = t + (uint32_t)HALF_BNN;
    threefry2x32(0u, 42u, x0, x1);
    float u0 = __uint_as_float((x0>>9) | 0x3f800000u) - 1.0f;
    float u1 = __uint_as_float((x1>>9) | 0x3f800000u) - 1.0f;
    float m0 = out_mask[t];
    float m1 = out_mask[t + HALF_BNN];
    int b0 = (int)(t >> 20);           // uniform within warp (32-aligned ranges)
    bool keep0 = (m0 > 0.0f) && !(u0 < m0*prob);
    bool keep1 = (m1 > 0.0f) && !(u1 < m1*prob);
    unsigned bal0 = __ballot_sync(0xffffffffu, keep0);
    unsigned bal1 = __ballot_sync(0xffffffffu, keep1);
    if (lane==0){
      if (bal0) atomicAdd(&cnt[b0],   __popc(bal0));
      if (bal1) atomicAdd(&cnt[b0+8], __popc(bal1));
    }
  }
  __syncthreads();
  if (threadIdx.x < BB && cnt[threadIdx.x]) atomicAdd(&g_kept[threadIdx.x], cnt[threadIdx.x]);
}

__global__ void k_loss(float* __restrict__ out_loss){
  int b = threadIdx.x;
  if (b < BB)
    out_loss[b] = (float)g_kept[b] / ((float)g_pos[b] + 1e-8f) + g_prob[1];
}

// xb = sup[b] @ cat(x,state)[b]   (1024x1024 @ 1024x128)
__global__ void k_gemm1(const float* __restrict__ x, const float* __restrict__ st){
  int b = blockIdx.y;
  int m0 = blockIdx.x*32;
  __shared__ float Asm[32][33];
  __shared__ float Xsm[32][128];
  int tx = threadIdx.x & 31;
  int ty = threadIdx.x >> 5;
  float acc[4][4] = {};
  const float* Ab = g_sup + (size_t)b*NNSQ;
  for (int k0=0;k0<NN_;k0+=32){
    #pragma unroll
    for (int l=0;l<4;l++){
      int idx = threadIdx.x + l*256;
      int r = idx>>5, c = idx&31;
      Asm[r][c] = Ab[(size_t)(m0+r)*NN_ + k0 + c];
    }
    #pragma unroll
    for (int l=0;l<16;l++){
      int idx = threadIdx.x + l*256;
      int r = idx>>7, c = idx&127;
      int kr = k0 + r;
      Xsm[r][c] = (c<64) ? x[((size_t)b*NN_ + kr)*64 + c]
                         : st[((size_t)b*NN_ + kr)*64 + (c-64)];
    }
    __syncthreads();
    #pragma unroll
    for (int kk=0;kk<32;kk++){
      float av[4], xv[4];
      #pragma unroll
      for (int i=0;i<4;i++) av[i] = Asm[ty*4+i][kk];
      #pragma unroll
      for (int j=0;j<4;j++) xv[j] = Xsm[kk][tx+32*j];
      #pragma unroll
      for (int i=0;i<4;i++)
        #pragma unroll
        for (int j=0;j<4;j++)
          acc[i][j] += av[i]*xv[j];
    }
    __syncthreads();
  }
  #pragma unroll
  for (int i=0;i<4;i++)
    #pragma unroll
    for (int j=0;j<4;j++)
      g_xb[((size_t)b*NN_ + m0 + ty*4 + i)*128 + tx + 32*j] = acc[i][j];
}

// c2 = sup[b] @ zs[b]   (1024x1024 @ 1024x64)
__global__ void k_gemm2(){
  int b = blockIdx.y;
  int m0 = blockIdx.x*64;
  __shared__ float Asm[64][33];
  __shared__ float Xsm[32][64];
  int tx = threadIdx.x & 15;
  int ty = threadIdx.x >> 4;
  float acc[4][4] = {};
  const float* Ab = g_sup + (size_t)b*NNSQ;
  const float* Xb = g_zs + (size_t)b*NN_*64;
  for (int k0=0;k0<NN_;k0+=32){
    #pragma unroll
    for (int l=0;l<8;l++){
      int idx = threadIdx.x + l*256;
      int r = idx>>5, c = idx&31;
      Asm[r][c] = Ab[(size_t)(m0+r)*NN_ + k0 + c];
    }
    #pragma unroll
    for (int l=0;l<8;l++){
      int idx = threadIdx.x + l*256;
      int r = idx>>6, c = idx&63;
      Xsm[r][c] = Xb[(size_t)(k0+r)*64 + c];
    }
    __syncthreads();
    #pragma unroll
    for (int kk=0;kk<32;kk++){
      float av[4], xv[4];
      #pragma unroll
      for (int i=0;i<4;i++) av[i] = Asm[ty*4+i][kk];
      #pragma unroll
      for (int j=0;j<4;j++) xv[j] = Xsm[kk][tx+16*j];
      #pragma unroll
      for (int i=0;i<4;i++)
        #pragma unroll
        for (int j=0;j<4;j++)
          acc[i][j] += av[i]*xv[j];
    }
    __syncthreads();
  }
  #pragma unroll
  for (int i=0;i<4;i++)
    #pragma unroll
    for (int j=0;j<4;j++)
      g_c2[((size_t)b*NN_ + m0 + ty*4 + i)*64 + tx + 16*j] = acc[i][j];
}

// r-gate: per-node weights applied to [x_a | x_b]; outputs z*state and r.
__global__ void k_gate_r(const float* __restrict__ x, const float* __restrict__ st){
  int n = blockIdx.x;
  int o = threadIdx.x; // 128
  __shared__ float Xg[16][256];
  for (int t=threadIdx.x; t<16*256; t+=128){
    int b = t>>8, i = t&255;
    float v;
    if (i < 64)       v = x[((size_t)b*NN_+n)*64 + i];
    else if (i < 128) v = st[((size_t)b*NN_+n)*64 + (i-64)];
    else              v = g_xb[((size_t)b*NN_+n)*128 + (i-128)];
    Xg[b][i] = v;
  }
  __syncthreads();
  float acc[16] = {};
  const float* W = g_Wn_r + (size_t)n*256*128 + o;
  #pragma unroll 4
  for (int i=0;i<256;i++){
    float w = W[(size_t)i*128];
    #pragma unroll
    for (int b=0;b<16;b++) acc[b] += Xg[b][i]*w;
  }
  float bias = g_bias_r[n*128+o];
  #pragma unroll
  for (int b=0;b<16;b++){
    float g = 1.0f/(1.0f+expf(-(acc[b]+bias)));
    if (o < 64) g_zs[((size_t)b*NN_+n)*64 + o] = g * st[((size_t)b*NN_+n)*64 + o];
    else        g_rb[((size_t)b*NN_+n)*64 + (o-64)] = g;
  }
}

// u-gate + GRU output h = r*state + (1-r)*tanh(gate_u)
__global__ void k_gate_u(const float* __restrict__ x, const float* __restrict__ st,
                         float* __restrict__ out_h){
  int n = blockIdx.x;
  int o = threadIdx.x; // 64
  __shared__ float Xg[16][256];
  for (int t=threadIdx.x; t<16*256; t+=64){
    int b = t>>8, i = t&255;
    float v;
    if (i < 64)       v = x[((size_t)b*NN_+n)*64 + i];
    else if (i < 128) v = g_zs[((size_t)b*NN_+n)*64 + (i-64)];
    else if (i < 192) v = g_xb[((size_t)b*NN_+n)*128 + (i-128)];   // sup@x part
    else              v = g_c2[((size_t)b*NN_+n)*64 + (i-192)];    // sup@(z*state)
    Xg[b][i] = v;
  }
  __syncthreads();
  float acc[16] = {};
  const float* W = g_Wn_u + (size_t)n*256*64 + o;
  #pragma unroll 4
  for (int i=0;i<256;i++){
    float w = W[(size_t)i*64];
    #pragma unroll
    for (int b=0;b<16;b++) acc[b] += Xg[b][i]*w;
  }
  float bias = g_bias_u[n*64+o];
  #pragma unroll
  for (int b=0;b<16;b++){
    float hc = tanhf(acc[b]+bias);
    float r = g_rb[((size_t)b*NN_+n)*64 + o];
    float sv = st[((size_t)b*NN_+n)*64 + o];
    out_h[((size_t)b*NN_+n)*64 + o] = r*sv + (1.0f-r)*hc;
  }
}

// ---------------- launch ----------------------------------------------------
extern "C" void kernel_launch(void* const* d_in, const int* in_sizes, int n_in,
                              void* d_out, int out_size){
  const float* x    = (const float*)d_in[0];
  const float* st   = (const float*)d_in[1];
  const float* we   = (const float*)d_in[2];
  const float* T    = (const float*)d_in[3];
  const float* Wpr  = (const float*)d_in[4];
  const float* bpr  = (const float*)d_in[5];
  const float* Wpu  = (const float*)d_in[6];
  const float* bpu  = (const float*)d_in[7];
  const float* mp   = (const float*)d_in[8];
  const float* tp   = (const float*)d_in[9];
  const float* gmm  = (const float*)d_in[10];
  const float* bta  = (const float*)d_in[11];
  const int*   itp  = (const int*)d_in[12];
  float* out = (float*)d_out;
  float* out_mask = out + OFF_MASK;

  k_setup<<<64,256>>>(we, itp);
  k_bias<<<NN_,128>>>(bpr, bpu);
  k_em<<<NN_,256>>>(mp);
  k_supports<<<NN_,256>>>();
  k_wgen<128,true><<<dim3(16,16),128>>>(Wpr);
  k_wgen<64,false><<<dim3(16,16),64>>>(Wpu);

  size_t smem_sup = (size_t)(2*WINDOW*NN_ + NN_)*sizeof(float); // 102400 B
  cudaFuncSetAttribute(k_supmask, cudaFuncAttributeMaxDynamicSharedMemorySize, (int)smem_sup);
  k_supmask<<<dim3(128,16),256,smem_sup>>>(T, tp, gmm, bta, out_mask);

  k_prob<<<1,1>>>();
  k_kept<<<8192,256>>>(out_mask);
  k_loss<<<1,16>>>(out + OFF_LOSS);

  k_gemm1<<<dim3(32,16),256>>>(x, st);
  k_gate_r<<<NN_,128>>>(x, st);
  k_gemm2<<<dim3(16,16),256>>>();
  k_gate_u<<<NN_,64>>>(x, st, out);
}

// round 3
// speedup vs baseline: 1.0007x; 1.0007x over previous
#include <cuda_runtime.h>
#include <cstdint>
#include <math.h>

#define BB 16
#define NN_ 1024
#define DOUT 64
#define EDIM 16
#define WINDOW 12
#define NNSQ (NN_*NN_)          /* 1048576 */
#define BNN (BB*NNSQ)           /* 16777216 */
#define HALF_BNN (BNN/2)        /* 8388608 */

#define OFF_MASK (BB*NN_*DOUT)          /* 1048576 */
#define OFF_LOSS (OFF_MASK + BNN)       /* 17825792 */

// ---------------- scratch (device globals; no dynamic alloc allowed) -------
__device__ float g_E[NN_*EDIM];
__device__ float g_Et[EDIM*NN_];
__device__ float g_EM[NNSQ];
__device__ float g_supports[NNSQ];
__device__ float g_sup[(size_t)BB*NNSQ];            // 64 MB
__device__ float g_Wn_r[(size_t)NN_*256*128];       // 134 MB
__device__ float g_Wn_u[(size_t)NN_*256*64];        // 67 MB
__device__ float g_bias_r[NN_*128];
__device__ float g_bias_u[NN_*64];
__device__ float g_xb[(size_t)BB*NN_*128];          // sup @ cat(x,state)
__device__ float g_zs[(size_t)BB*NN_*64];           // z * state
__device__ float g_rb[(size_t)BB*NN_*64];           // r gate
__device__ float g_c2[(size_t)BB*NN_*64];           // sup @ (z*state)
__device__ unsigned int g_pos[BB];
__device__ unsigned int g_kept[BB];
__device__ float g_prob[2];                         // prob_removes, loss addend

// ---------------- helpers --------------------------------------------------
__device__ __forceinline__ float warpSum(float v){
  #pragma unroll
  for (int o=16;o;o>>=1) v += __shfl_xor_sync(0xffffffffu, v, o);
  return v;
}
__device__ __forceinline__ float warpMax(float v){
  #pragma unroll
  for (int o=16;o;o>>=1) v = fmaxf(v, __shfl_xor_sync(0xffffffffu, v, o));
  return v;
}
__device__ __forceinline__ float blockSum(float v, float* red){
  int lane = threadIdx.x & 31, w = threadIdx.x >> 5;
  int nw = blockDim.x >> 5;
  v = warpSum(v);
  __syncthreads();
  if (lane==0) red[w] = v;
  __syncthreads();
  float r = (threadIdx.x < (unsigned)nw) ? red[threadIdx.x] : 0.0f;
  if (w==0) r = warpSum(r);
  if (threadIdx.x==0) red[0] = r;
  __syncthreads();
  return red[0];
}
__device__ __forceinline__ float blockMax(float v, float* red){
  int lane = threadIdx.x & 31, w = threadIdx.x >> 5;
  int nw = blockDim.x >> 5;
  v = warpMax(v);
  __syncthreads();
  if (lane==0) red[w] = v;
  __syncthreads();
  float r = (threadIdx.x < (unsigned)nw) ? red[threadIdx.x] : -3.4e38f;
  if (w==0) r = warpMax(r);
  if (threadIdx.x==0) red[0] = r;
  __syncthreads();
  return red[0];
}

__device__ __forceinline__ uint32_t rotl32(uint32_t x, int r){
  return __funnelshift_l(x, x, r);
}
// JAX threefry2x32, key = (k0,k1); 20 rounds, exact reference semantics.
__device__ __forceinline__ void threefry2x32(uint32_t k0, uint32_t k1,
                                             uint32_t& x0, uint32_t& x1){
  uint32_t ks0 = k0, ks1 = k1, ks2 = k0 ^ k1 ^ 0x1BD11BDAu;
  x0 += ks0; x1 += ks1;
  const int R0[4] = {13,15,26,6};
  const int R1[4] = {17,29,16,24};
  uint32_t ks[3] = {ks0, ks1, ks2};
  #pragma unroll
  for (int i=0;i<5;i++){
    #pragma unroll
    for (int j=0;j<4;j++){
      int r = (i & 1) ? R1[j] : R0[j];
      x0 += x1; x1 = rotl32(x1, r); x1 ^= x0;
    }
    x0 += ks[(i+1)%3];
    x1 += ks[(i+2)%3] + (uint32_t)(i+1);
  }
}

// ---------------- kernels --------------------------------------------------

// E = weight_embeddings + positional encoding row(iteration); also E^T; zero counters.
__global__ void k_setup(const float* __restrict__ we, const int* __restrict__ itp){
  int tid = blockIdx.x*blockDim.x + threadIdx.x;
  float it = (float)itp[0];
  if (tid < NN_*EDIM){
    int d = tid & 15;
    int pair = d >> 1;
    float arg = (float)((double)(2*pair) * (-9.210340371976184/16.0)); // -ln(1e4)/16 * (2i)
    float div = expf(arg);
    float pe = (d & 1) ? cosf(it*div) : sinf(it*div);
    float e = we[tid] + pe;
    g_E[tid] = e;
    g_Et[d*NN_ + (tid>>4)] = e;
  }
  if (blockIdx.x==0 && threadIdx.x < 2*BB){
    if (threadIdx.x < BB) g_pos[threadIdx.x] = 0u;
    else                  g_kept[threadIdx.x-BB] = 0u;
  }
}

// bias_r = E @ b_pool_r ; bias_u = E @ b_pool_u
__global__ void k_bias(const float* __restrict__ bpr, const float* __restrict__ bpu){
  int n = blockIdx.x, o = threadIdx.x; // 128 threads
  __shared__ float en[EDIM];
  if (o < EDIM) en[o] = g_E[n*EDIM+o];
  __syncthreads();
  float a = 0.f;
  #pragma unroll
  for (int d=0; d<EDIM; d++) a += en[d]*bpr[d*128+o];
  g_bias_r[n*128+o] = a;
  if (o < 64){
    float b = 0.f;
    #pragma unroll
    for (int d=0; d<EDIM; d++) b += en[d]*bpu[d*64+o];
    g_bias_u[n*64+o] = b;
  }
}

// EM = E @ mask_pool
__global__ void k_em(const float* __restrict__ mp){
  int n = blockIdx.x;
  __shared__ float en[EDIM];
  if (threadIdx.x < EDIM) en[threadIdx.x] = g_E[n*EDIM+threadIdx.x];
  __syncthreads();
  for (int m=threadIdx.x; m<NN_; m+=blockDim.x){
    float a = 0.f;
    #pragma unroll
    for (int d=0; d<EDIM; d++) a += en[d]*mp[d*NN_+m];
    g_EM[n*NN_+m] = a;
  }
}

// supports = softmax(relu(E @ E^T), axis=1)
__global__ void k_supports(){
  int n = blockIdx.x;
  __shared__ float row[NN_];
  __shared__ float red[32];
  float en[EDIM];
  #pragma unroll
  for (int d=0; d<EDIM; d++) en[d] = g_E[n*EDIM+d];
  float vmax = -3.4e38f;
  for (int m=threadIdx.x; m<NN_; m+=blockDim.x){
    float a = 0.f;
    #pragma unroll
    for (int d=0; d<EDIM; d++) a += en[d]*g_Et[d*NN_+m];
    a = fmaxf(a, 0.f);
    row[m] = a;
    vmax = fmaxf(vmax, a);
  }
  vmax = blockMax(vmax, red);
  float s = 0.f;
  for (int m=threadIdx.x; m<NN_; m+=blockDim.x){
    float e = expf(row[m]-vmax);
    row[m] = e; s += e;
  }
  s = blockSum(s, red);
  float inv = 1.0f/s;
  for (int m=threadIdx.x; m<NN_; m+=blockDim.x)
    g_supports[n*NN_+m] = row[m]*inv;
}

// Wn[n,i2,o] = sum_d E[n,d] * W_pool[d,i2,o]
template<int OC, bool IS_R>
__global__ void k_wgen(const float* __restrict__ Wp){
  float* Wn = IS_R ? (float*)g_Wn_r : (float*)g_Wn_u;
  int n0 = blockIdx.y*64;
  int i20 = blockIdx.x*16;
  int o = threadIdx.x; // OC threads
  __shared__ float Esm[64][EDIM];
  for (int t=threadIdx.x; t<64*EDIM; t+=OC)
    Esm[t>>4][t&15] = g_E[(n0 + (t>>4))*EDIM + (t&15)];
  __syncthreads();
  for (int ii=0; ii<16; ii++){
    int i2 = i20+ii;
    float w[EDIM];
    #pragma unroll
    for (int d=0; d<EDIM; d++) w[d] = Wp[((size_t)d*256 + i2)*OC + o];
    #pragma unroll 4
    for (int nn=0; nn<64; nn++){
      float a = 0.f;
      #pragma unroll
      for (int d=0; d<EDIM; d++) a += Esm[nn][d]*w[d];
      Wn[((size_t)(n0+nn)*256 + i2)*OC + o] = a;
    }
  }
}

// Fused: time-gram softmax + raw_mask + BN + hard-concrete mask + sup, per (b, 8 rows).
__global__ void k_supmask(const float* __restrict__ T, const float* __restrict__ TP,
                          const float* __restrict__ gamma, const float* __restrict__ beta,
                          float* __restrict__ out_mask){
  extern __shared__ float sm[];
  float* Tsm  = sm;                    // 12*1024
  float* TPsm = sm + WINDOW*NN_;       // 12*1024
  float* row  = TPsm + WINDOW*NN_;     // 1024
  __shared__ float red[32];
  int b = blockIdx.y;
  int n0 = blockIdx.x*8;
  for (int t=threadIdx.x; t<WINDOW*NN_; t+=blockDim.x){
    Tsm[t]  = T[(size_t)b*WINDOW*NN_ + t];
    TPsm[t] = TP[t];
  }
  __syncthreads();
  const float bnc = sqrtf(1.0f + 1e-5f);
  unsigned int cnt = 0;
  for (int r8=0; r8<8; r8++){
    int n = n0 + r8;
    float tv[WINDOW];
    #pragma unroll
    for (int w=0; w<WINDOW; w++) tv[w] = Tsm[w*NN_+n];
    float vmax = -3.4e38f;
    for (int m=threadIdx.x; m<NN_; m+=blockDim.x){
      float tg = 0.f;
      #pragma unroll
      for (int w=0; w<WINDOW; w++) tg += tv[w]*Tsm[w*NN_+m];
      tg = fmaxf(tg, 0.f);
      row[m] = tg;
      vmax = fmaxf(vmax, tg);
    }
    vmax = blockMax(vmax, red);
    float s = 0.f;
    for (int m=threadIdx.x; m<NN_; m+=blockDim.x){
      float e = expf(row[m]-vmax);
      row[m] = e; s += e;
    }
    s = blockSum(s, red);
    float inv = 1.0f/s;
    float gn = gamma[n], bt = beta[n];
    for (int m=threadIdx.x; m<NN_; m+=blockDim.x){
      float ts = row[m]*inv;
      float rm = g_EM[n*NN_+m];
      #pragma unroll
      for (int w=0; w<WINDOW; w++) rm += tv[w]*TPsm[w*NN_+m];
      rm = rm / bnc * gn + bt;
      float sv = 1.0f/(1.0f+expf(-(rm+3.0f))) * 1.2f - 0.2f;
      sv = fminf(fmaxf(sv, 0.0f), 1.0f);
      float mk = rintf(sv);   // round-half-to-even, matches jnp.round
      size_t idx = (size_t)b*NNSQ + (size_t)n*NN_ + m;
      out_mask[idx] = mk;
      g_sup[idx] = (g_supports[n*NN_+m] + ts)*0.5f*mk;
      cnt += (mk > 0.0f) ? 1u : 0u;
    }
    __syncthreads();
  }
  float fc = blockSum((float)cnt, red);
  if (threadIdx.x==0) atomicAdd(&g_pos[b], (unsigned int)(fc + 0.5f));
}

__global__ void k_prob(){
  unsigned int tot = 0;
  for (int i=0;i<BB;i++) tot += g_pos[i];
  float active = (float)tot / (float)BNN;   // exact (<=2^24)
  float p = 0.05f/active + 1e-8f;
  g_prob[0] = fminf(p, 1.0f);
  g_prob[1] = fmaxf(0.05f/active - 1.0f, 0.0f);
}

// Count reduced_mask>0 per batch using JAX threefry uniform(key=42).
__global__ void k_kept(const float* __restrict__ out_mask){
  __shared__ unsigned int cnt[BB];
  if (threadIdx.x < BB) cnt[threadIdx.x] = 0u;
  __syncthreads();
  float prob = g_prob[0];
  int lane = threadIdx.x & 31;
  unsigned int base = blockIdx.x*1024u + threadIdx.x;
  #pragma unroll
  for (int k=0;k<4;k++){
    unsigned int t = base + (unsigned)k*256u;
    uint32_t x0 = t, x1 = t + (uint32_t)HALF_BNN;
    threefry2x32(0u, 42u, x0, x1);
    float u0 = __uint_as_float((x0>>9) | 0x3f800000u) - 1.0f;
    float u1 = __uint_as_float((x1>>9) | 0x3f800000u) - 1.0f;
    float m0 = out_mask[t];
    float m1 = out_mask[t + HALF_BNN];
    int b0 = (int)(t >> 20);           // uniform within warp (32-aligned ranges)
    bool keep0 = (m0 > 0.0f) && !(u0 < m0*prob);
    bool keep1 = (m1 > 0.0f) && !(u1 < m1*prob);
    unsigned bal0 = __ballot_sync(0xffffffffu, keep0);
    unsigned bal1 = __ballot_sync(0xffffffffu, keep1);
    if (lane==0){
      if (bal0) atomicAdd(&cnt[b0],   __popc(bal0));
      if (bal1) atomicAdd(&cnt[b0+8], __popc(bal1));
    }
  }
  __syncthreads();
  if (threadIdx.x < BB && cnt[threadIdx.x]) atomicAdd(&g_kept[threadIdx.x], cnt[threadIdx.x]);
}

__global__ void k_loss(float* __restrict__ out_loss){
  int b = threadIdx.x;
  if (b < BB)
    out_loss[b] = (float)g_kept[b] / ((float)g_pos[b] + 1e-8f) + g_prob[1];
}

// xb = sup[b] @ cat(x,state)[b]   (1024x1024 @ 1024x128)
__global__ void k_gemm1(const float* __restrict__ x, const float* __restrict__ st){
  int b = blockIdx.y;
  int m0 = blockIdx.x*32;
  __shared__ float Asm[32][33];
  __shared__ float Xsm[32][128];
  int tx = threadIdx.x & 31;
  int ty = threadIdx.x >> 5;
  float acc[4][4] = {};
  const float* Ab = g_sup + (size_t)b*NNSQ;
  for (int k0=0;k0<NN_;k0+=32){
    #pragma unroll
    for (int l=0;l<4;l++){
      int idx = threadIdx.x + l*256;
      int r = idx>>5, c = idx&31;
      Asm[r][c] = Ab[(size_t)(m0+r)*NN_ + k0 + c];
    }
    #pragma unroll
    for (int l=0;l<16;l++){
      int idx = threadIdx.x + l*256;
      int r = idx>>7, c = idx&127;
      int kr = k0 + r;
      Xsm[r][c] = (c<64) ? x[((size_t)b*NN_ + kr)*64 + c]
                         : st[((size_t)b*NN_ + kr)*64 + (c-64)];
    }
    __syncthreads();
    #pragma unroll
    for (int kk=0;kk<32;kk++){
      float av[4], xv[4];
      #pragma unroll
      for (int i=0;i<4;i++) av[i] = Asm[ty*4+i][kk];
      #pragma unroll
      for (int j=0;j<4;j++) xv[j] = Xsm[kk][tx+32*j];
      #pragma unroll
      for (int i=0;i<4;i++)
        #pragma unroll
        for (int j=0;j<4;j++)
          acc[i][j] += av[i]*xv[j];
    }
    __syncthreads();
  }
  #pragma unroll
  for (int i=0;i<4;i++)
    #pragma unroll
    for (int j=0;j<4;j++)
      g_xb[((size_t)b*NN_ + m0 + ty*4 + i)*128 + tx + 32*j] = acc[i][j];
}

// c2 = sup[b] @ zs[b]   (1024x1024 @ 1024x64)
__global__ void k_gemm2(){
  int b = blockIdx.y;
  int m0 = blockIdx.x*64;
  __shared__ float Asm[64][33];
  __shared__ float Xsm[32][64];
  int tx = threadIdx.x & 15;
  int ty = threadIdx.x >> 4;
  float acc[4][4] = {};
  const float* Ab = g_sup + (size_t)b*NNSQ;
  const float* Xb = g_zs + (size_t)b*NN_*64;
  for (int k0=0;k0<NN_;k0+=32){
    #pragma unroll
    for (int l=0;l<8;l++){
      int idx = threadIdx.x + l*256;
      int r = idx>>5, c = idx&31;
      Asm[r][c] = Ab[(size_t)(m0+r)*NN_ + k0 + c];
    }
    #pragma unroll
    for (int l=0;l<8;l++){
      int idx = threadIdx.x + l*256;
      int r = idx>>6, c = idx&63;
      Xsm[r][c] = Xb[(size_t)(k0+r)*64 + c];
    }
    __syncthreads();
    #pragma unroll
    for (int kk=0;kk<32;kk++){
      float av[4], xv[4];
      #pragma unroll
      for (int i=0;i<4;i++) av[i] = Asm[ty*4+i][kk];
      #pragma unroll
      for (int j=0;j<4;j++) xv[j] = Xsm[kk][tx+16*j];
      #pragma unroll
      for (int i=0;i<4;i++)
        #pragma unroll
        for (int j=0;j<4;j++)
          acc[i][j] += av[i]*xv[j];
    }
    __syncthreads();
  }
  #pragma unroll
  for (int i=0;i<4;i++)
    #pragma unroll
    for (int j=0;j<4;j++)
      g_c2[((size_t)b*NN_ + m0 + ty*4 + i)*64 + tx + 16*j] = acc[i][j];
}

// r-gate: per-node weights applied to [x_a | x_b]; outputs z*state and r.
__global__ void k_gate_r(const float* __restrict__ x, const float* __restrict__ st){
  int n = blockIdx.x;
  int o = threadIdx.x; // 128
  __shared__ float Xg[16][256];
  for (int t=threadIdx.x; t<16*256; t+=128){
    int b = t>>8, i = t&255;
    float v;
    if (i < 64)       v = x[((size_t)b*NN_+n)*64 + i];
    else if (i < 128) v = st[((size_t)b*NN_+n)*64 + (i-64)];
    else              v = g_xb[((size_t)b*NN_+n)*128 + (i-128)];
    Xg[b][i] = v;
  }
  __syncthreads();
  float acc[16] = {};
  const float* W = g_Wn_r + (size_t)n*256*128 + o;
  #pragma unroll 4
  for (int i=0;i<256;i++){
    float w = W[(size_t)i*128];
    #pragma unroll
    for (int b=0;b<16;b++) acc[b] += Xg[b][i]*w;
  }
  float bias = g_bias_r[n*128+o];
  #pragma unroll
  for (int b=0;b<16;b++){
    float g = 1.0f/(1.0f+expf(-(acc[b]+bias)));
    if (o < 64) g_zs[((size_t)b*NN_+n)*64 + o] = g * st[((size_t)b*NN_+n)*64 + o];
    else        g_rb[((size_t)b*NN_+n)*64 + (o-64)] = g;
  }
}

// u-gate + GRU output h = r*state + (1-r)*tanh(gate_u)
__global__ void k_gate_u(const float* __restrict__ x, const float* __restrict__ st,
                         float* __restrict__ out_h){
  int n = blockIdx.x;
  int o = threadIdx.x; // 64
  __shared__ float Xg[16][256];
  for (int t=threadIdx.x; t<16*256; t+=64){
    int b = t>>8, i = t&255;
    float v;
    if (i < 64)       v = x[((size_t)b*NN_+n)*64 + i];
    else if (i < 128) v = g_zs[((size_t)b*NN_+n)*64 + (i-64)];
    else if (i < 192) v = g_xb[((size_t)b*NN_+n)*128 + (i-128)];   // sup@x part
    else              v = g_c2[((size_t)b*NN_+n)*64 + (i-192)];    // sup@(z*state)
    Xg[b][i] = v;
  }
  __syncthreads();
  float acc[16] = {};
  const float* W = g_Wn_u + (size_t)n*256*64 + o;
  #pragma unroll 4
  for (int i=0;i<256;i++){
    float w = W[(size_t)i*64];
    #pragma unroll
    for (int b=0;b<16;b++) acc[b] += Xg[b][i]*w;
  }
  float bias = g_bias_u[n*64+o];
  #pragma unroll
  for (int b=0;b<16;b++){
    float hc = tanhf(acc[b]+bias);
    float r = g_rb[((size_t)b*NN_+n)*64 + o];
    float sv = st[((size_t)b*NN_+n)*64 + o];
    out_h[((size_t)b*NN_+n)*64 + o] = r*sv + (1.0f-r)*hc;
  }
}

// ---------------- launch ----------------------------------------------------
extern "C" void kernel_launch(void* const* d_in, const int* in_sizes, int n_in,
                              void* d_out, int out_size){
  const float* x    = (const float*)d_in[0];
  const float* st   = (const float*)d_in[1];
  const float* we   = (const float*)d_in[2];
  const float* T    = (const float*)d_in[3];
  const float* Wpr  = (const float*)d_in[4];
  const float* bpr  = (const float*)d_in[5];
  const float* Wpu  = (const float*)d_in[6];
  const float* bpu  = (const float*)d_in[7];
  const float* mp   = (const float*)d_in[8];
  const float* tp   = (const float*)d_in[9];
  const float* gmm  = (const float*)d_in[10];
  const float* bta  = (const float*)d_in[11];
  const int*   itp  = (const int*)d_in[12];
  float* out = (float*)d_out;
  float* out_mask = out + OFF_MASK;

  k_setup<<<64,256>>>(we, itp);
  k_bias<<<NN_,128>>>(bpr, bpu);
  k_em<<<NN_,256>>>(mp);
  k_supports<<<NN_,256>>>();
  k_wgen<128,true><<<dim3(16,16),128>>>(Wpr);
  k_wgen<64,false><<<dim3(16,16),64>>>(Wpu);

  size_t smem_sup = (size_t)(2*WINDOW*NN_ + NN_)*sizeof(float); // 102400 B
  cudaFuncSetAttribute(k_supmask, cudaFuncAttributeMaxDynamicSharedMemorySize, (int)smem_sup);
  k_supmask<<<dim3(128,16),256,smem_sup>>>(T, tp, gmm, bta, out_mask);

  k_prob<<<1,1>>>();
  k_kept<<<8192,256>>>(out_mask);
  k_loss<<<1,16>>>(out + OFF_LOSS);

  k_gemm1<<<dim3(32,16),256>>>(x, st);
  k_gate_r<<<NN_,128>>>(x, st);
  k_gemm2<<<dim3(16,16),256>>>();
  k_gate_u<<<NN_,64>>>(x, st, out);
}

// round 4
// speedup vs baseline: 1.1604x; 1.1596x over previous
#include <cuda_runtime.h>
#include <cuda_bf16.h>
#include <cstdint>
#include <math.h>

#define BB 16
#define NN_ 1024
#define EDIM 16
#define WINDOW 12
#define NNSQ (NN_*NN_)
#define BNN (BB*NNSQ)
#define HALF_BNN (BNN/2)
#define OFF_MASK (BB*NN_*64)
#define OFF_LOSS (OFF_MASK + BNN)
#define MASK_THR (-2.66352776f)   /* ln(1.4) - 3 */

// ---------------- scratch ----------------
__device__ float g_E[NN_*EDIM];
__device__ float g_Et[EDIM*NN_];
__device__ float g_EM[NNSQ];
__device__ float g_supports[NNSQ];
__device__ __nv_bfloat16 g_sh[(size_t)BNN];       // sup hi
__device__ __nv_bfloat16 g_sl[(size_t)BNN];       // sup lo
__device__ uint32_t g_bits[BNN/32];
__device__ __nv_bfloat16 g_xh[(size_t)BB*NN_*128];
__device__ __nv_bfloat16 g_xl[(size_t)BB*NN_*128];
__device__ __nv_bfloat16 g_zh[(size_t)BB*NN_*64];
__device__ __nv_bfloat16 g_zl[(size_t)BB*NN_*64];
__device__ float g_Wn_r[(size_t)NN_*256*128];
__device__ float g_Wn_u[(size_t)NN_*256*64];
__device__ float g_bias_r[NN_*128];
__device__ float g_bias_u[NN_*64];
__device__ float g_xb[(size_t)BB*NN_*128];
__device__ float g_zs[(size_t)BB*NN_*64];
__device__ float g_rb[(size_t)BB*NN_*64];
__device__ float g_c2[(size_t)BB*NN_*64];
__device__ unsigned int g_pos[BB];
__device__ unsigned int g_kept[BB];
__device__ float g_prob[2];

// ---------------- helpers ----------------
__device__ __forceinline__ float warpSum(float v){
  #pragma unroll
  for (int o=16;o;o>>=1) v += __shfl_xor_sync(0xffffffffu, v, o);
  return v;
}
__device__ __forceinline__ float warpMax(float v){
  #pragma unroll
  for (int o=16;o;o>>=1) v = fmaxf(v, __shfl_xor_sync(0xffffffffu, v, o));
  return v;
}
__device__ __forceinline__ float blockSum(float v, float* red){
  int lane = threadIdx.x & 31, w = threadIdx.x >> 5;
  int nw = blockDim.x >> 5;
  v = warpSum(v);
  __syncthreads();
  if (lane==0) red[w] = v;
  __syncthreads();
  float r = (threadIdx.x < (unsigned)nw) ? red[threadIdx.x] : 0.0f;
  if (w==0) r = warpSum(r);
  if (threadIdx.x==0) red[0] = r;
  __syncthreads();
  return red[0];
}
__device__ __forceinline__ float blockMax(float v, float* red){
  int lane = threadIdx.x & 31, w = threadIdx.x >> 5;
  int nw = blockDim.x >> 5;
  v = warpMax(v);
  __syncthreads();
  if (lane==0) red[w] = v;
  __syncthreads();
  float r = (threadIdx.x < (unsigned)nw) ? red[threadIdx.x] : -3.4e38f;
  if (w==0) r = warpMax(r);
  if (threadIdx.x==0) red[0] = r;
  __syncthreads();
  return red[0];
}
__device__ __forceinline__ uint32_t rotl32(uint32_t x, int r){
  return __funnelshift_l(x, x, r);
}
__device__ __forceinline__ void threefry2x32(uint32_t k0, uint32_t k1,
                                             uint32_t& x0, uint32_t& x1){
  uint32_t ks0 = k0, ks1 = k1, ks2 = k0 ^ k1 ^ 0x1BD11BDAu;
  x0 += ks0; x1 += ks1;
  const int R0[4] = {13,15,26,6};
  const int R1[4] = {17,29,16,24};
  uint32_t ks[3] = {ks0, ks1, ks2};
  #pragma unroll
  for (int i=0;i<5;i++){
    #pragma unroll
    for (int j=0;j<4;j++){
      int r = (i & 1) ? R1[j] : R0[j];
      x0 += x1; x1 = rotl32(x1, r); x1 ^= x0;
    }
    x0 += ks[(i+1)%3];
    x1 += ks[(i+2)%3] + (uint32_t)(i+1);
  }
}
__device__ __forceinline__ void split_bf16(float v, __nv_bfloat16& h, __nv_bfloat16& l){
  h = __float2bfloat16(v);
  l = __float2bfloat16(v - __bfloat162float(h));
}
__device__ __forceinline__ void ldsm4(uint32_t& r0,uint32_t& r1,uint32_t& r2,uint32_t& r3,
                                      const __nv_bfloat16* p){
  uint32_t a = (uint32_t)__cvta_generic_to_shared(p);
  asm volatile("ldmatrix.sync.aligned.m8n8.x4.shared.b16 {%0,%1,%2,%3},[%4];"
    : "=r"(r0),"=r"(r1),"=r"(r2),"=r"(r3) : "r"(a));
}
__device__ __forceinline__ void ldsm2t(uint32_t& r0,uint32_t& r1, const __nv_bfloat16* p){
  uint32_t a = (uint32_t)__cvta_generic_to_shared(p);
  asm volatile("ldmatrix.sync.aligned.m8n8.x2.trans.shared.b16 {%0,%1},[%2];"
    : "=r"(r0),"=r"(r1) : "r"(a));
}
__device__ __forceinline__ void mma16816(float* c, const uint32_t* a, const uint32_t* b){
  asm volatile("mma.sync.aligned.m16n8k16.row.col.f32.bf16.bf16.f32 "
    "{%0,%1,%2,%3},{%4,%5,%6,%7},{%8,%9},{%0,%1,%2,%3};"
    : "+f"(c[0]),"+f"(c[1]),"+f"(c[2]),"+f"(c[3])
    : "r"(a[0]),"r"(a[1]),"r"(a[2]),"r"(a[3]), "r"(b[0]),"r"(b[1]));
}

// ---------------- small kernels ----------------
__global__ void k_setup(const float* __restrict__ we, const int* __restrict__ itp){
  int tid = blockIdx.x*blockDim.x + threadIdx.x;
  float it = (float)itp[0];
  if (tid < NN_*EDIM){
    int d = tid & 15;
    int pair = d >> 1;
    float arg = (float)((double)(2*pair) * (-9.210340371976184/16.0));
    float div = expf(arg);
    float pe = (d & 1) ? cosf(it*div) : sinf(it*div);
    float e = we[tid] + pe;
    g_E[tid] = e;
    g_Et[d*NN_ + (tid>>4)] = e;
  }
  if (blockIdx.x==0 && threadIdx.x < 2*BB){
    if (threadIdx.x < BB) g_pos[threadIdx.x] = 0u;
    else                  g_kept[threadIdx.x-BB] = 0u;
  }
}

__global__ void k_bias(const float* __restrict__ bpr, const float* __restrict__ bpu){
  int n = blockIdx.x, o = threadIdx.x;
  __shared__ float en[EDIM];
  if (o < EDIM) en[o] = g_E[n*EDIM+o];
  __syncthreads();
  float a = 0.f;
  #pragma unroll
  for (int d=0; d<EDIM; d++) a += en[d]*bpr[d*128+o];
  g_bias_r[n*128+o] = a;
  if (o < 64){
    float b = 0.f;
    #pragma unroll
    for (int d=0; d<EDIM; d++) b += en[d]*bpu[d*64+o];
    g_bias_u[n*64+o] = b;
  }
}

__global__ void k_em(const float* __restrict__ mp){
  int n = blockIdx.x;
  __shared__ float en[EDIM];
  if (threadIdx.x < EDIM) en[threadIdx.x] = g_E[n*EDIM+threadIdx.x];
  __syncthreads();
  for (int m=threadIdx.x; m<NN_; m+=blockDim.x){
    float a = 0.f;
    #pragma unroll
    for (int d=0; d<EDIM; d++) a += en[d]*mp[d*NN_+m];
    g_EM[n*NN_+m] = a;
  }
}

__global__ void k_supports(){
  int n = blockIdx.x;
  __shared__ float row[NN_];
  __shared__ float red[32];
  float en[EDIM];
  #pragma unroll
  for (int d=0; d<EDIM; d++) en[d] = g_E[n*EDIM+d];
  float vmax = -3.4e38f;
  for (int m=threadIdx.x; m<NN_; m+=blockDim.x){
    float a = 0.f;
    #pragma unroll
    for (int d=0; d<EDIM; d++) a += en[d]*g_Et[d*NN_+m];
    a = fmaxf(a, 0.f);
    row[m] = a;
    vmax = fmaxf(vmax, a);
  }
  vmax = blockMax(vmax, red);
  float s = 0.f;
  for (int m=threadIdx.x; m<NN_; m+=blockDim.x){
    float e = __expf(row[m]-vmax);
    row[m] = e; s += e;
  }
  s = blockSum(s, red);
  float inv = 1.0f/s;
  for (int m=threadIdx.x; m<NN_; m+=blockDim.x)
    g_supports[n*NN_+m] = row[m]*inv;
}

// cat(x,state) -> bf16 hi/lo, layout [b][k][128]
__global__ void k_prep(const float* __restrict__ x, const float* __restrict__ st){
  int t = blockIdx.x*blockDim.x + threadIdx.x;
  if (t >= BB*NN_*128) return;
  int j = t & 127; int bn = t >> 7;
  float v = (j<64) ? x[(size_t)bn*64 + j] : st[(size_t)bn*64 + (j-64)];
  __nv_bfloat16 h, l; split_bf16(v, h, l);
  g_xh[t] = h; g_xl[t] = l;
}

template<int OC, bool IS_R>
__global__ void k_wgen(const float* __restrict__ Wp){
  float* Wn = IS_R ? (float*)g_Wn_r : (float*)g_Wn_u;
  int n0 = blockIdx.y*64;
  int i20 = blockIdx.x*16;
  int o = threadIdx.x;
  __shared__ float Esm[64][EDIM];
  for (int t=threadIdx.x; t<64*EDIM; t+=OC)
    Esm[t>>4][t&15] = g_E[(n0 + (t>>4))*EDIM + (t&15)];
  __syncthreads();
  for (int ii=0; ii<16; ii++){
    int i2 = i20+ii;
    float w[EDIM];
    #pragma unroll
    for (int d=0; d<EDIM; d++) w[d] = Wp[((size_t)d*256 + i2)*OC + o];
    #pragma unroll 4
    for (int nn=0; nn<64; nn++){
      float a = 0.f;
      #pragma unroll
      for (int d=0; d<EDIM; d++) a += Esm[nn][d]*w[d];
      Wn[((size_t)(n0+nn)*256 + i2)*OC + o] = a;
    }
  }
}

// Fused: time-gram softmax + raw_mask + threshold mask + sup (bf16 hi/lo) + bits.
__global__ void k_supmask(const float* __restrict__ T, const float* __restrict__ TP,
                          const float* __restrict__ gamma, const float* __restrict__ beta,
                          float* __restrict__ out_mask){
  extern __shared__ float sm[];
  float* Tsm  = sm;
  float* TPsm = sm + WINDOW*NN_;
  float* row  = TPsm + WINDOW*NN_;
  __shared__ float red[32];
  int b = blockIdx.y;
  int n0 = blockIdx.x*16;
  int lane = threadIdx.x & 31;
  for (int t=threadIdx.x; t<WINDOW*NN_; t+=blockDim.x){
    Tsm[t]  = T[(size_t)b*WINDOW*NN_ + t];
    TPsm[t] = TP[t];
  }
  __syncthreads();
  const float bni = 1.0f/sqrtf(1.0f + 1e-5f);
  unsigned int cnt = 0;
  for (int r16=0; r16<16; r16++){
    int n = n0 + r16;
    float tv[WINDOW];
    #pragma unroll
    for (int w=0; w<WINDOW; w++) tv[w] = Tsm[w*NN_+n];
    float vmax = -3.4e38f;
    for (int m=threadIdx.x; m<NN_; m+=blockDim.x){
      float tg = 0.f;
      #pragma unroll
      for (int w=0; w<WINDOW; w++) tg += tv[w]*Tsm[w*NN_+m];
      tg = fmaxf(tg, 0.f);
      row[m] = tg;
      vmax = fmaxf(vmax, tg);
    }
    vmax = blockMax(vmax, red);
    float s = 0.f;
    for (int m=threadIdx.x; m<NN_; m+=blockDim.x){
      float e = __expf(row[m]-vmax);
      row[m] = e; s += e;
    }
    s = blockSum(s, red);
    float inv = 1.0f/s;
    float gn = gamma[n], bt = beta[n];
    for (int m=threadIdx.x; m<NN_; m+=blockDim.x){
      float ts = row[m]*inv;
      float rm = g_EM[n*NN_+m];
      #pragma unroll
      for (int w=0; w<WINDOW; w++) rm += tv[w]*TPsm[w*NN_+m];
      rm = rm*bni*gn + bt;
      float mk = (rm > MASK_THR) ? 1.0f : 0.0f;
      size_t idx = (size_t)b*NNSQ + (size_t)n*NN_ + m;
      out_mask[idx] = mk;
      float supv = (g_supports[n*NN_+m] + ts)*0.5f*mk;
      __nv_bfloat16 h, l; split_bf16(supv, h, l);
      g_sh[idx] = h; g_sl[idx] = l;
      cnt += (mk > 0.0f) ? 1u : 0u;
      unsigned bal = __ballot_sync(0xffffffffu, mk > 0.0f);
      if (lane==0) g_bits[idx>>5] = bal;
    }
    __syncthreads();
  }
  float fc = blockSum((float)cnt, red);
  if (threadIdx.x==0) atomicAdd(&g_pos[b], (unsigned int)(fc + 0.5f));
}

__global__ void k_prob(){
  unsigned int tot = 0;
  for (int i=0;i<BB;i++) tot += g_pos[i];
  float active = (float)tot / (float)BNN;
  float p = 0.05f/active + 1e-8f;
  g_prob[0] = fminf(p, 1.0f);
  g_prob[1] = fmaxf(0.05f/active - 1.0f, 0.0f);
}

__global__ void k_kept(){
  __shared__ unsigned int cnt[BB];
  if (threadIdx.x < BB) cnt[threadIdx.x] = 0u;
  __syncthreads();
  float prob = g_prob[0];
  int lane = threadIdx.x & 31;
  unsigned int base = blockIdx.x*1024u + threadIdx.x;
  #pragma unroll
  for (int k=0;k<4;k++){
    unsigned int t = base + (unsigned)k*256u;
    uint32_t x0 = t, x1 = t + (uint32_t)HALF_BNN;
    threefry2x32(0u, 42u, x0, x1);
    float u0 = __uint_as_float((x0>>9) | 0x3f800000u) - 1.0f;
    float u1 = __uint_as_float((x1>>9) | 0x3f800000u) - 1.0f;
    uint32_t w0 = g_bits[t>>5];
    uint32_t w1 = g_bits[(t + HALF_BNN)>>5];
    int b0 = (int)(t >> 20);
    bool keep0 = ((w0>>lane)&1u) && !(u0 < prob);
    bool keep1 = ((w1>>lane)&1u) && !(u1 < prob);
    unsigned bal0 = __ballot_sync(0xffffffffu, keep0);
    unsigned bal1 = __ballot_sync(0xffffffffu, keep1);
    if (lane==0){
      if (bal0) atomicAdd(&cnt[b0],   __popc(bal0));
      if (bal1) atomicAdd(&cnt[b0+8], __popc(bal1));
    }
  }
  __syncthreads();
  if (threadIdx.x < BB && cnt[threadIdx.x]) atomicAdd(&g_kept[threadIdx.x], cnt[threadIdx.x]);
}

__global__ void k_loss(float* __restrict__ out_loss){
  int b = threadIdx.x;
  if (b < BB)
    out_loss[b] = (float)g_kept[b] / ((float)g_pos[b] + 1e-8f) + g_prob[1];
}

// C[b] = sup[b](1024x1024) @ X[b](1024xNO), bf16 hi/lo 3-term mma.
template<int NO>
__global__ void k_mma(const __nv_bfloat16* __restrict__ Bh, const __nv_bfloat16* __restrict__ Bl,
                      float* __restrict__ C){
  constexpr int NWN = NO/64;
  constexpr int NWM = 8/NWN;
  constexpr int WM  = 128/NWM;       // 32 or 16
  constexpr int MFR = WM/16;         // 2 or 1
  constexpr int BST = NO+8;
  __shared__ __nv_bfloat16 Ash[128*40], Asl[128*40];
  __shared__ __nv_bfloat16 Bsh[32*BST], Bsl[32*BST];
  int b = blockIdx.y;
  int m0 = blockIdx.x*128;
  int w = threadIdx.x>>5, lane = threadIdx.x&31;
  int wm = (w / NWN)*WM;
  int wn = (w % NWN)*64;
  float acc[MFR][8][4];
  #pragma unroll
  for (int i=0;i<MFR;i++)
    #pragma unroll
    for (int j=0;j<8;j++)
      #pragma unroll
      for (int q=0;q<4;q++) acc[i][j][q] = 0.f;
  const __nv_bfloat16* Ahb = g_sh + (size_t)b*NNSQ;
  const __nv_bfloat16* Alb = g_sl + (size_t)b*NNSQ;
  const __nv_bfloat16* Bhb = Bh + (size_t)b*NN_*NO;
  const __nv_bfloat16* Blb = Bl + (size_t)b*NN_*NO;
  for (int k0=0;k0<NN_;k0+=32){
    #pragma unroll
    for (int i = threadIdx.x; i<512; i+=256){
      int r = i>>2, c = i&3;
      *(uint4*)&Ash[r*40 + c*8] = *(const uint4*)&Ahb[(size_t)(m0+r)*NN_ + k0 + c*8];
      *(uint4*)&Asl[r*40 + c*8] = *(const uint4*)&Alb[(size_t)(m0+r)*NN_ + k0 + c*8];
    }
    #pragma unroll
    for (int i = threadIdx.x; i<32*NO/8; i+=256){
      int r = i/(NO/8), c = i%(NO/8);
      *(uint4*)&Bsh[r*BST + c*8] = *(const uint4*)&Bhb[(size_t)(k0+r)*NO + c*8];
      *(uint4*)&Bsl[r*BST + c*8] = *(const uint4*)&Blb[(size_t)(k0+r)*NO + c*8];
    }
    __syncthreads();
    #pragma unroll
    for (int kk=0; kk<2; kk++){
      uint32_t ah[MFR][4], al[MFR][4];
      #pragma unroll
      for (int i=0;i<MFR;i++){
        int ar = (wm + i*16 + (lane&15))*40 + kk*16 + (lane>>4)*8;
        ldsm4(ah[i][0],ah[i][1],ah[i][2],ah[i][3], &Ash[ar]);
        ldsm4(al[i][0],al[i][1],al[i][2],al[i][3], &Asl[ar]);
      }
      #pragma unroll
      for (int j=0;j<8;j++){
        uint32_t bh[2], bl[2];
        int br = (kk*16 + (lane&15))*BST + wn + j*8;
        ldsm2t(bh[0],bh[1], &Bsh[br]);
        ldsm2t(bl[0],bl[1], &Bsl[br]);
        #pragma unroll
        for (int i=0;i<MFR;i++){
          mma16816(acc[i][j], ah[i], bh);
          mma16816(acc[i][j], ah[i], bl);
          mma16816(acc[i][j], al[i], bh);
        }
      }
    }
    __syncthreads();
  }
  #pragma unroll
  for (int i=0;i<MFR;i++)
    #pragma unroll
    for (int j=0;j<8;j++){
      int r0 = m0 + wm + i*16 + (lane>>2);
      int c0 = wn + j*8 + (lane&3)*2;
      float* Cp = C + ((size_t)b*NN_ + r0)*NO + c0;
      Cp[0] = acc[i][j][0]; Cp[1] = acc[i][j][1];
      Cp[(size_t)8*NO] = acc[i][j][2]; Cp[(size_t)8*NO+1] = acc[i][j][3];
    }
}

__global__ void k_gate_r(const float* __restrict__ x, const float* __restrict__ st){
  int n = blockIdx.x;
  int o = threadIdx.x; // 128
  __shared__ float Xg[16][256];
  for (int t=threadIdx.x; t<16*256; t+=128){
    int b = t>>8, i = t&255;
    float v;
    if (i < 64)       v = x[((size_t)b*NN_+n)*64 + i];
    else if (i < 128) v = st[((size_t)b*NN_+n)*64 + (i-64)];
    else              v = g_xb[((size_t)b*NN_+n)*128 + (i-128)];
    Xg[b][i] = v;
  }
  __syncthreads();
  float acc[16] = {};
  const float* W = g_Wn_r + (size_t)n*256*128 + o;
  #pragma unroll 4
  for (int i=0;i<256;i++){
    float w = W[(size_t)i*128];
    #pragma unroll
    for (int b=0;b<16;b++) acc[b] += Xg[b][i]*w;
  }
  float bias = g_bias_r[n*128+o];
  #pragma unroll
  for (int b=0;b<16;b++){
    float g = 1.0f/(1.0f+__expf(-(acc[b]+bias)));
    size_t idx = ((size_t)b*NN_+n)*64;
    if (o < 64){
      float zsv = g * st[idx + o];
      g_zs[idx + o] = zsv;
      __nv_bfloat16 h, l; split_bf16(zsv, h, l);
      g_zh[idx + o] = h; g_zl[idx + o] = l;
    } else {
      g_rb[idx + (o-64)] = g;
    }
  }
}

__global__ void k_gate_u(const float* __restrict__ x, const float* __restrict__ st,
                         float* __restrict__ out_h){
  int n = blockIdx.x;
  int o = threadIdx.x; // 64
  __shared__ float Xg[16][256];
  for (int t=threadIdx.x; t<16*256; t+=64){
    int b = t>>8, i = t&255;
    float v;
    if (i < 64)       v = x[((size_t)b*NN_+n)*64 + i];
    else if (i < 128) v = g_zs[((size_t)b*NN_+n)*64 + (i-64)];
    else if (i < 192) v = g_xb[((size_t)b*NN_+n)*128 + (i-128)];
    else              v = g_c2[((size_t)b*NN_+n)*64 + (i-192)];
    Xg[b][i] = v;
  }
  __syncthreads();
  float acc[16] = {};
  const float* W = g_Wn_u + (size_t)n*256*64 + o;
  #pragma unroll 4
  for (int i=0;i<256;i++){
    float w = W[(size_t)i*64];
    #pragma unroll
    for (int b=0;b<16;b++) acc[b] += Xg[b][i]*w;
  }
  float bias = g_bias_u[n*64+o];
  #pragma unroll
  for (int b=0;b<16;b++){
    float hc = tanhf(acc[b]+bias);
    float r = g_rb[((size_t)b*NN_+n)*64 + o];
    float sv = st[((size_t)b*NN_+n)*64 + o];
    out_h[((size_t)b*NN_+n)*64 + o] = r*sv + (1.0f-r)*hc;
  }
}

// ---------------- launch ----------------
extern "C" void kernel_launch(void* const* d_in, const int* in_sizes, int n_in,
                              void* d_out, int out_size){
  const float* x    = (const float*)d_in[0];
  const float* st   = (const float*)d_in[1];
  const float* we   = (const float*)d_in[2];
  const float* T    = (const float*)d_in[3];
  const float* Wpr  = (const float*)d_in[4];
  const float* bpr  = (const float*)d_in[5];
  const float* Wpu  = (const float*)d_in[6];
  const float* bpu  = (const float*)d_in[7];
  const float* mp   = (const float*)d_in[8];
  const float* tp   = (const float*)d_in[9];
  const float* gmm  = (const float*)d_in[10];
  const float* bta  = (const float*)d_in[11];
  const int*   itp  = (const int*)d_in[12];
  float* out = (float*)d_out;
  float* out_mask = out + OFF_MASK;

  static __nv_bfloat16 *xh_p=nullptr, *xl_p=nullptr, *zh_p=nullptr, *zl_p=nullptr;
  static float *xb_p=nullptr, *c2_p=nullptr;
  if (!xh_p){
    cudaGetSymbolAddress((void**)&xh_p, g_xh);
    cudaGetSymbolAddress((void**)&xl_p, g_xl);
    cudaGetSymbolAddress((void**)&zh_p, g_zh);
    cudaGetSymbolAddress((void**)&zl_p, g_zl);
    cudaGetSymbolAddress((void**)&xb_p, g_xb);
    cudaGetSymbolAddress((void**)&c2_p, g_c2);
  }

  k_setup<<<64,256>>>(we, itp);
  k_bias<<<NN_,128>>>(bpr, bpu);
  k_em<<<NN_,256>>>(mp);
  k_supports<<<NN_,256>>>();
  k_prep<<<8192,256>>>(x, st);
  k_wgen<128,true><<<dim3(16,16),128>>>(Wpr);
  k_wgen<64,false><<<dim3(16,16),64>>>(Wpu);

  size_t smem_sup = (size_t)(2*WINDOW*NN_ + NN_)*sizeof(float);
  cudaFuncSetAttribute(k_supmask, cudaFuncAttributeMaxDynamicSharedMemorySize, (int)smem_sup);
  k_supmask<<<dim3(64,16),256,smem_sup>>>(T, tp, gmm, bta, out_mask);

  k_prob<<<1,1>>>();
  k_kept<<<8192,256>>>();
  k_loss<<<1,16>>>(out + OFF_LOSS);

  k_mma<128><<<dim3(8,16),256>>>(xh_p, xl_p, xb_p);
  k_gate_r<<<NN_,128>>>(x, st);
  k_mma<64><<<dim3(8,16),256>>>(zh_p, zl_p, c2_p);
  k_gate_u<<<NN_,64>>>(x, st, out);
}

// round 5
// speedup vs baseline: 1.3874x; 1.1956x over previous
#include <cuda_runtime.h>
#include <cuda_bf16.h>
#include <cstdint>
#include <math.h>

#define BB 16
#define NN_ 1024
#define EDIM 16
#define WINDOW 12
#define NNSQ (NN_*NN_)
#define BNN (BB*NNSQ)
#define HALF_BNN (BNN/2)
#define OFF_MASK (BB*NN_*64)
#define OFF_LOSS (OFF_MASK + BNN)
#define MASK_THR (-2.66352776f)   /* ln(1.4) - 3 */

// ---------------- scratch ----------------
__device__ float g_E[NN_*EDIM];
__device__ float g_Et[EDIM*NN_];
__device__ float g_EM[NNSQ];
__device__ float g_supports[NNSQ];
__device__ __nv_bfloat16 g_sh[(size_t)BNN];
__device__ __nv_bfloat16 g_sl[(size_t)BNN];
__device__ uint32_t g_bits[BNN/32];
__device__ __nv_bfloat16 g_xh[(size_t)BB*NN_*128];
__device__ __nv_bfloat16 g_xl[(size_t)BB*NN_*128];
__device__ __nv_bfloat16 g_zh[(size_t)BB*NN_*64];
__device__ __nv_bfloat16 g_zl[(size_t)BB*NN_*64];
__device__ float g_Wn_r[(size_t)NN_*256*128];
__device__ float g_Wn_u[(size_t)NN_*256*64];
__device__ float g_bias_r[NN_*128];
__device__ float g_bias_u[NN_*64];
__device__ float g_xb[(size_t)BB*NN_*128];
__device__ float g_zs[(size_t)BB*NN_*64];
__device__ float g_rb[(size_t)BB*NN_*64];
__device__ float g_c2[(size_t)BB*NN_*64];
__device__ unsigned int g_pos[BB];
__device__ unsigned int g_kept[BB];

// ---------------- helpers ----------------
__device__ __forceinline__ float warpSum(float v){
  #pragma unroll
  for (int o=16;o;o>>=1) v += __shfl_xor_sync(0xffffffffu, v, o);
  return v;
}
__device__ __forceinline__ float warpMax(float v){
  #pragma unroll
  for (int o=16;o;o>>=1) v = fmaxf(v, __shfl_xor_sync(0xffffffffu, v, o));
  return v;
}
__device__ __forceinline__ float blockSum(float v, float* red){
  int lane = threadIdx.x & 31, w = threadIdx.x >> 5;
  int nw = blockDim.x >> 5;
  v = warpSum(v);
  __syncthreads();
  if (lane==0) red[w] = v;
  __syncthreads();
  float r = (threadIdx.x < (unsigned)nw) ? red[threadIdx.x] : 0.0f;
  if (w==0) r = warpSum(r);
  if (threadIdx.x==0) red[0] = r;
  __syncthreads();
  return red[0];
}
__device__ __forceinline__ float blockMax(float v, float* red){
  int lane = threadIdx.x & 31, w = threadIdx.x >> 5;
  int nw = blockDim.x >> 5;
  v = warpMax(v);
  __syncthreads();
  if (lane==0) red[w] = v;
  __syncthreads();
  float r = (threadIdx.x < (unsigned)nw) ? red[threadIdx.x] : -3.4e38f;
  if (w==0) r = warpMax(r);
  if (threadIdx.x==0) red[0] = r;
  __syncthreads();
  return red[0];
}
__device__ __forceinline__ uint32_t rotl32(uint32_t x, int r){
  return __funnelshift_l(x, x, r);
}
__device__ __forceinline__ void threefry2x32(uint32_t k0, uint32_t k1,
                                             uint32_t& x0, uint32_t& x1){
  uint32_t ks0 = k0, ks1 = k1, ks2 = k0 ^ k1 ^ 0x1BD11BDAu;
  x0 += ks0; x1 += ks1;
  const int R0[4] = {13,15,26,6};
  const int R1[4] = {17,29,16,24};
  uint32_t ks[3] = {ks0, ks1, ks2};
  #pragma unroll
  for (int i=0;i<5;i++){
    #pragma unroll
    for (int j=0;j<4;j++){
      int r = (i & 1) ? R1[j] : R0[j];
      x0 += x1; x1 = rotl32(x1, r); x1 ^= x0;
    }
    x0 += ks[(i+1)%3];
    x1 += ks[(i+2)%3] + (uint32_t)(i+1);
  }
}
__device__ __forceinline__ void split_bf16(float v, __nv_bfloat16& h, __nv_bfloat16& l){
  h = __float2bfloat16(v);
  l = __float2bfloat16(v - __bfloat162float(h));
}
__device__ __forceinline__ void ldsm4(uint32_t& r0,uint32_t& r1,uint32_t& r2,uint32_t& r3,
                                      const __nv_bfloat16* p){
  uint32_t a = (uint32_t)__cvta_generic_to_shared(p);
  asm volatile("ldmatrix.sync.aligned.m8n8.x4.shared.b16 {%0,%1,%2,%3},[%4];"
    : "=r"(r0),"=r"(r1),"=r"(r2),"=r"(r3) : "r"(a));
}
__device__ __forceinline__ void ldsm2t(uint32_t& r0,uint32_t& r1, const __nv_bfloat16* p){
  uint32_t a = (uint32_t)__cvta_generic_to_shared(p);
  asm volatile("ldmatrix.sync.aligned.m8n8.x2.trans.shared.b16 {%0,%1},[%2];"
    : "=r"(r0),"=r"(r1) : "r"(a));
}
__device__ __forceinline__ void mma16816(float* c, const uint32_t* a, const uint32_t* b){
  asm volatile("mma.sync.aligned.m16n8k16.row.col.f32.bf16.bf16.f32 "
    "{%0,%1,%2,%3},{%4,%5,%6,%7},{%8,%9},{%0,%1,%2,%3};"
    : "+f"(c[0]),"+f"(c[1]),"+f"(c[2]),"+f"(c[3])
    : "r"(a[0]),"r"(a[1]),"r"(a[2]),"r"(a[3]), "r"(b[0]),"r"(b[1]));
}
__device__ __forceinline__ float prob_from_pos(){
  unsigned int tot = 0;
  #pragma unroll
  for (int i=0;i<BB;i++) tot += g_pos[i];
  float active = (float)tot / (float)BNN;
  return fminf(0.05f/active + 1e-8f, 1.0f);
}

// ---------------- small kernels ----------------
__global__ void k_setup(const float* __restrict__ we, const int* __restrict__ itp){
  int tid = blockIdx.x*blockDim.x + threadIdx.x;
  float it = (float)itp[0];
  if (tid < NN_*EDIM){
    int d = tid & 15;
    int pair = d >> 1;
    float arg = (float)((double)(2*pair) * (-9.210340371976184/16.0));
    float div = expf(arg);
    float pe = (d & 1) ? cosf(it*div) : sinf(it*div);
    float e = we[tid] + pe;
    g_E[tid] = e;
    g_Et[d*NN_ + (tid>>4)] = e;
  }
  if (blockIdx.x==0 && threadIdx.x < 2*BB){
    if (threadIdx.x < BB) g_pos[threadIdx.x] = 0u;
    else                  g_kept[threadIdx.x-BB] = 0u;
  }
}

__global__ void k_bias(const float* __restrict__ bpr, const float* __restrict__ bpu){
  int n = blockIdx.x, o = threadIdx.x;
  __shared__ float en[EDIM];
  if (o < EDIM) en[o] = g_E[n*EDIM+o];
  __syncthreads();
  float a = 0.f;
  #pragma unroll
  for (int d=0; d<EDIM; d++) a += en[d]*bpr[d*128+o];
  g_bias_r[n*128+o] = a;
  if (o < 64){
    float b = 0.f;
    #pragma unroll
    for (int d=0; d<EDIM; d++) b += en[d]*bpu[d*64+o];
    g_bias_u[n*64+o] = b;
  }
}

__global__ void k_em(const float* __restrict__ mp){
  int n = blockIdx.x;
  __shared__ float en[EDIM];
  if (threadIdx.x < EDIM) en[threadIdx.x] = g_E[n*EDIM+threadIdx.x];
  __syncthreads();
  for (int m=threadIdx.x; m<NN_; m+=blockDim.x){
    float a = 0.f;
    #pragma unroll
    for (int d=0; d<EDIM; d++) a += en[d]*mp[d*NN_+m];
    g_EM[n*NN_+m] = a;
  }
}

__global__ void k_supports(){
  int n = blockIdx.x;
  __shared__ float row[NN_];
  __shared__ float red[32];
  float en[EDIM];
  #pragma unroll
  for (int d=0; d<EDIM; d++) en[d] = g_E[n*EDIM+d];
  float vmax = -3.4e38f;
  for (int m=threadIdx.x; m<NN_; m+=blockDim.x){
    float a = 0.f;
    #pragma unroll
    for (int d=0; d<EDIM; d++) a += en[d]*g_Et[d*NN_+m];
    a = fmaxf(a, 0.f);
    row[m] = a;
    vmax = fmaxf(vmax, a);
  }
  vmax = blockMax(vmax, red);
  float s = 0.f;
  for (int m=threadIdx.x; m<NN_; m+=blockDim.x){
    float e = __expf(row[m]-vmax);
    row[m] = e; s += e;
  }
  s = blockSum(s, red);
  float inv = 1.0f/s;
  for (int m=threadIdx.x; m<NN_; m+=blockDim.x)
    g_supports[n*NN_+m] = row[m]*inv;
}

__global__ void k_prep(const float* __restrict__ x, const float* __restrict__ st){
  int t = blockIdx.x*blockDim.x + threadIdx.x;
  if (t >= BB*NN_*128) return;
  int j = t & 127; int bn = t >> 7;
  float v = (j<64) ? x[(size_t)bn*64 + j] : st[(size_t)bn*64 + (j-64)];
  __nv_bfloat16 h, l; split_bf16(v, h, l);
  g_xh[t] = h; g_xl[t] = l;
}

// Wn[n,i2,o] = sum_d E[n,d] * W_pool[d,i2,o]  (float4 I/O)
template<int OC, bool IS_R>
__global__ void k_wgen(const float* __restrict__ Wp){
  float* Wn = IS_R ? (float*)g_Wn_r : (float*)g_Wn_u;
  constexpr int NQ = OC/4;
  constexpr int NI = 128/NQ;
  int n0 = blockIdx.y*64;
  int i20 = blockIdx.x*16;
  int t = threadIdx.x;
  int oq = t % NQ, ig = t / NQ;
  __shared__ float Esm[64][EDIM];
  for (int q=t; q<64*EDIM; q+=128)
    Esm[q>>4][q&15] = g_E[(n0 + (q>>4))*EDIM + (q&15)];
  __syncthreads();
  for (int ii=ig; ii<16; ii+=NI){
    int i2 = i20+ii;
    float4 w[EDIM];
    #pragma unroll
    for (int d=0; d<EDIM; d++)
      w[d] = *(const float4*)&Wp[((size_t)d*256 + i2)*OC + oq*4];
    #pragma unroll 4
    for (int nn=0; nn<64; nn++){
      float4 a = make_float4(0.f,0.f,0.f,0.f);
      #pragma unroll
      for (int d=0; d<EDIM; d++){
        float e = Esm[nn][d];
        a.x += e*w[d].x; a.y += e*w[d].y; a.z += e*w[d].z; a.w += e*w[d].w;
      }
      *(float4*)&Wn[((size_t)(n0+nn)*256 + i2)*OC + oq*4] = a;
    }
  }
}

__global__ void k_supmask(const float* __restrict__ T, const float* __restrict__ TP,
                          const float* __restrict__ gamma, const float* __restrict__ beta,
                          float* __restrict__ out_mask){
  extern __shared__ float sm[];
  float* Tsm  = sm;
  float* TPsm = sm + WINDOW*NN_;
  float* row  = TPsm + WINDOW*NN_;
  __shared__ float red[32];
  int b = blockIdx.y;
  int n0 = blockIdx.x*16;
  int lane = threadIdx.x & 31;
  for (int t=threadIdx.x; t<WINDOW*NN_; t+=blockDim.x){
    Tsm[t]  = T[(size_t)b*WINDOW*NN_ + t];
    TPsm[t] = TP[t];
  }
  __syncthreads();
  const float bni = 1.0f/sqrtf(1.0f + 1e-5f);
  unsigned int cnt = 0;
  for (int r16=0; r16<16; r16++){
    int n = n0 + r16;
    float tv[WINDOW];
    #pragma unroll
    for (int w=0; w<WINDOW; w++) tv[w] = Tsm[w*NN_+n];
    float vmax = -3.4e38f;
    for (int m=threadIdx.x; m<NN_; m+=blockDim.x){
      float tg = 0.f;
      #pragma unroll
      for (int w=0; w<WINDOW; w++) tg += tv[w]*Tsm[w*NN_+m];
      tg = fmaxf(tg, 0.f);
      row[m] = tg;
      vmax = fmaxf(vmax, tg);
    }
    vmax = blockMax(vmax, red);
    float s = 0.f;
    for (int m=threadIdx.x; m<NN_; m+=blockDim.x){
      float e = __expf(row[m]-vmax);
      row[m] = e; s += e;
    }
    s = blockSum(s, red);
    float inv = 1.0f/s;
    float gn = gamma[n], bt = beta[n];
    for (int m=threadIdx.x; m<NN_; m+=blockDim.x){
      float ts = row[m]*inv;
      float rm = g_EM[n*NN_+m];
      #pragma unroll
      for (int w=0; w<WINDOW; w++) rm += tv[w]*TPsm[w*NN_+m];
      rm = rm*bni*gn + bt;
      float mk = (rm > MASK_THR) ? 1.0f : 0.0f;
      size_t idx = (size_t)b*NNSQ + (size_t)n*NN_ + m;
      out_mask[idx] = mk;
      float supv = (g_supports[n*NN_+m] + ts)*0.5f*mk;
      __nv_bfloat16 h, l; split_bf16(supv, h, l);
      g_sh[idx] = h; g_sl[idx] = l;
      cnt += (mk > 0.0f) ? 1u : 0u;
      unsigned bal = __ballot_sync(0xffffffffu, mk > 0.0f);
      if (lane==0) g_bits[idx>>5] = bal;
    }
    __syncthreads();
  }
  float fc = blockSum((float)cnt, red);
  if (threadIdx.x==0) atomicAdd(&g_pos[b], (unsigned int)(fc + 0.5f));
}

__global__ void k_kept(){
  __shared__ unsigned int cnt[BB];
  if (threadIdx.x < BB) cnt[threadIdx.x] = 0u;
  __syncthreads();
  float prob = prob_from_pos();
  int lane = threadIdx.x & 31;
  unsigned int base = blockIdx.x*1024u + threadIdx.x;
  #pragma unroll
  for (int k=0;k<4;k++){
    unsigned int t = base + (unsigned)k*256u;
    uint32_t x0 = t, x1 = t + (uint32_t)HALF_BNN;
    threefry2x32(0u, 42u, x0, x1);
    float u0 = __uint_as_float((x0>>9) | 0x3f800000u) - 1.0f;
    float u1 = __uint_as_float((x1>>9) | 0x3f800000u) - 1.0f;
    uint32_t w0 = g_bits[t>>5];
    uint32_t w1 = g_bits[(t + HALF_BNN)>>5];
    int b0 = (int)(t >> 20);
    bool keep0 = ((w0>>lane)&1u) && !(u0 < prob);
    bool keep1 = ((w1>>lane)&1u) && !(u1 < prob);
    unsigned bal0 = __ballot_sync(0xffffffffu, keep0);
    unsigned bal1 = __ballot_sync(0xffffffffu, keep1);
    if (lane==0){
      if (bal0) atomicAdd(&cnt[b0],   __popc(bal0));
      if (bal1) atomicAdd(&cnt[b0+8], __popc(bal1));
    }
  }
  __syncthreads();
  if (threadIdx.x < BB && cnt[threadIdx.x]) atomicAdd(&g_kept[threadIdx.x], cnt[threadIdx.x]);
}

__global__ void k_loss(float* __restrict__ out_loss){
  unsigned int tot = 0;
  #pragma unroll
  for (int i=0;i<BB;i++) tot += g_pos[i];
  float active = (float)tot / (float)BNN;
  float addend = fmaxf(0.05f/active - 1.0f, 0.0f);
  int b = threadIdx.x;
  if (b < BB)
    out_loss[b] = (float)g_kept[b] / ((float)g_pos[b] + 1e-8f) + addend;
}

template<int NO>
__global__ void k_mma(const __nv_bfloat16* __restrict__ Bh, const __nv_bfloat16* __restrict__ Bl,
                      float* __restrict__ C){
  constexpr int NWN = NO/64;
  constexpr int NWM = 8/NWN;
  constexpr int WM  = 128/NWM;
  constexpr int MFR = WM/16;
  constexpr int BST = NO+8;
  __shared__ __nv_bfloat16 Ash[128*40], Asl[128*40];
  __shared__ __nv_bfloat16 Bsh[32*BST], Bsl[32*BST];
  int b = blockIdx.y;
  int m0 = blockIdx.x*128;
  int w = threadIdx.x>>5, lane = threadIdx.x&31;
  int wm = (w / NWN)*WM;
  int wn = (w % NWN)*64;
  float acc[MFR][8][4];
  #pragma unroll
  for (int i=0;i<MFR;i++)
    #pragma unroll
    for (int j=0;j<8;j++)
      #pragma unroll
      for (int q=0;q<4;q++) acc[i][j][q] = 0.f;
  const __nv_bfloat16* Ahb = g_sh + (size_t)b*NNSQ;
  const __nv_bfloat16* Alb = g_sl + (size_t)b*NNSQ;
  const __nv_bfloat16* Bhb = Bh + (size_t)b*NN_*NO;
  const __nv_bfloat16* Blb = Bl + (size_t)b*NN_*NO;
  for (int k0=0;k0<NN_;k0+=32){
    #pragma unroll
    for (int i = threadIdx.x; i<512; i+=256){
      int r = i>>2, c = i&3;
      *(uint4*)&Ash[r*40 + c*8] = *(const uint4*)&Ahb[(size_t)(m0+r)*NN_ + k0 + c*8];
      *(uint4*)&Asl[r*40 + c*8] = *(const uint4*)&Alb[(size_t)(m0+r)*NN_ + k0 + c*8];
    }
    #pragma unroll
    for (int i = threadIdx.x; i<32*NO/8; i+=256){
      int r = i/(NO/8), c = i%(NO/8);
      *(uint4*)&Bsh[r*BST + c*8] = *(const uint4*)&Bhb[(size_t)(k0+r)*NO + c*8];
      *(uint4*)&Bsl[r*BST + c*8] = *(const uint4*)&Blb[(size_t)(k0+r)*NO + c*8];
    }
    __syncthreads();
    #pragma unroll
    for (int kk=0; kk<2; kk++){
      uint32_t ah[MFR][4], al[MFR][4];
      #pragma unroll
      for (int i=0;i<MFR;i++){
        int ar = (wm + i*16 + (lane&15))*40 + kk*16 + (lane>>4)*8;
        ldsm4(ah[i][0],ah[i][1],ah[i][2],ah[i][3], &Ash[ar]);
        ldsm4(al[i][0],al[i][1],al[i][2],al[i][3], &Asl[ar]);
      }
      #pragma unroll
      for (int j=0;j<8;j++){
        uint32_t bh[2], bl[2];
        int br = (kk*16 + (lane&15))*BST + wn + j*8;
        ldsm2t(bh[0],bh[1], &Bsh[br]);
        ldsm2t(bl[0],bl[1], &Bsl[br]);
        #pragma unroll
        for (int i=0;i<MFR;i++){
          mma16816(acc[i][j], ah[i], bh);
          mma16816(acc[i][j], ah[i], bl);
          mma16816(acc[i][j], al[i], bh);
        }
      }
    }
    __syncthreads();
  }
  #pragma unroll
  for (int i=0;i<MFR;i++)
    #pragma unroll
    for (int j=0;j<8;j++){
      int r0 = m0 + wm + i*16 + (lane>>2);
      int c0 = wn + j*8 + (lane&3)*2;
      float* Cp = C + ((size_t)b*NN_ + r0)*NO + c0;
      Cp[0] = acc[i][j][0]; Cp[1] = acc[i][j][1];
      Cp[(size_t)8*NO] = acc[i][j][2]; Cp[(size_t)8*NO+1] = acc[i][j][3];
    }
}

// r-gate: 4b x 4o register tile per thread, transposed Xg staging.
__global__ void __launch_bounds__(128) k_gate_r(const float* __restrict__ x,
                                                const float* __restrict__ st){
  int n = blockIdx.x;
  __shared__ float Xg[256*20];
  int t = threadIdx.x;
  for (int q=t; q<4096; q+=128){
    int b = q>>8, i = q&255;
    float v;
    if (i < 64)       v = x[((size_t)b*NN_+n)*64 + i];
    else if (i < 128) v = st[((size_t)b*NN_+n)*64 + (i-64)];
    else              v = g_xb[((size_t)b*NN_+n)*128 + (i-128)];
    Xg[i*20 + b] = v;
  }
  __syncthreads();
  int og = t>>2, bg = t&3;
  int o0 = og*4, b0 = bg*4;
  float acc[4][4] = {};
  const float* W = g_Wn_r + (size_t)n*256*128 + o0;
  #pragma unroll 2
  for (int i=0;i<256;i++){
    float4 xv = *(float4*)&Xg[i*20 + b0];
    float4 wv = *(const float4*)&W[(size_t)i*128];
    float xs[4] = {xv.x,xv.y,xv.z,xv.w};
    float ws[4] = {wv.x,wv.y,wv.z,wv.w};
    #pragma unroll
    for (int bi=0;bi<4;bi++)
      #pragma unroll
      for (int oi=0;oi<4;oi++)
        acc[bi][oi] += xs[bi]*ws[oi];
  }
  float4 bias = *(const float4*)&g_bias_r[n*128 + o0];
  float bs[4] = {bias.x,bias.y,bias.z,bias.w};
  #pragma unroll
  for (int bi=0;bi<4;bi++){
    int b = b0+bi;
    size_t idx = ((size_t)b*NN_+n)*64;
    #pragma unroll
    for (int oi=0;oi<4;oi++){
      int o = o0+oi;
      float g = 1.0f/(1.0f+__expf(-(acc[bi][oi]+bs[oi])));
      if (o < 64){
        float zsv = g * st[idx + o];
        g_zs[idx + o] = zsv;
        __nv_bfloat16 h, l; split_bf16(zsv, h, l);
        g_zh[idx + o] = h; g_zl[idx + o] = l;
      } else {
        g_rb[idx + (o-64)] = g;
      }
    }
  }
}

// u-gate + GRU output: 2b x 4o register tile per thread.
__global__ void __launch_bounds__(128) k_gate_u(const float* __restrict__ x,
                                                const float* __restrict__ st,
                                                float* __restrict__ out_h){
  int n = blockIdx.x;
  __shared__ float Xg[256*20];
  int t = threadIdx.x;
  for (int q=t; q<4096; q+=128){
    int b = q>>8, i = q&255;
    float v;
    if (i < 64)       v = x[((size_t)b*NN_+n)*64 + i];
    else if (i < 128) v = g_zs[((size_t)b*NN_+n)*64 + (i-64)];
    else if (i < 192) v = g_xb[((size_t)b*NN_+n)*128 + (i-128)];
    else              v = g_c2[((size_t)b*NN_+n)*64 + (i-192)];
    Xg[i*20 + b] = v;
  }
  __syncthreads();
  int og = t>>3, bg = t&7;
  int o0 = og*4, b0 = bg*2;
  float acc[2][4] = {};
  const float* W = g_Wn_u + (size_t)n*256*64 + o0;
  #pragma unroll 2
  for (int i=0;i<256;i++){
    float2 xv = *(float2*)&Xg[i*20 + b0];
    float4 wv = *(const float4*)&W[(size_t)i*64];
    float xs[2] = {xv.x,xv.y};
    float ws[4] = {wv.x,wv.y,wv.z,wv.w};
    #pragma unroll
    for (int bi=0;bi<2;bi++)
      #pragma unroll
      for (int oi=0;oi<4;oi++)
        acc[bi][oi] += xs[bi]*ws[oi];
  }
  float4 bias = *(const float4*)&g_bias_u[n*64 + o0];
  float bs[4] = {bias.x,bias.y,bias.z,bias.w};
  #pragma unroll
  for (int bi=0;bi<2;bi++){
    int b = b0+bi;
    size_t idx = ((size_t)b*NN_+n)*64;
    #pragma unroll
    for (int oi=0;oi<4;oi++){
      int o = o0+oi;
      float hc = tanhf(acc[bi][oi]+bs[oi]);
      float r = g_rb[idx + o];
      float sv = st[idx + o];
      out_h[idx + o] = r*sv + (1.0f-r)*hc;
    }
  }
}

// ---------------- launch ----------------
extern "C" void kernel_launch(void* const* d_in, const int* in_sizes, int n_in,
                              void* d_out, int out_size){
  const float* x    = (const float*)d_in[0];
  const float* st   = (const float*)d_in[1];
  const float* we   = (const float*)d_in[2];
  const float* T    = (const float*)d_in[3];
  const float* Wpr  = (const float*)d_in[4];
  const float* bpr  = (const float*)d_in[5];
  const float* Wpu  = (const float*)d_in[6];
  const float* bpu  = (const float*)d_in[7];
  const float* mp   = (const float*)d_in[8];
  const float* tp   = (const float*)d_in[9];
  const float* gmm  = (const float*)d_in[10];
  const float* bta  = (const float*)d_in[11];
  const int*   itp  = (const int*)d_in[12];
  float* out = (float*)d_out;
  float* out_mask = out + OFF_MASK;

  static __nv_bfloat16 *xh_p=nullptr, *xl_p=nullptr, *zh_p=nullptr, *zl_p=nullptr;
  static float *xb_p=nullptr, *c2_p=nullptr;
  if (!xh_p){
    cudaGetSymbolAddress((void**)&xh_p, g_xh);
    cudaGetSymbolAddress((void**)&xl_p, g_xl);
    cudaGetSymbolAddress((void**)&zh_p, g_zh);
    cudaGetSymbolAddress((void**)&zl_p, g_zl);
    cudaGetSymbolAddress((void**)&xb_p, g_xb);
    cudaGetSymbolAddress((void**)&c2_p, g_c2);
  }

  k_setup<<<64,256>>>(we, itp);
  k_bias<<<NN_,128>>>(bpr, bpu);
  k_em<<<NN_,256>>>(mp);
  k_supports<<<NN_,256>>>();
  k_prep<<<8192,256>>>(x, st);
  k_wgen<128,true><<<dim3(16,16),128>>>(Wpr);
  k_wgen<64,false><<<dim3(16,16),128>>>(Wpu);

  size_t smem_sup = (size_t)(2*WINDOW*NN_ + NN_)*sizeof(float);
  cudaFuncSetAttribute(k_supmask, cudaFuncAttributeMaxDynamicSharedMemorySize, (int)smem_sup);
  k_supmask<<<dim3(64,16),256,smem_sup>>>(T, tp, gmm, bta, out_mask);

  k_kept<<<8192,256>>>();
  k_loss<<<1,16>>>(out + OFF_LOSS);

  k_mma<128><<<dim3(8,16),256>>>(xh_p, xl_p, xb_p);
  k_gate_r<<<NN_,128>>>(x, st);
  k_mma<64><<<dim3(8,16),256>>>(zh_p, zl_p, c2_p);
  k_gate_u<<<NN_,128>>>(x, st, out);
}

// round 6
// speedup vs baseline: 1.8026x; 1.2993x over previous
#include <cuda_runtime.h>
#include <cuda_bf16.h>
#include <cstdint>
#include <math.h>

#define BB 16
#define NN_ 1024
#define EDIM 16
#define WINDOW 12
#define NNSQ (NN_*NN_)
#define BNN (BB*NNSQ)
#define HALF_BNN (BNN/2)
#define OFF_MASK (BB*NN_*64)
#define OFF_LOSS (OFF_MASK + BNN)
#define MASK_THR (-2.66352776f)   /* ln(1.4) - 3 */

// ---------------- scratch ----------------
__device__ float g_E[NN_*EDIM];
__device__ float g_Et[EDIM*NN_];
__device__ float g_EM[NNSQ];
__device__ float g_supports[NNSQ];
__device__ __nv_bfloat16 g_sh[(size_t)BNN];
__device__ __nv_bfloat16 g_sl[(size_t)BNN];
__device__ uint32_t g_bits[BNN/32];
__device__ __nv_bfloat16 g_xh[(size_t)BB*NN_*128];
__device__ __nv_bfloat16 g_xl[(size_t)BB*NN_*128];
__device__ __nv_bfloat16 g_zh[(size_t)BB*NN_*64];
__device__ __nv_bfloat16 g_zl[(size_t)BB*NN_*64];
__device__ float g_Wn_r[(size_t)NN_*256*128];
__device__ float g_Wn_u[(size_t)NN_*256*64];
__device__ float g_bias_r[NN_*128];
__device__ float g_bias_u[NN_*64];
__device__ float g_xb[(size_t)BB*NN_*128];
__device__ float g_zs[(size_t)BB*NN_*64];
__device__ float g_rb[(size_t)BB*NN_*64];
__device__ float g_c2[(size_t)BB*NN_*64];
__device__ unsigned int g_pos[BB];
__device__ unsigned int g_kept[BB];

// ---------------- helpers ----------------
__device__ __forceinline__ float warpSum(float v){
  #pragma unroll
  for (int o=16;o;o>>=1) v += __shfl_xor_sync(0xffffffffu, v, o);
  return v;
}
__device__ __forceinline__ float blockSum(float v, float* red){
  int lane = threadIdx.x & 31, w = threadIdx.x >> 5;
  int nw = blockDim.x >> 5;
  v = warpSum(v);
  __syncthreads();
  if (lane==0) red[w] = v;
  __syncthreads();
  float r = (threadIdx.x < (unsigned)nw) ? red[threadIdx.x] : 0.0f;
  if (w==0) r = warpSum(r);
  if (threadIdx.x==0) red[0] = r;
  __syncthreads();
  return red[0];
}
__device__ __forceinline__ uint32_t rotl32(uint32_t x, int r){
  return __funnelshift_l(x, x, r);
}
__device__ __forceinline__ void threefry2x32(uint32_t k0, uint32_t k1,
                                             uint32_t& x0, uint32_t& x1){
  uint32_t ks0 = k0, ks1 = k1, ks2 = k0 ^ k1 ^ 0x1BD11BDAu;
  x0 += ks0; x1 += ks1;
  const int R0[4] = {13,15,26,6};
  const int R1[4] = {17,29,16,24};
  uint32_t ks[3] = {ks0, ks1, ks2};
  #pragma unroll
  for (int i=0;i<5;i++){
    #pragma unroll
    for (int j=0;j<4;j++){
      int r = (i & 1) ? R1[j] : R0[j];
      x0 += x1; x1 = rotl32(x1, r); x1 ^= x0;
    }
    x0 += ks[(i+1)%3];
    x1 += ks[(i+2)%3] + (uint32_t)(i+1);
  }
}
__device__ __forceinline__ void split_bf16(float v, __nv_bfloat16& h, __nv_bfloat16& l){
  h = __float2bfloat16(v);
  l = __float2bfloat16(v - __bfloat162float(h));
}
__device__ __forceinline__ uint32_t pack_bf2(__nv_bfloat16 a, __nv_bfloat16 b){
  __nv_bfloat162 p(a, b);
  return *reinterpret_cast<uint32_t*>(&p);
}
__device__ __forceinline__ void ldsm4(uint32_t& r0,uint32_t& r1,uint32_t& r2,uint32_t& r3,
                                      const __nv_bfloat16* p){
  uint32_t a = (uint32_t)__cvta_generic_to_shared(p);
  asm volatile("ldmatrix.sync.aligned.m8n8.x4.shared.b16 {%0,%1,%2,%3},[%4];"
    : "=r"(r0),"=r"(r1),"=r"(r2),"=r"(r3) : "r"(a));
}
__device__ __forceinline__ void ldsm2t(uint32_t& r0,uint32_t& r1, const __nv_bfloat16* p){
  uint32_t a = (uint32_t)__cvta_generic_to_shared(p);
  asm volatile("ldmatrix.sync.aligned.m8n8.x2.trans.shared.b16 {%0,%1},[%2];"
    : "=r"(r0),"=r"(r1) : "r"(a));
}
__device__ __forceinline__ void mma16816(float* c, const uint32_t* a, const uint32_t* b){
  asm volatile("mma.sync.aligned.m16n8k16.row.col.f32.bf16.bf16.f32 "
    "{%0,%1,%2,%3},{%4,%5,%6,%7},{%8,%9},{%0,%1,%2,%3};"
    : "+f"(c[0]),"+f"(c[1]),"+f"(c[2]),"+f"(c[3])
    : "r"(a[0]),"r"(a[1]),"r"(a[2]),"r"(a[3]), "r"(b[0]),"r"(b[1]));
}
__device__ __forceinline__ float prob_from_pos(){
  unsigned int tot = 0;
  #pragma unroll
  for (int i=0;i<BB;i++) tot += g_pos[i];
  float active = (float)tot / (float)BNN;
  return fminf(0.05f/active + 1e-8f, 1.0f);
}

// ---------------- kernels ----------------

// E = we + positional row; transpose; zero counters.
__global__ void k_setup(const float* __restrict__ we, const int* __restrict__ itp){
  int tid = blockIdx.x*blockDim.x + threadIdx.x;
  float it = (float)itp[0];
  if (tid < NN_*EDIM){
    int d = tid & 15;
    int pair = d >> 1;
    float arg = (float)((double)(2*pair) * (-9.210340371976184/16.0));
    float div = expf(arg);
    float pe = (d & 1) ? cosf(it*div) : sinf(it*div);
    float e = we[tid] + pe;
    g_E[tid] = e;
    g_Et[d*NN_ + (tid>>4)] = e;
  }
  if (blockIdx.x==0 && threadIdx.x < 2*BB){
    if (threadIdx.x < BB) g_pos[threadIdx.x] = 0u;
    else                  g_kept[threadIdx.x-BB] = 0u;
  }
}

// Merged: [0,1024) em+bias per node, [1024,2048) supports per node, [2048,4096) prep.
__global__ void k_pre(const float* __restrict__ mp,
                      const float* __restrict__ bpr, const float* __restrict__ bpu,
                      const float* __restrict__ x, const float* __restrict__ st){
  int g = blockIdx.x;
  if (g < NN_){
    // em (vectorized) + bias
    int n = g;
    __shared__ float en[EDIM];
    if (threadIdx.x < EDIM) en[threadIdx.x] = g_E[n*EDIM+threadIdx.x];
    __syncthreads();
    int m0 = threadIdx.x*4;
    float4 a = make_float4(0.f,0.f,0.f,0.f);
    #pragma unroll
    for (int d=0; d<EDIM; d++){
      float4 mv = *(const float4*)&mp[d*NN_+m0];
      float e = en[d];
      a.x += e*mv.x; a.y += e*mv.y; a.z += e*mv.z; a.w += e*mv.w;
    }
    *(float4*)&g_EM[n*NN_+m0] = a;
    int o = threadIdx.x;
    if (o < 128){
      float br = 0.f;
      #pragma unroll
      for (int d=0; d<EDIM; d++) br += en[d]*bpr[d*128+o];
      g_bias_r[n*128+o] = br;
      if (o < 64){
        float bu = 0.f;
        #pragma unroll
        for (int d=0; d<EDIM; d++) bu += en[d]*bpu[d*64+o];
        g_bias_u[n*64+o] = bu;
      }
    }
  } else if (g < 2*NN_){
    // supports = softmax(relu(E E^T)) row n — 2-pass, no max-subtract (values bounded)
    int n = g - NN_;
    __shared__ float row[NN_];
    __shared__ float red[32];
    float en[EDIM];
    #pragma unroll
    for (int d=0; d<EDIM; d++) en[d] = g_E[n*EDIM+d];
    int m0 = threadIdx.x*4;
    float4 a = make_float4(0.f,0.f,0.f,0.f);
    #pragma unroll
    for (int d=0; d<EDIM; d++){
      float4 ev = *(const float4*)&g_Et[d*NN_+m0];
      float e = en[d];
      a.x += e*ev.x; a.y += e*ev.y; a.z += e*ev.z; a.w += e*ev.w;
    }
    a.x = __expf(fmaxf(a.x,0.f)); a.y = __expf(fmaxf(a.y,0.f));
    a.z = __expf(fmaxf(a.z,0.f)); a.w = __expf(fmaxf(a.w,0.f));
    *(float4*)&row[m0] = a;
    float s = blockSum(a.x+a.y+a.z+a.w, red);
    float inv = 1.0f/s;
    float4 r4 = *(float4*)&row[m0];
    r4.x *= inv; r4.y *= inv; r4.z *= inv; r4.w *= inv;
    *(float4*)&g_supports[n*NN_+m0] = r4;
  } else {
    // prep: cat(x,state) -> bf16 hi/lo
    int q = (g - 2*NN_)*256 + threadIdx.x;     // quad index
    int t4 = q*4;
    int j = t4 & 127; int bn = t4 >> 7;
    float4 v = (j < 64) ? *(const float4*)&x[(size_t)bn*64 + j]
                        : *(const float4*)&st[(size_t)bn*64 + (j-64)];
    __nv_bfloat16 h0,l0,h1,l1,h2,l2,h3,l3;
    split_bf16(v.x,h0,l0); split_bf16(v.y,h1,l1);
    split_bf16(v.z,h2,l2); split_bf16(v.w,h3,l3);
    uint2 hv = make_uint2(pack_bf2(h0,h1), pack_bf2(h2,h3));
    uint2 lv = make_uint2(pack_bf2(l0,l1), pack_bf2(l2,l3));
    *(uint2*)&g_xh[t4] = hv;
    *(uint2*)&g_xl[t4] = lv;
  }
}

// Wn[n,i2,o] = sum_d E[n,d] * Wp[d,i2,o] — r and u in one launch.
template<int OC>
__device__ __forceinline__ void wgen_body(const float* __restrict__ Wp, float* __restrict__ Wn,
                                          int lb){
  constexpr int NQ = OC/4;
  constexpr int NI = 128/NQ;
  int n0 = (lb>>4)*64;
  int i20 = (lb&15)*16;
  int t = threadIdx.x;
  int oq = t % NQ, ig = t / NQ;
  __shared__ float Esm[64][EDIM];
  for (int q=t; q<64*EDIM; q+=128)
    Esm[q>>4][q&15] = g_E[(n0 + (q>>4))*EDIM + (q&15)];
  __syncthreads();
  for (int ii=ig; ii<16; ii+=NI){
    int i2 = i20+ii;
    float4 w[EDIM];
    #pragma unroll
    for (int d=0; d<EDIM; d++)
      w[d] = *(const float4*)&Wp[((size_t)d*256 + i2)*OC + oq*4];
    #pragma unroll 4
    for (int nn=0; nn<64; nn++){
      float4 a = make_float4(0.f,0.f,0.f,0.f);
      #pragma unroll
      for (int d=0; d<EDIM; d++){
        float e = Esm[nn][d];
        a.x += e*w[d].x; a.y += e*w[d].y; a.z += e*w[d].z; a.w += e*w[d].w;
      }
      *(float4*)&Wn[((size_t)(n0+nn)*256 + i2)*OC + oq*4] = a;
    }
  }
}
__global__ void __launch_bounds__(128) k_wgen(const float* __restrict__ Wpr,
                                              const float* __restrict__ Wpu){
  int blk = blockIdx.x;
  if (blk < 256) wgen_body<128>(Wpr, g_Wn_r, blk);
  else           wgen_body<64>(Wpu, g_Wn_u, blk-256);
}

// Fused: time-gram softmax (2-pass, no max) + raw_mask + threshold + sup bf16 hi/lo + bits.
__global__ void k_supmask(const float* __restrict__ T, const float* __restrict__ TP,
                          const float* __restrict__ gamma, const float* __restrict__ beta,
                          float* __restrict__ out_mask){
  extern __shared__ float sm[];
  float* Tsm  = sm;
  float* TPsm = sm + WINDOW*NN_;
  float* row  = TPsm + WINDOW*NN_;
  __shared__ float red[32];
  int b = blockIdx.y;
  int n0 = blockIdx.x*16;
  int lane = threadIdx.x & 31;
  for (int t=threadIdx.x; t<WINDOW*NN_; t+=blockDim.x){
    Tsm[t]  = T[(size_t)b*WINDOW*NN_ + t];
    TPsm[t] = TP[t];
  }
  __syncthreads();
  const float bni = 1.0f/sqrtf(1.0f + 1e-5f);
  unsigned int cnt = 0;
  int m0 = threadIdx.x*4;
  for (int r16=0; r16<16; r16++){
    int n = n0 + r16;
    float tv[WINDOW];
    #pragma unroll
    for (int w=0; w<WINDOW; w++) tv[w] = Tsm[w*NN_+n];
    // pass A: gram + exp + sum
    float4 tg = make_float4(0.f,0.f,0.f,0.f);
    #pragma unroll
    for (int w=0; w<WINDOW; w++){
      float4 tw = *(float4*)&Tsm[w*NN_+m0];
      float t = tv[w];
      tg.x += t*tw.x; tg.y += t*tw.y; tg.z += t*tw.z; tg.w += t*tw.w;
    }
    tg.x = __expf(fmaxf(tg.x,0.f)); tg.y = __expf(fmaxf(tg.y,0.f));
    tg.z = __expf(fmaxf(tg.z,0.f)); tg.w = __expf(fmaxf(tg.w,0.f));
    *(float4*)&row[m0] = tg;
    float s = blockSum(tg.x+tg.y+tg.z+tg.w, red);
    float inv = 1.0f/s;
    // pass B: raw_mask + threshold + sup
    float gn = gamma[n], bt = beta[n];
    float4 e4 = *(float4*)&row[m0];
    float4 rm = *(const float4*)&g_EM[n*NN_+m0];
    #pragma unroll
    for (int w=0; w<WINDOW; w++){
      float4 tp = *(float4*)&TPsm[w*NN_+m0];
      float t = tv[w];
      rm.x += t*tp.x; rm.y += t*tp.y; rm.z += t*tp.z; rm.w += t*tp.w;
    }
    float sc = bni*gn;
    rm.x = rm.x*sc + bt; rm.y = rm.y*sc + bt;
    rm.z = rm.z*sc + bt; rm.w = rm.w*sc + bt;
    uint32_t nib = (rm.x > MASK_THR ? 1u:0u) | (rm.y > MASK_THR ? 2u:0u)
                 | (rm.z > MASK_THR ? 4u:0u) | (rm.w > MASK_THR ? 8u:0u);
    float4 mk = make_float4(nib&1u?1.f:0.f, nib&2u?1.f:0.f, nib&4u?1.f:0.f, nib&8u?1.f:0.f);
    size_t idx = (size_t)b*NNSQ + (size_t)n*NN_ + m0;
    *(float4*)&out_mask[idx] = mk;
    float4 sp = *(const float4*)&g_supports[n*NN_+m0];
    sp.x = (sp.x + e4.x*inv)*0.5f*mk.x;
    sp.y = (sp.y + e4.y*inv)*0.5f*mk.y;
    sp.z = (sp.z + e4.z*inv)*0.5f*mk.z;
    sp.w = (sp.w + e4.w*inv)*0.5f*mk.w;
    __nv_bfloat16 h0,l0,h1,l1,h2,l2,h3,l3;
    split_bf16(sp.x,h0,l0); split_bf16(sp.y,h1,l1);
    split_bf16(sp.z,h2,l2); split_bf16(sp.w,h3,l3);
    *(uint2*)&g_sh[idx] = make_uint2(pack_bf2(h0,h1), pack_bf2(h2,h3));
    *(uint2*)&g_sl[idx] = make_uint2(pack_bf2(l0,l1), pack_bf2(l2,l3));
    cnt += __popc(nib);
    // bits: 8 lanes -> one 32-bit word
    uint32_t v = nib << ((lane&7)*4);
    v |= __shfl_xor_sync(0xffffffffu, v, 1);
    v |= __shfl_xor_sync(0xffffffffu, v, 2);
    v |= __shfl_xor_sync(0xffffffffu, v, 4);
    if ((lane&7)==0) g_bits[idx>>5] = v;
    __syncthreads();
  }
  float fc = blockSum((float)cnt, red);
  if (threadIdx.x==0) atomicAdd(&g_pos[b], (unsigned int)(fc + 0.5f));
}

// mma body (block computes 128xNO tile of sup[b] @ X[b])
template<int NO>
__device__ __forceinline__ void mma_body(int m0, int b,
    const __nv_bfloat16* __restrict__ Bh, const __nv_bfloat16* __restrict__ Bl,
    float* __restrict__ C){
  constexpr int NWN = NO/64;
  constexpr int NWM = 8/NWN;
  constexpr int WM  = 128/NWM;
  constexpr int MFR = WM/16;
  constexpr int BST = NO+8;
  __shared__ __nv_bfloat16 Ash[128*40], Asl[128*40];
  __shared__ __nv_bfloat16 Bsh[32*BST], Bsl[32*BST];
  int w = threadIdx.x>>5, lane = threadIdx.x&31;
  int wm = (w / NWN)*WM;
  int wn = (w % NWN)*64;
  float acc[MFR][8][4];
  #pragma unroll
  for (int i=0;i<MFR;i++)
    #pragma unroll
    for (int j=0;j<8;j++)
      #pragma unroll
      for (int q=0;q<4;q++) acc[i][j][q] = 0.f;
  const __nv_bfloat16* Ahb = g_sh + (size_t)b*NNSQ;
  const __nv_bfloat16* Alb = g_sl + (size_t)b*NNSQ;
  const __nv_bfloat16* Bhb = Bh + (size_t)b*NN_*NO;
  const __nv_bfloat16* Blb = Bl + (size_t)b*NN_*NO;
  for (int k0=0;k0<NN_;k0+=32){
    #pragma unroll
    for (int i = threadIdx.x; i<512; i+=256){
      int r = i>>2, c = i&3;
      *(uint4*)&Ash[r*40 + c*8] = *(const uint4*)&Ahb[(size_t)(m0+r)*NN_ + k0 + c*8];
      *(uint4*)&Asl[r*40 + c*8] = *(const uint4*)&Alb[(size_t)(m0+r)*NN_ + k0 + c*8];
    }
    #pragma unroll
    for (int i = threadIdx.x; i<32*NO/8; i+=256){
      int r = i/(NO/8), c = i%(NO/8);
      *(uint4*)&Bsh[r*BST + c*8] = *(const uint4*)&Bhb[(size_t)(k0+r)*NO + c*8];
      *(uint4*)&Bsl[r*BST + c*8] = *(const uint4*)&Blb[(size_t)(k0+r)*NO + c*8];
    }
    __syncthreads();
    #pragma unroll
    for (int kk=0; kk<2; kk++){
      uint32_t ah[MFR][4], al[MFR][4];
      #pragma unroll
      for (int i=0;i<MFR;i++){
        int ar = (wm + i*16 + (lane&15))*40 + kk*16 + (lane>>4)*8;
        ldsm4(ah[i][0],ah[i][1],ah[i][2],ah[i][3], &Ash[ar]);
        ldsm4(al[i][0],al[i][1],al[i][2],al[i][3], &Asl[ar]);
      }
      #pragma unroll
      for (int j=0;j<8;j++){
        uint32_t bh[2], bl[2];
        int br = (kk*16 + (lane&15))*BST + wn + j*8;
        ldsm2t(bh[0],bh[1], &Bsh[br]);
        ldsm2t(bl[0],bl[1], &Bsl[br]);
        #pragma unroll
        for (int i=0;i<MFR;i++){
          mma16816(acc[i][j], ah[i], bh);
          mma16816(acc[i][j], ah[i], bl);
          mma16816(acc[i][j], al[i], bh);
        }
      }
    }
    __syncthreads();
  }
  #pragma unroll
  for (int i=0;i<MFR;i++)
    #pragma unroll
    for (int j=0;j<8;j++){
      int r0 = m0 + wm + i*16 + (lane>>2);
      int c0 = wn + j*8 + (lane&3)*2;
      float* Cp = C + ((size_t)b*NN_ + r0)*NO + c0;
      Cp[0] = acc[i][j][0]; Cp[1] = acc[i][j][1];
      Cp[(size_t)8*NO] = acc[i][j][2]; Cp[(size_t)8*NO+1] = acc[i][j][3];
    }
}

// Merged: blocks [0,128) mma<128> (xb = sup@cat(x,state)); blocks [128,8320) kept-count.
__global__ void k_mma_kept(const __nv_bfloat16* __restrict__ Bh,
                           const __nv_bfloat16* __restrict__ Bl,
                           float* __restrict__ C){
  if (blockIdx.x < 128){
    mma_body<128>((blockIdx.x & 7)*128, blockIdx.x >> 3, Bh, Bl, C);
    return;
  }
  __shared__ unsigned int cnt[BB];
  if (threadIdx.x < BB) cnt[threadIdx.x] = 0u;
  __syncthreads();
  float prob = prob_from_pos();
  int lane = threadIdx.x & 31;
  unsigned int base = (blockIdx.x-128)*1024u + threadIdx.x;
  #pragma unroll
  for (int k=0;k<4;k++){
    unsigned int t = base + (unsigned)k*256u;
    uint32_t x0 = t, x1 = t + (uint32_t)HALF_BNN;
    threefry2x32(0u, 42u, x0, x1);
    float u0 = __uint_as_float((x0>>9) | 0x3f800000u) - 1.0f;
    float u1 = __uint_as_float((x1>>9) | 0x3f800000u) - 1.0f;
    uint32_t w0 = g_bits[t>>5];
    uint32_t w1 = g_bits[(t + HALF_BNN)>>5];
    int b0 = (int)(t >> 20);
    bool keep0 = ((w0>>lane)&1u) && !(u0 < prob);
    bool keep1 = ((w1>>lane)&1u) && !(u1 < prob);
    unsigned bal0 = __ballot_sync(0xffffffffu, keep0);
    unsigned bal1 = __ballot_sync(0xffffffffu, keep1);
    if (lane==0){
      if (bal0) atomicAdd(&cnt[b0],   __popc(bal0));
      if (bal1) atomicAdd(&cnt[b0+8], __popc(bal1));
    }
  }
  __syncthreads();
  if (threadIdx.x < BB && cnt[threadIdx.x]) atomicAdd(&g_kept[threadIdx.x], cnt[threadIdx.x]);
}

__global__ void k_mma64(const __nv_bfloat16* __restrict__ Bh,
                        const __nv_bfloat16* __restrict__ Bl,
                        float* __restrict__ C){
  mma_body<64>(blockIdx.x*128, blockIdx.y, Bh, Bl, C);
}

// r-gate: 4b x 4o register tile per thread.
__global__ void __launch_bounds__(128) k_gate_r(const float* __restrict__ x,
                                                const float* __restrict__ st){
  int n = blockIdx.x;
  __shared__ float Xg[256*20];
  int t = threadIdx.x;
  for (int q=t; q<4096; q+=128){
    int b = q>>8, i = q&255;
    float v;
    if (i < 64)       v = x[((size_t)b*NN_+n)*64 + i];
    else if (i < 128) v = st[((size_t)b*NN_+n)*64 + (i-64)];
    else              v = g_xb[((size_t)b*NN_+n)*128 + (i-128)];
    Xg[i*20 + b] = v;
  }
  __syncthreads();
  int og = t>>2, bg = t&3;
  int o0 = og*4, b0 = bg*4;
  float acc[4][4] = {};
  const float* W = g_Wn_r + (size_t)n*256*128 + o0;
  #pragma unroll 2
  for (int i=0;i<256;i++){
    float4 xv = *(float4*)&Xg[i*20 + b0];
    float4 wv = *(const float4*)&W[(size_t)i*128];
    float xs[4] = {xv.x,xv.y,xv.z,xv.w};
    float ws[4] = {wv.x,wv.y,wv.z,wv.w};
    #pragma unroll
    for (int bi=0;bi<4;bi++)
      #pragma unroll
      for (int oi=0;oi<4;oi++)
        acc[bi][oi] += xs[bi]*ws[oi];
  }
  float4 bias = *(const float4*)&g_bias_r[n*128 + o0];
  float bs[4] = {bias.x,bias.y,bias.z,bias.w};
  #pragma unroll
  for (int bi=0;bi<4;bi++){
    int b = b0+bi;
    size_t idx = ((size_t)b*NN_+n)*64;
    #pragma unroll
    for (int oi=0;oi<4;oi++){
      int o = o0+oi;
      float g = 1.0f/(1.0f+__expf(-(acc[bi][oi]+bs[oi])));
      if (o < 64){
        float zsv = g * st[idx + o];
        g_zs[idx + o] = zsv;
        __nv_bfloat16 h, l; split_bf16(zsv, h, l);
        g_zh[idx + o] = h; g_zl[idx + o] = l;
      } else {
        g_rb[idx + (o-64)] = g;
      }
    }
  }
}

// u-gate + GRU output; block 1024 computes mask_loss.
__global__ void __launch_bounds__(128) k_gate_u(const float* __restrict__ x,
                                                const float* __restrict__ st,
                                                float* __restrict__ out_h,
                                                float* __restrict__ out_loss){
  if (blockIdx.x == NN_){
    if (threadIdx.x < BB){
      unsigned int tot = 0;
      #pragma unroll
      for (int i=0;i<BB;i++) tot += g_pos[i];
      float active = (float)tot / (float)BNN;
      float addend = fmaxf(0.05f/active - 1.0f, 0.0f);
      int b = threadIdx.x;
      out_loss[b] = (float)g_kept[b] / ((float)g_pos[b] + 1e-8f) + addend;
    }
    return;
  }
  int n = blockIdx.x;
  __shared__ float Xg[256*20];
  int t = threadIdx.x;
  for (int q=t; q<4096; q+=128){
    int b = q>>8, i = q&255;
    float v;
    if (i < 64)       v = x[((size_t)b*NN_+n)*64 + i];
    else if (i < 128) v = g_zs[((size_t)b*NN_+n)*64 + (i-64)];
    else if (i < 192) v = g_xb[((size_t)b*NN_+n)*128 + (i-128)];
    else              v = g_c2[((size_t)b*NN_+n)*64 + (i-192)];
    Xg[i*20 + b] = v;
  }
  __syncthreads();
  int og = t>>3, bg = t&7;
  int o0 = og*4, b0 = bg*2;
  float acc[2][4] = {};
  const float* W = g_Wn_u + (size_t)n*256*64 + o0;
  #pragma unroll 2
  for (int i=0;i<256;i++){
    float2 xv = *(float2*)&Xg[i*20 + b0];
    float4 wv = *(const float4*)&W[(size_t)i*64];
    float xs[2] = {xv.x,xv.y};
    float ws[4] = {wv.x,wv.y,wv.z,wv.w};
    #pragma unroll
    for (int bi=0;bi<2;bi++)
      #pragma unroll
      for (int oi=0;oi<4;oi++)
        acc[bi][oi] += xs[bi]*ws[oi];
  }
  float4 bias = *(const float4*)&g_bias_u[n*64 + o0];
  float bs[4] = {bias.x,bias.y,bias.z,bias.w};
  #pragma unroll
  for (int bi=0;bi<2;bi++){
    int b = b0+bi;
    size_t idx = ((size_t)b*NN_+n)*64;
    #pragma unroll
    for (int oi=0;oi<4;oi++){
      int o = o0+oi;
      float hc = tanhf(acc[bi][oi]+bs[oi]);
      float r = g_rb[idx + o];
      float sv = st[idx + o];
      out_h[idx + o] = r*sv + (1.0f-r)*hc;
    }
  }
}

// ---------------- launch ----------------
extern "C" void kernel_launch(void* const* d_in, const int* in_sizes, int n_in,
                              void* d_out, int out_size){
  const float* x    = (const float*)d_in[0];
  const float* st   = (const float*)d_in[1];
  const float* we   = (const float*)d_in[2];
  const float* T    = (const float*)d_in[3];
  const float* Wpr  = (const float*)d_in[4];
  const float* bpr  = (const float*)d_in[5];
  const float* Wpu  = (const float*)d_in[6];
  const float* bpu  = (const float*)d_in[7];
  const float* mp   = (const float*)d_in[8];
  const float* tp   = (const float*)d_in[9];
  const float* gmm  = (const float*)d_in[10];
  const float* bta  = (const float*)d_in[11];
  const int*   itp  = (const int*)d_in[12];
  float* out = (float*)d_out;
  float* out_mask = out + OFF_MASK;

  static __nv_bfloat16 *xh_p=nullptr, *xl_p=nullptr, *zh_p=nullptr, *zl_p=nullptr;
  static float *xb_p=nullptr, *c2_p=nullptr;
  if (!xh_p){
    cudaGetSymbolAddress((void**)&xh_p, g_xh);
    cudaGetSymbolAddress((void**)&xl_p, g_xl);
    cudaGetSymbolAddress((void**)&zh_p, g_zh);
    cudaGetSymbolAddress((void**)&zl_p, g_zl);
    cudaGetSymbolAddress((void**)&xb_p, g_xb);
    cudaGetSymbolAddress((void**)&c2_p, g_c2);
    size_t smem_sup = (size_t)(2*WINDOW*NN_ + NN_)*sizeof(float);
    cudaFuncSetAttribute(k_supmask, cudaFuncAttributeMaxDynamicSharedMemorySize, (int)smem_sup);
  }
  size_t smem_sup = (size_t)(2*WINDOW*NN_ + NN_)*sizeof(float);

  k_setup<<<64,256>>>(we, itp);                       // 1
  k_pre<<<4096,256>>>(mp, bpr, bpu, x, st);           // 2: em+bias | supports | prep
  k_wgen<<<512,128>>>(Wpr, Wpu);                      // 3
  k_supmask<<<dim3(64,16),256,smem_sup>>>(T, tp, gmm, bta, out_mask);  // 4 (profiled slot)
  k_mma_kept<<<8320,256>>>(xh_p, xl_p, xb_p);         // 5: mma<128> + kept
  k_gate_r<<<NN_,128>>>(x, st);                       // 6
  k_mma64<<<dim3(8,16),256>>>(zh_p, zl_p, c2_p);      // 7
  k_gate_u<<<NN_+1,128>>>(x, st, out, out + OFF_LOSS);// 8 (+loss)
}

// round 7
// speedup vs baseline: 2.0422x; 1.1329x over previous
#include <cuda_runtime.h>
#include <cuda_bf16.h>
#include <cstdint>
#include <math.h>

#define BB 16
#define NN_ 1024
#define EDIM 16
#define WINDOW 12
#define NNSQ (NN_*NN_)
#define BNN (BB*NNSQ)
#define HALF_BNN (BNN/2)
#define OFF_MASK (BB*NN_*64)
#define OFF_LOSS (OFF_MASK + BNN)
#define MASK_THR (-2.66352776f)   /* ln(1.4) - 3 */

// ---------------- scratch ----------------
__device__ float g_E[NN_*EDIM];
__device__ float g_Et[EDIM*NN_];
__device__ float g_EM[NNSQ];
__device__ float g_supports[NNSQ];
__device__ __nv_bfloat16 g_sh[(size_t)BNN];
__device__ __nv_bfloat16 g_sl[(size_t)BNN];
__device__ uint32_t g_bits[BNN/32];
__device__ __nv_bfloat16 g_xh[(size_t)BB*NN_*128];
__device__ __nv_bfloat16 g_xl[(size_t)BB*NN_*128];
__device__ __nv_bfloat16 g_zh[(size_t)BB*NN_*64];
__device__ __nv_bfloat16 g_zl[(size_t)BB*NN_*64];
__device__ float g_Wn_r[(size_t)NN_*256*128];
__device__ float g_Wn_u[(size_t)NN_*256*64];
__device__ float g_bias_r[NN_*128];
__device__ float g_bias_u[NN_*64];
__device__ float g_xb[(size_t)BB*NN_*128];
__device__ float g_zs[(size_t)BB*NN_*64];
__device__ float g_rb[(size_t)BB*NN_*64];
__device__ float g_c2[(size_t)BB*NN_*64];
__device__ unsigned int g_pos[BB];
__device__ unsigned int g_kept[BB];

// ---------------- helpers ----------------
__device__ __forceinline__ float warpSum(float v){
  #pragma unroll
  for (int o=16;o;o>>=1) v += __shfl_xor_sync(0xffffffffu, v, o);
  return v;
}
__device__ __forceinline__ float blockSum(float v, float* red){
  int lane = threadIdx.x & 31, w = threadIdx.x >> 5;
  int nw = blockDim.x >> 5;
  v = warpSum(v);
  __syncthreads();
  if (lane==0) red[w] = v;
  __syncthreads();
  float r = (threadIdx.x < (unsigned)nw) ? red[threadIdx.x] : 0.0f;
  if (w==0) r = warpSum(r);
  if (threadIdx.x==0) red[0] = r;
  __syncthreads();
  return red[0];
}
__device__ __forceinline__ uint32_t rotl32(uint32_t x, int r){
  return __funnelshift_l(x, x, r);
}
__device__ __forceinline__ void threefry2x32(uint32_t k0, uint32_t k1,
                                             uint32_t& x0, uint32_t& x1){
  uint32_t ks0 = k0, ks1 = k1, ks2 = k0 ^ k1 ^ 0x1BD11BDAu;
  x0 += ks0; x1 += ks1;
  const int R0[4] = {13,15,26,6};
  const int R1[4] = {17,29,16,24};
  uint32_t ks[3] = {ks0, ks1, ks2};
  #pragma unroll
  for (int i=0;i<5;i++){
    #pragma unroll
    for (int j=0;j<4;j++){
      int r = (i & 1) ? R1[j] : R0[j];
      x0 += x1; x1 = rotl32(x1, r); x1 ^= x0;
    }
    x0 += ks[(i+1)%3];
    x1 += ks[(i+2)%3] + (uint32_t)(i+1);
  }
}
__device__ __forceinline__ void split_bf16(float v, __nv_bfloat16& h, __nv_bfloat16& l){
  h = __float2bfloat16(v);
  l = __float2bfloat16(v - __bfloat162float(h));
}
__device__ __forceinline__ uint32_t pack_bf2(__nv_bfloat16 a, __nv_bfloat16 b){
  __nv_bfloat162 p(a, b);
  return *reinterpret_cast<uint32_t*>(&p);
}
__device__ __forceinline__ void ldsm4(uint32_t& r0,uint32_t& r1,uint32_t& r2,uint32_t& r3,
                                      const __nv_bfloat16* p){
  uint32_t a = (uint32_t)__cvta_generic_to_shared(p);
  asm volatile("ldmatrix.sync.aligned.m8n8.x4.shared.b16 {%0,%1,%2,%3},[%4];"
    : "=r"(r0),"=r"(r1),"=r"(r2),"=r"(r3) : "r"(a));
}
__device__ __forceinline__ void ldsm2t(uint32_t& r0,uint32_t& r1, const __nv_bfloat16* p){
  uint32_t a = (uint32_t)__cvta_generic_to_shared(p);
  asm volatile("ldmatrix.sync.aligned.m8n8.x2.trans.shared.b16 {%0,%1},[%2];"
    : "=r"(r0),"=r"(r1) : "r"(a));
}
__device__ __forceinline__ void mma16816(float* c, const uint32_t* a, const uint32_t* b){
  asm volatile("mma.sync.aligned.m16n8k16.row.col.f32.bf16.bf16.f32 "
    "{%0,%1,%2,%3},{%4,%5,%6,%7},{%8,%9},{%0,%1,%2,%3};"
    : "+f"(c[0]),"+f"(c[1]),"+f"(c[2]),"+f"(c[3])
    : "r"(a[0]),"r"(a[1]),"r"(a[2]),"r"(a[3]), "r"(b[0]),"r"(b[1]));
}
__device__ __forceinline__ float prob_from_pos(){
  unsigned int tot = 0;
  #pragma unroll
  for (int i=0;i<BB;i++) tot += g_pos[i];
  float active = (float)tot / (float)BNN;
  return fminf(0.05f/active + 1e-8f, 1.0f);
}

// ---------------- kernels ----------------

__global__ void k_setup(const float* __restrict__ we, const int* __restrict__ itp){
  int tid = blockIdx.x*blockDim.x + threadIdx.x;
  float it = (float)itp[0];
  if (tid < NN_*EDIM){
    int d = tid & 15;
    int pair = d >> 1;
    float arg = (float)((double)(2*pair) * (-9.210340371976184/16.0));
    float div = expf(arg);
    float pe = (d & 1) ? cosf(it*div) : sinf(it*div);
    float e = we[tid] + pe;
    g_E[tid] = e;
    g_Et[d*NN_ + (tid>>4)] = e;
  }
  if (blockIdx.x==0 && threadIdx.x < 2*BB){
    if (threadIdx.x < BB) g_pos[threadIdx.x] = 0u;
    else                  g_kept[threadIdx.x-BB] = 0u;
  }
}

// Merged: [0,1024) em+bias, [1024,2048) supports, [2048,4096) prep.
__global__ void k_pre(const float* __restrict__ mp,
                      const float* __restrict__ bpr, const float* __restrict__ bpu,
                      const float* __restrict__ x, const float* __restrict__ st){
  int g = blockIdx.x;
  if (g < NN_){
    int n = g;
    __shared__ float en[EDIM];
    if (threadIdx.x < EDIM) en[threadIdx.x] = g_E[n*EDIM+threadIdx.x];
    __syncthreads();
    int m0 = threadIdx.x*4;
    float4 a = make_float4(0.f,0.f,0.f,0.f);
    #pragma unroll
    for (int d=0; d<EDIM; d++){
      float4 mv = *(const float4*)&mp[d*NN_+m0];
      float e = en[d];
      a.x += e*mv.x; a.y += e*mv.y; a.z += e*mv.z; a.w += e*mv.w;
    }
    *(float4*)&g_EM[n*NN_+m0] = a;
    int o = threadIdx.x;
    if (o < 128){
      float br = 0.f;
      #pragma unroll
      for (int d=0; d<EDIM; d++) br += en[d]*bpr[d*128+o];
      g_bias_r[n*128+o] = br;
      if (o < 64){
        float bu = 0.f;
        #pragma unroll
        for (int d=0; d<EDIM; d++) bu += en[d]*bpu[d*64+o];
        g_bias_u[n*64+o] = bu;
      }
    }
  } else if (g < 2*NN_){
    int n = g - NN_;
    __shared__ float row[NN_];
    __shared__ float red[32];
    float en[EDIM];
    #pragma unroll
    for (int d=0; d<EDIM; d++) en[d] = g_E[n*EDIM+d];
    int m0 = threadIdx.x*4;
    float4 a = make_float4(0.f,0.f,0.f,0.f);
    #pragma unroll
    for (int d=0; d<EDIM; d++){
      float4 ev = *(const float4*)&g_Et[d*NN_+m0];
      float e = en[d];
      a.x += e*ev.x; a.y += e*ev.y; a.z += e*ev.z; a.w += e*ev.w;
    }
    a.x = __expf(fmaxf(a.x,0.f)); a.y = __expf(fmaxf(a.y,0.f));
    a.z = __expf(fmaxf(a.z,0.f)); a.w = __expf(fmaxf(a.w,0.f));
    *(float4*)&row[m0] = a;
    float s = blockSum(a.x+a.y+a.z+a.w, red);
    float inv = 1.0f/s;
    float4 r4 = *(float4*)&row[m0];
    r4.x *= inv; r4.y *= inv; r4.z *= inv; r4.w *= inv;
    *(float4*)&g_supports[n*NN_+m0] = r4;
  } else {
    int q = (g - 2*NN_)*256 + threadIdx.x;
    int t4 = q*4;
    int j = t4 & 127; int bn = t4 >> 7;
    float4 v = (j < 64) ? *(const float4*)&x[(size_t)bn*64 + j]
                        : *(const float4*)&st[(size_t)bn*64 + (j-64)];
    __nv_bfloat16 h0,l0,h1,l1,h2,l2,h3,l3;
    split_bf16(v.x,h0,l0); split_bf16(v.y,h1,l1);
    split_bf16(v.z,h2,l2); split_bf16(v.w,h3,l3);
    *(uint2*)&g_xh[t4] = make_uint2(pack_bf2(h0,h1), pack_bf2(h2,h3));
    *(uint2*)&g_xl[t4] = make_uint2(pack_bf2(l0,l1), pack_bf2(l2,l3));
  }
}

// Wn[n,i2,o] = sum_d E[n,d] * Wp[d,i2,o]  (256 threads)
template<int OC>
__device__ __forceinline__ void wgen_body(const float* __restrict__ Wp, float* __restrict__ Wn,
                                          int lb, float* Esm){
  constexpr int NQ = OC/4;          // 32 or 16
  constexpr int NI = 256/NQ;        // 8 or 16
  int n0 = (lb>>4)*64;
  int i20 = (lb&15)*16;
  int t = threadIdx.x;
  int oq = t % NQ, ig = t / NQ;
  for (int q=t; q<64*EDIM; q+=256)
    Esm[q] = g_E[(n0 + (q>>4))*EDIM + (q&15)];
  __syncthreads();
  for (int ii=ig; ii<16; ii+=NI){
    int i2 = i20+ii;
    float4 w[EDIM];
    #pragma unroll
    for (int d=0; d<EDIM; d++)
      w[d] = *(const float4*)&Wp[((size_t)d*256 + i2)*OC + oq*4];
    #pragma unroll 4
    for (int nn=0; nn<64; nn++){
      float4 a = make_float4(0.f,0.f,0.f,0.f);
      #pragma unroll
      for (int d=0; d<EDIM; d++){
        float e = Esm[nn*EDIM + d];
        a.x += e*w[d].x; a.y += e*w[d].y; a.z += e*w[d].z; a.w += e*w[d].w;
      }
      *(float4*)&Wn[((size_t)(n0+nn)*256 + i2)*OC + oq*4] = a;
    }
  }
}

// Combined launch: every 5th block does wgen (512 total), rest do supmask (2048).
// Supmask: 8 rows/block, register-blocked (tg[8][4], rm[8][4]); Tsm/TPsm read once per w.
__global__ void __launch_bounds__(256) k_sup_wgen(
    const float* __restrict__ T, const float* __restrict__ TP,
    const float* __restrict__ gamma, const float* __restrict__ beta,
    float* __restrict__ out_mask,
    const float* __restrict__ Wpr, const float* __restrict__ Wpu){
  __shared__ float Esm[64*EDIM];          // wgen E cache (also scratch)
  __shared__ float red[8][8];
  __shared__ float inv8[8];
  int bid = blockIdx.x;
  if (bid % 5 == 0){
    int lb = bid/5;
    if (lb < 256) wgen_body<128>(Wpr, g_Wn_r, lb, Esm);
    else          wgen_body<64>(Wpu, g_Wn_u, lb-256, Esm);
    return;
  }
  int id = bid - bid/5 - 1;               // [0, 2048)
  int b = id >> 7;
  int n0 = (id & 127)*8;
  extern __shared__ float sm[];
  float* Tsm  = sm;                       // 12*1024
  float* TPsm = sm + WINDOW*NN_;          // 12*1024
  int tid = threadIdx.x, lane = tid & 31, wrp = tid >> 5;
  for (int t=tid; t<WINDOW*NN_; t+=256){
    Tsm[t]  = T[(size_t)b*WINDOW*NN_ + t];
    TPsm[t] = TP[t];
  }
  __syncthreads();
  int m0 = tid*4;
  // Phase A: time-gram for 8 rows, register accumulators
  float tg[8][4];
  #pragma unroll
  for (int r=0;r<8;r++){ tg[r][0]=0.f; tg[r][1]=0.f; tg[r][2]=0.f; tg[r][3]=0.f; }
  #pragma unroll
  for (int w=0; w<WINDOW; w++){
    float4 tw = *(float4*)&Tsm[w*NN_+m0];
    #pragma unroll
    for (int r=0;r<8;r++){
      float tvs = Tsm[w*NN_ + n0 + r];
      tg[r][0] += tvs*tw.x; tg[r][1] += tvs*tw.y;
      tg[r][2] += tvs*tw.z; tg[r][3] += tvs*tw.w;
    }
  }
  float psum[8];
  #pragma unroll
  for (int r=0;r<8;r++){
    tg[r][0] = __expf(fmaxf(tg[r][0],0.f));
    tg[r][1] = __expf(fmaxf(tg[r][1],0.f));
    tg[r][2] = __expf(fmaxf(tg[r][2],0.f));
    tg[r][3] = __expf(fmaxf(tg[r][3],0.f));
    psum[r] = (tg[r][0]+tg[r][1])+(tg[r][2]+tg[r][3]);
  }
  #pragma unroll
  for (int r=0;r<8;r++) psum[r] = warpSum(psum[r]);
  if (lane==0){
    #pragma unroll
    for (int r=0;r<8;r++) red[r][wrp] = psum[r];
  }
  __syncthreads();
  if (tid < 8){
    float s = 0.f;
    #pragma unroll
    for (int k=0;k<8;k++) s += red[tid][k];
    inv8[tid] = 1.0f/s;
  }
  __syncthreads();
  // Phase B: raw mask for 8 rows
  float rm[8][4];
  #pragma unroll
  for (int r=0;r<8;r++){
    float4 t = *(const float4*)&g_EM[(size_t)(n0+r)*NN_ + m0];
    rm[r][0]=t.x; rm[r][1]=t.y; rm[r][2]=t.z; rm[r][3]=t.w;
  }
  #pragma unroll
  for (int w=0; w<WINDOW; w++){
    float4 tp = *(float4*)&TPsm[w*NN_+m0];
    #pragma unroll
    for (int r=0;r<8;r++){
      float tvs = Tsm[w*NN_ + n0 + r];
      rm[r][0] += tvs*tp.x; rm[r][1] += tvs*tp.y;
      rm[r][2] += tvs*tp.z; rm[r][3] += tvs*tp.w;
    }
  }
  // Final: threshold + mask + sup stores + bits
  const float bni = 1.0f/sqrtf(1.0f + 1e-5f);
  unsigned int cnt = 0;
  #pragma unroll
  for (int r=0;r<8;r++){
    int n = n0 + r;
    float sc = bni*gamma[n], bt = beta[n];
    float v0 = rm[r][0]*sc + bt, v1 = rm[r][1]*sc + bt;
    float v2 = rm[r][2]*sc + bt, v3 = rm[r][3]*sc + bt;
    uint32_t nib = (v0 > MASK_THR ? 1u:0u) | (v1 > MASK_THR ? 2u:0u)
                 | (v2 > MASK_THR ? 4u:0u) | (v3 > MASK_THR ? 8u:0u);
    float4 mk = make_float4(nib&1u?1.f:0.f, nib&2u?1.f:0.f, nib&4u?1.f:0.f, nib&8u?1.f:0.f);
    size_t idx = (size_t)b*NNSQ + (size_t)n*NN_ + m0;
    *(float4*)&out_mask[idx] = mk;
    float inv = inv8[r];
    float4 sp = *(const float4*)&g_supports[n*NN_+m0];
    sp.x = (sp.x + tg[r][0]*inv)*0.5f*mk.x;
    sp.y = (sp.y + tg[r][1]*inv)*0.5f*mk.y;
    sp.z = (sp.z + tg[r][2]*inv)*0.5f*mk.z;
    sp.w = (sp.w + tg[r][3]*inv)*0.5f*mk.w;
    __nv_bfloat16 h0,l0,h1,l1,h2,l2,h3,l3;
    split_bf16(sp.x,h0,l0); split_bf16(sp.y,h1,l1);
    split_bf16(sp.z,h2,l2); split_bf16(sp.w,h3,l3);
    *(uint2*)&g_sh[idx] = make_uint2(pack_bf2(h0,h1), pack_bf2(h2,h3));
    *(uint2*)&g_sl[idx] = make_uint2(pack_bf2(l0,l1), pack_bf2(l2,l3));
    cnt += __popc(nib);
    uint32_t v = nib << ((lane&7)*4);
    v |= __shfl_xor_sync(0xffffffffu, v, 1);
    v |= __shfl_xor_sync(0xffffffffu, v, 2);
    v |= __shfl_xor_sync(0xffffffffu, v, 4);
    if ((lane&7)==0) g_bits[idx>>5] = v;
  }
  float fc = blockSum((float)cnt, (float*)red);
  if (tid==0) atomicAdd(&g_pos[b], (unsigned int)(fc + 0.5f));
}

// mma body (block computes 128xNO tile of sup[b] @ X[b])
template<int NO>
__device__ __forceinline__ void mma_body(int m0, int b,
    const __nv_bfloat16* __restrict__ Bh, const __nv_bfloat16* __restrict__ Bl,
    float* __restrict__ C){
  constexpr int NWN = NO/64;
  constexpr int NWM = 8/NWN;
  constexpr int WM  = 128/NWM;
  constexpr int MFR = WM/16;
  constexpr int BST = NO+8;
  __shared__ __nv_bfloat16 Ash[128*40], Asl[128*40];
  __shared__ __nv_bfloat16 Bsh[32*BST], Bsl[32*BST];
  int w = threadIdx.x>>5, lane = threadIdx.x&31;
  int wm = (w / NWN)*WM;
  int wn = (w % NWN)*64;
  float acc[MFR][8][4];
  #pragma unroll
  for (int i=0;i<MFR;i++)
    #pragma unroll
    for (int j=0;j<8;j++)
      #pragma unroll
      for (int q=0;q<4;q++) acc[i][j][q] = 0.f;
  const __nv_bfloat16* Ahb = g_sh + (size_t)b*NNSQ;
  const __nv_bfloat16* Alb = g_sl + (size_t)b*NNSQ;
  const __nv_bfloat16* Bhb = Bh + (size_t)b*NN_*NO;
  const __nv_bfloat16* Blb = Bl + (size_t)b*NN_*NO;
  for (int k0=0;k0<NN_;k0+=32){
    #pragma unroll
    for (int i = threadIdx.x; i<512; i+=256){
      int r = i>>2, c = i&3;
      *(uint4*)&Ash[r*40 + c*8] = *(const uint4*)&Ahb[(size_t)(m0+r)*NN_ + k0 + c*8];
      *(uint4*)&Asl[r*40 + c*8] = *(const uint4*)&Alb[(size_t)(m0+r)*NN_ + k0 + c*8];
    }
    #pragma unroll
    for (int i = threadIdx.x; i<32*NO/8; i+=256){
      int r = i/(NO/8), c = i%(NO/8);
      *(uint4*)&Bsh[r*BST + c*8] = *(const uint4*)&Bhb[(size_t)(k0+r)*NO + c*8];
      *(uint4*)&Bsl[r*BST + c*8] = *(const uint4*)&Blb[(size_t)(k0+r)*NO + c*8];
    }
    __syncthreads();
    #pragma unroll
    for (int kk=0; kk<2; kk++){
      uint32_t ah[MFR][4], al[MFR][4];
      #pragma unroll
      for (int i=0;i<MFR;i++){
        int ar = (wm + i*16 + (lane&15))*40 + kk*16 + (lane>>4)*8;
        ldsm4(ah[i][0],ah[i][1],ah[i][2],ah[i][3], &Ash[ar]);
        ldsm4(al[i][0],al[i][1],al[i][2],al[i][3], &Asl[ar]);
      }
      #pragma unroll
      for (int j=0;j<8;j++){
        uint32_t bh[2], bl[2];
        int br = (kk*16 + (lane&15))*BST + wn + j*8;
        ldsm2t(bh[0],bh[1], &Bsh[br]);
        ldsm2t(bl[0],bl[1], &Bsl[br]);
        #pragma unroll
        for (int i=0;i<MFR;i++){
          mma16816(acc[i][j], ah[i], bh);
          mma16816(acc[i][j], ah[i], bl);
          mma16816(acc[i][j], al[i], bh);
        }
      }
    }
    __syncthreads();
  }
  #pragma unroll
  for (int i=0;i<MFR;i++)
    #pragma unroll
    for (int j=0;j<8;j++){
      int r0 = m0 + wm + i*16 + (lane>>2);
      int c0 = wn + j*8 + (lane&3)*2;
      float* Cp = C + ((size_t)b*NN_ + r0)*NO + c0;
      Cp[0] = acc[i][j][0]; Cp[1] = acc[i][j][1];
      Cp[(size_t)8*NO] = acc[i][j][2]; Cp[(size_t)8*NO+1] = acc[i][j][3];
    }
}

// Merged: blocks [0,128) mma<128>; blocks [128,8320) kept-count.
__global__ void k_mma_kept(const __nv_bfloat16* __restrict__ Bh,
                           const __nv_bfloat16* __restrict__ Bl,
                           float* __restrict__ C){
  if (blockIdx.x < 128){
    mma_body<128>((blockIdx.x & 7)*128, blockIdx.x >> 3, Bh, Bl, C);
    return;
  }
  __shared__ unsigned int cnt[BB];
  if (threadIdx.x < BB) cnt[threadIdx.x] = 0u;
  __syncthreads();
  float prob = prob_from_pos();
  int lane = threadIdx.x & 31;
  unsigned int base = (blockIdx.x-128)*1024u + threadIdx.x;
  #pragma unroll
  for (int k=0;k<4;k++){
    unsigned int t = base + (unsigned)k*256u;
    uint32_t x0 = t, x1 = t + (uint32_t)HALF_BNN;
    threefry2x32(0u, 42u, x0, x1);
    float u0 = __uint_as_float((x0>>9) | 0x3f800000u) - 1.0f;
    float u1 = __uint_as_float((x1>>9) | 0x3f800000u) - 1.0f;
    uint32_t w0 = g_bits[t>>5];
    uint32_t w1 = g_bits[(t + HALF_BNN)>>5];
    int b0 = (int)(t >> 20);
    bool keep0 = ((w0>>lane)&1u) && !(u0 < prob);
    bool keep1 = ((w1>>lane)&1u) && !(u1 < prob);
    unsigned bal0 = __ballot_sync(0xffffffffu, keep0);
    unsigned bal1 = __ballot_sync(0xffffffffu, keep1);
    if (lane==0){
      if (bal0) atomicAdd(&cnt[b0],   __popc(bal0));
      if (bal1) atomicAdd(&cnt[b0+8], __popc(bal1));
    }
  }
  __syncthreads();
  if (threadIdx.x < BB && cnt[threadIdx.x]) atomicAdd(&g_kept[threadIdx.x], cnt[threadIdx.x]);
}

__global__ void k_mma64(const __nv_bfloat16* __restrict__ Bh,
                        const __nv_bfloat16* __restrict__ Bl,
                        float* __restrict__ C){
  mma_body<64>(blockIdx.x*128, blockIdx.y, Bh, Bl, C);
}

// r-gate: 4b x 4o register tile per thread.
__global__ void __launch_bounds__(128) k_gate_r(const float* __restrict__ x,
                                                const float* __restrict__ st){
  int n = blockIdx.x;
  __shared__ float Xg[256*20];
  int t = threadIdx.x;
  for (int q=t; q<4096; q+=128){
    int b = q>>8, i = q&255;
    float v;
    if (i < 64)       v = x[((size_t)b*NN_+n)*64 + i];
    else if (i < 128) v = st[((size_t)b*NN_+n)*64 + (i-64)];
    else              v = g_xb[((size_t)b*NN_+n)*128 + (i-128)];
    Xg[i*20 + b] = v;
  }
  __syncthreads();
  int og = t>>2, bg = t&3;
  int o0 = og*4, b0 = bg*4;
  float acc[4][4] = {};
  const float* W = g_Wn_r + (size_t)n*256*128 + o0;
  #pragma unroll 2
  for (int i=0;i<256;i++){
    float4 xv = *(float4*)&Xg[i*20 + b0];
    float4 wv = *(const float4*)&W[(size_t)i*128];
    float xs[4] = {xv.x,xv.y,xv.z,xv.w};
    float ws[4] = {wv.x,wv.y,wv.z,wv.w};
    #pragma unroll
    for (int bi=0;bi<4;bi++)
      #pragma unroll
      for (int oi=0;oi<4;oi++)
        acc[bi][oi] += xs[bi]*ws[oi];
  }
  float4 bias = *(const float4*)&g_bias_r[n*128 + o0];
  float bs[4] = {bias.x,bias.y,bias.z,bias.w};
  #pragma unroll
  for (int bi=0;bi<4;bi++){
    int b = b0+bi;
    size_t idx = ((size_t)b*NN_+n)*64;
    #pragma unroll
    for (int oi=0;oi<4;oi++){
      int o = o0+oi;
      float g = 1.0f/(1.0f+__expf(-(acc[bi][oi]+bs[oi])));
      if (o < 64){
        float zsv = g * st[idx + o];
        g_zs[idx + o] = zsv;
        __nv_bfloat16 h, l; split_bf16(zsv, h, l);
        g_zh[idx + o] = h; g_zl[idx + o] = l;
      } else {
        g_rb[idx + (o-64)] = g;
      }
    }
  }
}

// u-gate + GRU output; block 1024 computes mask_loss.
__global__ void __launch_bounds__(128) k_gate_u(const float* __restrict__ x,
                                                const float* __restrict__ st,
                                                float* __restrict__ out_h,
                                                float* __restrict__ out_loss){
  if (blockIdx.x == NN_){
    if (threadIdx.x < BB){
      unsigned int tot = 0;
      #pragma unroll
      for (int i=0;i<BB;i++) tot += g_pos[i];
      float active = (float)tot / (float)BNN;
      float addend = fmaxf(0.05f/active - 1.0f, 0.0f);
      int b = threadIdx.x;
      out_loss[b] = (float)g_kept[b] / ((float)g_pos[b] + 1e-8f) + addend;
    }
    return;
  }
  int n = blockIdx.x;
  __shared__ float Xg[256*20];
  int t = threadIdx.x;
  for (int q=t; q<4096; q+=128){
    int b = q>>8, i = q&255;
    float v;
    if (i < 64)       v = x[((size_t)b*NN_+n)*64 + i];
    else if (i < 128) v = g_zs[((size_t)b*NN_+n)*64 + (i-64)];
    else if (i < 192) v = g_xb[((size_t)b*NN_+n)*128 + (i-128)];
    else              v = g_c2[((size_t)b*NN_+n)*64 + (i-192)];
    Xg[i*20 + b] = v;
  }
  __syncthreads();
  int og = t>>3, bg = t&7;
  int o0 = og*4, b0 = bg*2;
  float acc[2][4] = {};
  const float* W = g_Wn_u + (size_t)n*256*64 + o0;
  #pragma unroll 2
  for (int i=0;i<256;i++){
    float2 xv = *(float2*)&Xg[i*20 + b0];
    float4 wv = *(const float4*)&W[(size_t)i*64];
    float xs[2] = {xv.x,xv.y};
    float ws[4] = {wv.x,wv.y,wv.z,wv.w};
    #pragma unroll
    for (int bi=0;bi<2;bi++)
      #pragma unroll
      for (int oi=0;oi<4;oi++)
        acc[bi][oi] += xs[bi]*ws[oi];
  }
  float4 bias = *(const float4*)&g_bias_u[n*64 + o0];
  float bs[4] = {bias.x,bias.y,bias.z,bias.w};
  #pragma unroll
  for (int bi=0;bi<2;bi++){
    int b = b0+bi;
    size_t idx = ((size_t)b*NN_+n)*64;
    #pragma unroll
    for (int oi=0;oi<4;oi++){
      int o = o0+oi;
      float hc = tanhf(acc[bi][oi]+bs[oi]);
      float r = g_rb[idx + o];
      float sv = st[idx + o];
      out_h[idx + o] = r*sv + (1.0f-r)*hc;
    }
  }
}

// ---------------- launch ----------------
extern "C" void kernel_launch(void* const* d_in, const int* in_sizes, int n_in,
                              void* d_out, int out_size){
  const float* x    = (const float*)d_in[0];
  const float* st   = (const float*)d_in[1];
  const float* we   = (const float*)d_in[2];
  const float* T    = (const float*)d_in[3];
  const float* Wpr  = (const float*)d_in[4];
  const float* bpr  = (const float*)d_in[5];
  const float* Wpu  = (const float*)d_in[6];
  const float* bpu  = (const float*)d_in[7];
  const float* mp   = (const float*)d_in[8];
  const float* tp   = (const float*)d_in[9];
  const float* gmm  = (const float*)d_in[10];
  const float* bta  = (const float*)d_in[11];
  const int*   itp  = (const int*)d_in[12];
  float* out = (float*)d_out;
  float* out_mask = out + OFF_MASK;

  static __nv_bfloat16 *xh_p=nullptr, *xl_p=nullptr, *zh_p=nullptr, *zl_p=nullptr;
  static float *xb_p=nullptr, *c2_p=nullptr;
  if (!xh_p){
    cudaGetSymbolAddress((void**)&xh_p, g_xh);
    cudaGetSymbolAddress((void**)&xl_p, g_xl);
    cudaGetSymbolAddress((void**)&zh_p, g_zh);
    cudaGetSymbolAddress((void**)&zl_p, g_zl);
    cudaGetSymbolAddress((void**)&xb_p, g_xb);
    cudaGetSymbolAddress((void**)&c2_p, g_c2);
    size_t smem_sup = (size_t)(2*WINDOW*NN_)*sizeof(float); // 96 KB
    cudaFuncSetAttribute(k_sup_wgen, cudaFuncAttributeMaxDynamicSharedMemorySize, (int)smem_sup);
  }
  size_t smem_sup = (size_t)(2*WINDOW*NN_)*sizeof(float);

  k_setup<<<64,256>>>(we, itp);                        // 1
  k_pre<<<4096,256>>>(mp, bpr, bpu, x, st);            // 2
  k_sup_wgen<<<2560,256,smem_sup>>>(T, tp, gmm, bta, out_mask, Wpr, Wpu); // 3
  k_mma_kept<<<8320,256>>>(xh_p, xl_p, xb_p);          // 4
  k_gate_r<<<NN_,128>>>(x, st);                        // 5
  k_mma64<<<dim3(8,16),256>>>(zh_p, zl_p, c2_p);       // 6
  k_gate_u<<<NN_+1,128>>>(x, st, out, out + OFF_LOSS); // 7
}

// round 8
// speedup vs baseline: 2.1130x; 1.0346x over previous
#include <cuda_runtime.h>
#include <cuda_bf16.h>
#include <cstdint>
#include <math.h>

#define BB 16
#define NN_ 1024
#define EDIM 16
#define WINDOW 12
#define NNSQ (NN_*NN_)
#define BNN (BB*NNSQ)
#define HALF_BNN (BNN/2)
#define OFF_MASK (BB*NN_*64)
#define OFF_LOSS (OFF_MASK + BNN)
#define MASK_THR (-2.66352776f)   /* ln(1.4) - 3 */

// ---------------- scratch ----------------
__device__ float g_E[NN_*EDIM];
__device__ float g_Et[EDIM*NN_];
__device__ float g_EM[NNSQ];
__device__ float g_supports[NNSQ];
__device__ __nv_bfloat16 g_sh[(size_t)BNN];
__device__ __nv_bfloat16 g_sl[(size_t)BNN];
__device__ uint32_t g_bits[BNN/32];
__device__ __nv_bfloat16 g_xh[(size_t)BB*NN_*128];
__device__ __nv_bfloat16 g_xl[(size_t)BB*NN_*128];
__device__ __nv_bfloat16 g_zh[(size_t)BB*NN_*64];
__device__ __nv_bfloat16 g_zl[(size_t)BB*NN_*64];
__device__ float g_Wn_r[(size_t)NN_*256*128];
__device__ float g_Wn_u[(size_t)NN_*256*64];
__device__ float g_bias_r[NN_*128];
__device__ float g_bias_u[NN_*64];
__device__ float g_xb[(size_t)BB*NN_*128];
__device__ float g_zs[(size_t)BB*NN_*64];
__device__ float g_rb[(size_t)BB*NN_*64];
__device__ float g_c2[(size_t)BB*NN_*64];
__device__ unsigned int g_pos[BB];
__device__ unsigned int g_kept[BB];

// ---------------- helpers ----------------
__device__ __forceinline__ float warpSum(float v){
  #pragma unroll
  for (int o=16;o;o>>=1) v += __shfl_xor_sync(0xffffffffu, v, o);
  return v;
}
__device__ __forceinline__ float blockSum(float v, float* red){
  int lane = threadIdx.x & 31, w = threadIdx.x >> 5;
  int nw = blockDim.x >> 5;
  v = warpSum(v);
  __syncthreads();
  if (lane==0) red[w] = v;
  __syncthreads();
  float r = (threadIdx.x < (unsigned)nw) ? red[threadIdx.x] : 0.0f;
  if (w==0) r = warpSum(r);
  if (threadIdx.x==0) red[0] = r;
  __syncthreads();
  return red[0];
}
__device__ __forceinline__ uint32_t rotl32(uint32_t x, int r){
  return __funnelshift_l(x, x, r);
}
__device__ __forceinline__ void threefry2x32(uint32_t k0, uint32_t k1,
                                             uint32_t& x0, uint32_t& x1){
  uint32_t ks0 = k0, ks1 = k1, ks2 = k0 ^ k1 ^ 0x1BD11BDAu;
  x0 += ks0; x1 += ks1;
  const int R0[4] = {13,15,26,6};
  const int R1[4] = {17,29,16,24};
  uint32_t ks[3] = {ks0, ks1, ks2};
  #pragma unroll
  for (int i=0;i<5;i++){
    #pragma unroll
    for (int j=0;j<4;j++){
      int r = (i & 1) ? R1[j] : R0[j];
      x0 += x1; x1 = rotl32(x1, r); x1 ^= x0;
    }
    x0 += ks[(i+1)%3];
    x1 += ks[(i+2)%3] + (uint32_t)(i+1);
  }
}
__device__ __forceinline__ void split_bf16(float v, __nv_bfloat16& h, __nv_bfloat16& l){
  h = __float2bfloat16(v);
  l = __float2bfloat16(v - __bfloat162float(h));
}
__device__ __forceinline__ uint32_t pack_bf2(__nv_bfloat16 a, __nv_bfloat16 b){
  __nv_bfloat162 p(a, b);
  return *reinterpret_cast<uint32_t*>(&p);
}
__device__ __forceinline__ void ldsm4(uint32_t& r0,uint32_t& r1,uint32_t& r2,uint32_t& r3,
                                      const __nv_bfloat16* p){
  uint32_t a = (uint32_t)__cvta_generic_to_shared(p);
  asm volatile("ldmatrix.sync.aligned.m8n8.x4.shared.b16 {%0,%1,%2,%3},[%4];"
    : "=r"(r0),"=r"(r1),"=r"(r2),"=r"(r3) : "r"(a));
}
__device__ __forceinline__ void ldsm2t(uint32_t& r0,uint32_t& r1, const __nv_bfloat16* p){
  uint32_t a = (uint32_t)__cvta_generic_to_shared(p);
  asm volatile("ldmatrix.sync.aligned.m8n8.x2.trans.shared.b16 {%0,%1},[%2];"
    : "=r"(r0),"=r"(r1) : "r"(a));
}
__device__ __forceinline__ void mma16816(float* c, const uint32_t* a, const uint32_t* b){
  asm volatile("mma.sync.aligned.m16n8k16.row.col.f32.bf16.bf16.f32 "
    "{%0,%1,%2,%3},{%4,%5,%6,%7},{%8,%9},{%0,%1,%2,%3};"
    : "+f"(c[0]),"+f"(c[1]),"+f"(c[2]),"+f"(c[3])
    : "r"(a[0]),"r"(a[1]),"r"(a[2]),"r"(a[3]), "r"(b[0]),"r"(b[1]));
}
__device__ __forceinline__ float prob_from_pos(){
  unsigned int tot = 0;
  #pragma unroll
  for (int i=0;i<BB;i++) tot += g_pos[i];
  float active = (float)tot / (float)BNN;
  return fminf(0.05f/active + 1e-8f, 1.0f);
}

// ---------------- kernels ----------------

__global__ void k_setup(const float* __restrict__ we, const int* __restrict__ itp){
  int tid = blockIdx.x*blockDim.x + threadIdx.x;
  float it = (float)itp[0];
  if (tid < NN_*EDIM){
    int d = tid & 15;
    int pair = d >> 1;
    float arg = (float)((double)(2*pair) * (-9.210340371976184/16.0));
    float div = expf(arg);
    float pe = (d & 1) ? cosf(it*div) : sinf(it*div);
    float e = we[tid] + pe;
    g_E[tid] = e;
    g_Et[d*NN_ + (tid>>4)] = e;
  }
  if (blockIdx.x==0 && threadIdx.x < 2*BB){
    if (threadIdx.x < BB) g_pos[threadIdx.x] = 0u;
    else                  g_kept[threadIdx.x-BB] = 0u;
  }
}

// Merged: [0,1024) em+bias, [1024,2048) supports, [2048,4096) prep.
__global__ void k_pre(const float* __restrict__ mp,
                      const float* __restrict__ bpr, const float* __restrict__ bpu,
                      const float* __restrict__ x, const float* __restrict__ st){
  int g = blockIdx.x;
  if (g < NN_){
    int n = g;
    __shared__ float en[EDIM];
    if (threadIdx.x < EDIM) en[threadIdx.x] = g_E[n*EDIM+threadIdx.x];
    __syncthreads();
    int m0 = threadIdx.x*4;
    float4 a = make_float4(0.f,0.f,0.f,0.f);
    #pragma unroll
    for (int d=0; d<EDIM; d++){
      float4 mv = *(const float4*)&mp[d*NN_+m0];
      float e = en[d];
      a.x += e*mv.x; a.y += e*mv.y; a.z += e*mv.z; a.w += e*mv.w;
    }
    *(float4*)&g_EM[n*NN_+m0] = a;
    int o = threadIdx.x;
    if (o < 128){
      float br = 0.f;
      #pragma unroll
      for (int d=0; d<EDIM; d++) br += en[d]*bpr[d*128+o];
      g_bias_r[n*128+o] = br;
      if (o < 64){
        float bu = 0.f;
        #pragma unroll
        for (int d=0; d<EDIM; d++) bu += en[d]*bpu[d*64+o];
        g_bias_u[n*64+o] = bu;
      }
    }
  } else if (g < 2*NN_){
    int n = g - NN_;
    __shared__ float row[NN_];
    __shared__ float red[32];
    float en[EDIM];
    #pragma unroll
    for (int d=0; d<EDIM; d++) en[d] = g_E[n*EDIM+d];
    int m0 = threadIdx.x*4;
    float4 a = make_float4(0.f,0.f,0.f,0.f);
    #pragma unroll
    for (int d=0; d<EDIM; d++){
      float4 ev = *(const float4*)&g_Et[d*NN_+m0];
      float e = en[d];
      a.x += e*ev.x; a.y += e*ev.y; a.z += e*ev.z; a.w += e*ev.w;
    }
    a.x = __expf(fmaxf(a.x,0.f)); a.y = __expf(fmaxf(a.y,0.f));
    a.z = __expf(fmaxf(a.z,0.f)); a.w = __expf(fmaxf(a.w,0.f));
    *(float4*)&row[m0] = a;
    float s = blockSum(a.x+a.y+a.z+a.w, red);
    float inv = 1.0f/s;
    float4 r4 = *(float4*)&row[m0];
    r4.x *= inv; r4.y *= inv; r4.z *= inv; r4.w *= inv;
    *(float4*)&g_supports[n*NN_+m0] = r4;
  } else {
    int q = (g - 2*NN_)*256 + threadIdx.x;
    int t4 = q*4;
    int j = t4 & 127; int bn = t4 >> 7;
    float4 v = (j < 64) ? *(const float4*)&x[(size_t)bn*64 + j]
                        : *(const float4*)&st[(size_t)bn*64 + (j-64)];
    __nv_bfloat16 h0,l0,h1,l1,h2,l2,h3,l3;
    split_bf16(v.x,h0,l0); split_bf16(v.y,h1,l1);
    split_bf16(v.z,h2,l2); split_bf16(v.w,h3,l3);
    *(uint2*)&g_xh[t4] = make_uint2(pack_bf2(h0,h1), pack_bf2(h2,h3));
    *(uint2*)&g_xl[t4] = make_uint2(pack_bf2(l0,l1), pack_bf2(l2,l3));
  }
}

// Wn[n,i2,o] = sum_d E[n,d] * Wp[d,i2,o]  (256 threads)
template<int OC>
__device__ __forceinline__ void wgen_body(const float* __restrict__ Wp, float* __restrict__ Wn,
                                          int lb, float* Esm){
  constexpr int NQ = OC/4;
  constexpr int NI = 256/NQ;
  int n0 = (lb>>4)*64;
  int i20 = (lb&15)*16;
  int t = threadIdx.x;
  int oq = t % NQ, ig = t / NQ;
  for (int q=t; q<64*EDIM; q+=256)
    Esm[q] = g_E[(n0 + (q>>4))*EDIM + (q&15)];
  __syncthreads();
  for (int ii=ig; ii<16; ii+=NI){
    int i2 = i20+ii;
    float4 w[EDIM];
    #pragma unroll
    for (int d=0; d<EDIM; d++)
      w[d] = *(const float4*)&Wp[((size_t)d*256 + i2)*OC + oq*4];
    #pragma unroll 4
    for (int nn=0; nn<64; nn++){
      float4 a = make_float4(0.f,0.f,0.f,0.f);
      #pragma unroll
      for (int d=0; d<EDIM; d++){
        float e = Esm[nn*EDIM + d];
        a.x += e*w[d].x; a.y += e*w[d].y; a.z += e*w[d].z; a.w += e*w[d].w;
      }
      *(float4*)&Wn[((size_t)(n0+nn)*256 + i2)*OC + oq*4] = a;
    }
  }
}

// Combined: every 5th block wgen (512), rest supmask (2048), 8 rows/block register-blocked.
__global__ void __launch_bounds__(256) k_sup_wgen(
    const float* __restrict__ T, const float* __restrict__ TP,
    const float* __restrict__ gamma, const float* __restrict__ beta,
    float* __restrict__ out_mask,
    const float* __restrict__ Wpr, const float* __restrict__ Wpu){
  __shared__ float Esm[64*EDIM];
  __shared__ float red[8][8];
  __shared__ float inv8[8];
  int bid = blockIdx.x;
  if (bid % 5 == 0){
    int lb = bid/5;
    if (lb < 256) wgen_body<128>(Wpr, g_Wn_r, lb, Esm);
    else          wgen_body<64>(Wpu, g_Wn_u, lb-256, Esm);
    return;
  }
  int id = bid - bid/5 - 1;
  int b = id >> 7;
  int n0 = (id & 127)*8;
  extern __shared__ float sm[];
  float* Tsm  = sm;
  float* TPsm = sm + WINDOW*NN_;
  int tid = threadIdx.x, lane = tid & 31, wrp = tid >> 5;
  for (int t=tid; t<WINDOW*NN_; t+=256){
    Tsm[t]  = T[(size_t)b*WINDOW*NN_ + t];
    TPsm[t] = TP[t];
  }
  __syncthreads();
  int m0 = tid*4;
  float tg[8][4];
  #pragma unroll
  for (int r=0;r<8;r++){ tg[r][0]=0.f; tg[r][1]=0.f; tg[r][2]=0.f; tg[r][3]=0.f; }
  #pragma unroll
  for (int w=0; w<WINDOW; w++){
    float4 tw = *(float4*)&Tsm[w*NN_+m0];
    #pragma unroll
    for (int r=0;r<8;r++){
      float tvs = Tsm[w*NN_ + n0 + r];
      tg[r][0] += tvs*tw.x; tg[r][1] += tvs*tw.y;
      tg[r][2] += tvs*tw.z; tg[r][3] += tvs*tw.w;
    }
  }
  float psum[8];
  #pragma unroll
  for (int r=0;r<8;r++){
    tg[r][0] = __expf(fmaxf(tg[r][0],0.f));
    tg[r][1] = __expf(fmaxf(tg[r][1],0.f));
    tg[r][2] = __expf(fmaxf(tg[r][2],0.f));
    tg[r][3] = __expf(fmaxf(tg[r][3],0.f));
    psum[r] = (tg[r][0]+tg[r][1])+(tg[r][2]+tg[r][3]);
  }
  #pragma unroll
  for (int r=0;r<8;r++) psum[r] = warpSum(psum[r]);
  if (lane==0){
    #pragma unroll
    for (int r=0;r<8;r++) red[r][wrp] = psum[r];
  }
  __syncthreads();
  if (tid < 8){
    float s = 0.f;
    #pragma unroll
    for (int k=0;k<8;k++) s += red[tid][k];
    inv8[tid] = 1.0f/s;
  }
  __syncthreads();
  float rm[8][4];
  #pragma unroll
  for (int r=0;r<8;r++){
    float4 t = *(const float4*)&g_EM[(size_t)(n0+r)*NN_ + m0];
    rm[r][0]=t.x; rm[r][1]=t.y; rm[r][2]=t.z; rm[r][3]=t.w;
  }
  #pragma unroll
  for (int w=0; w<WINDOW; w++){
    float4 tp = *(float4*)&TPsm[w*NN_+m0];
    #pragma unroll
    for (int r=0;r<8;r++){
      float tvs = Tsm[w*NN_ + n0 + r];
      rm[r][0] += tvs*tp.x; rm[r][1] += tvs*tp.y;
      rm[r][2] += tvs*tp.z; rm[r][3] += tvs*tp.w;
    }
  }
  const float bni = 1.0f/sqrtf(1.0f + 1e-5f);
  unsigned int cnt = 0;
  #pragma unroll
  for (int r=0;r<8;r++){
    int n = n0 + r;
    float sc = bni*gamma[n], bt = beta[n];
    float v0 = rm[r][0]*sc + bt, v1 = rm[r][1]*sc + bt;
    float v2 = rm[r][2]*sc + bt, v3 = rm[r][3]*sc + bt;
    uint32_t nib = (v0 > MASK_THR ? 1u:0u) | (v1 > MASK_THR ? 2u:0u)
                 | (v2 > MASK_THR ? 4u:0u) | (v3 > MASK_THR ? 8u:0u);
    float4 mk = make_float4(nib&1u?1.f:0.f, nib&2u?1.f:0.f, nib&4u?1.f:0.f, nib&8u?1.f:0.f);
    size_t idx = (size_t)b*NNSQ + (size_t)n*NN_ + m0;
    *(float4*)&out_mask[idx] = mk;
    float inv = inv8[r];
    float4 sp = *(const float4*)&g_supports[n*NN_+m0];
    sp.x = (sp.x + tg[r][0]*inv)*0.5f*mk.x;
    sp.y = (sp.y + tg[r][1]*inv)*0.5f*mk.y;
    sp.z = (sp.z + tg[r][2]*inv)*0.5f*mk.z;
    sp.w = (sp.w + tg[r][3]*inv)*0.5f*mk.w;
    __nv_bfloat16 h0,l0,h1,l1,h2,l2,h3,l3;
    split_bf16(sp.x,h0,l0); split_bf16(sp.y,h1,l1);
    split_bf16(sp.z,h2,l2); split_bf16(sp.w,h3,l3);
    *(uint2*)&g_sh[idx] = make_uint2(pack_bf2(h0,h1), pack_bf2(h2,h3));
    *(uint2*)&g_sl[idx] = make_uint2(pack_bf2(l0,l1), pack_bf2(l2,l3));
    cnt += __popc(nib);
    uint32_t v = nib << ((lane&7)*4);
    v |= __shfl_xor_sync(0xffffffffu, v, 1);
    v |= __shfl_xor_sync(0xffffffffu, v, 2);
    v |= __shfl_xor_sync(0xffffffffu, v, 4);
    if ((lane&7)==0) g_bits[idx>>5] = v;
  }
  float fc = blockSum((float)cnt, (float*)red);
  if (tid==0) atomicAdd(&g_pos[b], (unsigned int)(fc + 0.5f));
}

// kept-count: standalone, low-reg, overlapped on a forked stream.
__global__ void __launch_bounds__(256) k_kept(){
  __shared__ unsigned int cnt[BB];
  if (threadIdx.x < BB) cnt[threadIdx.x] = 0u;
  __syncthreads();
  float prob = prob_from_pos();
  int lane = threadIdx.x & 31;
  unsigned int base = blockIdx.x*1024u + threadIdx.x;
  #pragma unroll
  for (int k=0;k<4;k++){
    unsigned int t = base + (unsigned)k*256u;
    uint32_t x0 = t, x1 = t + (uint32_t)HALF_BNN;
    threefry2x32(0u, 42u, x0, x1);
    float u0 = __uint_as_float((x0>>9) | 0x3f800000u) - 1.0f;
    float u1 = __uint_as_float((x1>>9) | 0x3f800000u) - 1.0f;
    uint32_t w0 = g_bits[t>>5];
    uint32_t w1 = g_bits[(t + HALF_BNN)>>5];
    int b0 = (int)(t >> 20);
    bool keep0 = ((w0>>lane)&1u) && !(u0 < prob);
    bool keep1 = ((w1>>lane)&1u) && !(u1 < prob);
    unsigned bal0 = __ballot_sync(0xffffffffu, keep0);
    unsigned bal1 = __ballot_sync(0xffffffffu, keep1);
    if (lane==0){
      if (bal0) atomicAdd(&cnt[b0],   __popc(bal0));
      if (bal1) atomicAdd(&cnt[b0+8], __popc(bal1));
    }
  }
  __syncthreads();
  if (threadIdx.x < BB && cnt[threadIdx.x]) atomicAdd(&g_kept[threadIdx.x], cnt[threadIdx.x]);
}

// mma<128>: 512 threads, 16 warps (8M x 2N), double-buffered smem + register prefetch.
__global__ void __launch_bounds__(512) k_mma128(const __nv_bfloat16* __restrict__ Bh,
                                                const __nv_bfloat16* __restrict__ Bl,
                                                float* __restrict__ C){
  constexpr int NO = 128;
  constexpr int BST = NO+8;
  constexpr int APITCH = 40;
  __shared__ __nv_bfloat16 Ash[2][128*APITCH], Asl[2][128*APITCH];
  __shared__ __nv_bfloat16 Bsh[2][32*BST],     Bsl[2][32*BST];
  int b = blockIdx.x >> 3;
  int m0 = (blockIdx.x & 7)*128;
  int w = threadIdx.x>>5, lane = threadIdx.x&31;
  int wm = (w>>1)*16;
  int wn = (w&1)*64;
  float acc[8][4];
  #pragma unroll
  for (int j=0;j<8;j++){ acc[j][0]=0.f; acc[j][1]=0.f; acc[j][2]=0.f; acc[j][3]=0.f; }
  const __nv_bfloat16* Ahb = g_sh + (size_t)b*NNSQ;
  const __nv_bfloat16* Alb = g_sl + (size_t)b*NNSQ;
  const __nv_bfloat16* Bhb = Bh + (size_t)b*NN_*NO;
  const __nv_bfloat16* Blb = Bl + (size_t)b*NN_*NO;
  // per-thread load slots (one uint4 each)
  int ar = threadIdx.x>>2, ac = threadIdx.x&3;          // A: 128 rows x 4 col-chunks
  int brr = threadIdx.x>>4, bc = threadIdx.x&15;        // B: 32 rows x 16 col-chunks
  uint4 pAh, pAl, pBh, pBl;
  auto ldtile = [&](int k0){
    pAh = *(const uint4*)&Ahb[(size_t)(m0+ar)*NN_ + k0 + ac*8];
    pAl = *(const uint4*)&Alb[(size_t)(m0+ar)*NN_ + k0 + ac*8];
    pBh = *(const uint4*)&Bhb[(size_t)(k0+brr)*NO + bc*8];
    pBl = *(const uint4*)&Blb[(size_t)(k0+brr)*NO + bc*8];
  };
  auto sttile = [&](int buf){
    *(uint4*)&Ash[buf][ar*APITCH + ac*8] = pAh;
    *(uint4*)&Asl[buf][ar*APITCH + ac*8] = pAl;
    *(uint4*)&Bsh[buf][brr*BST + bc*8] = pBh;
    *(uint4*)&Bsl[buf][brr*BST + bc*8] = pBl;
  };
  ldtile(0);
  sttile(0);
  __syncthreads();
  #pragma unroll 1
  for (int t=0;t<32;t++){
    if (t+1 < 32) ldtile((t+1)*32);
    int buf = t & 1;
    #pragma unroll
    for (int kk=0; kk<2; kk++){
      uint32_t ah[4], al[4];
      int aoff = (wm + (lane&15))*APITCH + kk*16 + (lane>>4)*8;
      ldsm4(ah[0],ah[1],ah[2],ah[3], &Ash[buf][aoff]);
      ldsm4(al[0],al[1],al[2],al[3], &Asl[buf][aoff]);
      #pragma unroll
      for (int j=0;j<8;j++){
        uint32_t bh[2], bl[2];
        int boff = (kk*16 + (lane&15))*BST + wn + j*8;
        ldsm2t(bh[0],bh[1], &Bsh[buf][boff]);
        ldsm2t(bl[0],bl[1], &Bsl[buf][boff]);
        mma16816(acc[j], ah, bh);
        mma16816(acc[j], ah, bl);
        mma16816(acc[j], al, bh);
      }
    }
    if (t+1 < 32){
      __syncthreads();
      sttile((t+1)&1);
      __syncthreads();
    }
  }
  #pragma unroll
  for (int j=0;j<8;j++){
    int r0 = m0 + wm + (lane>>2);
    int c0 = wn + j*8 + (lane&3)*2;
    float* Cp = C + ((size_t)b*NN_ + r0)*NO + c0;
    Cp[0] = acc[j][0]; Cp[1] = acc[j][1];
    Cp[(size_t)8*NO] = acc[j][2]; Cp[(size_t)8*NO+1] = acc[j][3];
  }
}

// mma<64> (proven 256-thread version)
__global__ void k_mma64(const __nv_bfloat16* __restrict__ Bh,
                        const __nv_bfloat16* __restrict__ Bl,
                        float* __restrict__ C){
  constexpr int NO = 64;
  constexpr int BST = NO+8;
  __shared__ __nv_bfloat16 Ash[128*40], Asl[128*40];
  __shared__ __nv_bfloat16 Bsh[32*BST], Bsl[32*BST];
  int b = blockIdx.y;
  int m0 = blockIdx.x*128;
  int w = threadIdx.x>>5, lane = threadIdx.x&31;
  int wm = w*16;
  int wn = 0;
  float acc[8][4];
  #pragma unroll
  for (int j=0;j<8;j++){ acc[j][0]=0.f; acc[j][1]=0.f; acc[j][2]=0.f; acc[j][3]=0.f; }
  const __nv_bfloat16* Ahb = g_sh + (size_t)b*NNSQ;
  const __nv_bfloat16* Alb = g_sl + (size_t)b*NNSQ;
  const __nv_bfloat16* Bhb = Bh + (size_t)b*NN_*NO;
  const __nv_bfloat16* Blb = Bl + (size_t)b*NN_*NO;
  for (int k0=0;k0<NN_;k0+=32){
    #pragma unroll
    for (int i = threadIdx.x; i<512; i+=256){
      int r = i>>2, c = i&3;
      *(uint4*)&Ash[r*40 + c*8] = *(const uint4*)&Ahb[(size_t)(m0+r)*NN_ + k0 + c*8];
      *(uint4*)&Asl[r*40 + c*8] = *(const uint4*)&Alb[(size_t)(m0+r)*NN_ + k0 + c*8];
    }
    {
      int i = threadIdx.x;
      int r = i>>3, c = i&7;
      *(uint4*)&Bsh[r*BST + c*8] = *(const uint4*)&Bhb[(size_t)(k0+r)*NO + c*8];
      *(uint4*)&Bsl[r*BST + c*8] = *(const uint4*)&Blb[(size_t)(k0+r)*NO + c*8];
    }
    __syncthreads();
    #pragma unroll
    for (int kk=0; kk<2; kk++){
      uint32_t ah[4], al[4];
      int aoff = (wm + (lane&15))*40 + kk*16 + (lane>>4)*8;
      ldsm4(ah[0],ah[1],ah[2],ah[3], &Ash[aoff]);
      ldsm4(al[0],al[1],al[2],al[3], &Asl[aoff]);
      #pragma unroll
      for (int j=0;j<8;j++){
        uint32_t bh[2], bl[2];
        int boff = (kk*16 + (lane&15))*BST + wn + j*8;
        ldsm2t(bh[0],bh[1], &Bsh[boff]);
        ldsm2t(bl[0],bl[1], &Bsl[boff]);
        mma16816(acc[j], ah, bh);
        mma16816(acc[j], ah, bl);
        mma16816(acc[j], al, bh);
      }
    }
    __syncthreads();
  }
  #pragma unroll
  for (int j=0;j<8;j++){
    int r0 = m0 + wm + (lane>>2);
    int c0 = wn + j*8 + (lane&3)*2;
    float* Cp = C + ((size_t)b*NN_ + r0)*NO + c0;
    Cp[0] = acc[j][0]; Cp[1] = acc[j][1];
    Cp[(size_t)8*NO] = acc[j][2]; Cp[(size_t)8*NO+1] = acc[j][3];
  }
}

// r-gate: 4b x 4o register tile per thread.
__global__ void __launch_bounds__(128) k_gate_r(const float* __restrict__ x,
                                                const float* __restrict__ st){
  int n = blockIdx.x;
  __shared__ float Xg[256*20];
  int t = threadIdx.x;
  for (int q=t; q<4096; q+=128){
    int b = q>>8, i = q&255;
    float v;
    if (i < 64)       v = x[((size_t)b*NN_+n)*64 + i];
    else if (i < 128) v = st[((size_t)b*NN_+n)*64 + (i-64)];
    else              v = g_xb[((size_t)b*NN_+n)*128 + (i-128)];
    Xg[i*20 + b] = v;
  }
  __syncthreads();
  int og = t>>2, bg = t&3;
  int o0 = og*4, b0 = bg*4;
  float acc[4][4] = {};
  const float* W = g_Wn_r + (size_t)n*256*128 + o0;
  #pragma unroll 2
  for (int i=0;i<256;i++){
    float4 xv = *(float4*)&Xg[i*20 + b0];
    float4 wv = *(const float4*)&W[(size_t)i*128];
    float xs[4] = {xv.x,xv.y,xv.z,xv.w};
    float ws[4] = {wv.x,wv.y,wv.z,wv.w};
    #pragma unroll
    for (int bi=0;bi<4;bi++)
      #pragma unroll
      for (int oi=0;oi<4;oi++)
        acc[bi][oi] += xs[bi]*ws[oi];
  }
  float4 bias = *(const float4*)&g_bias_r[n*128 + o0];
  float bs[4] = {bias.x,bias.y,bias.z,bias.w};
  #pragma unroll
  for (int bi=0;bi<4;bi++){
    int b = b0+bi;
    size_t idx = ((size_t)b*NN_+n)*64;
    #pragma unroll
    for (int oi=0;oi<4;oi++){
      int o = o0+oi;
      float g = 1.0f/(1.0f+__expf(-(acc[bi][oi]+bs[oi])));
      if (o < 64){
        float zsv = g * st[idx + o];
        g_zs[idx + o] = zsv;
        __nv_bfloat16 h, l; split_bf16(zsv, h, l);
        g_zh[idx + o] = h; g_zl[idx + o] = l;
      } else {
        g_rb[idx + (o-64)] = g;
      }
    }
  }
}

// u-gate + GRU output; block 1024 computes mask_loss.
__global__ void __launch_bounds__(128) k_gate_u(const float* __restrict__ x,
                                                const float* __restrict__ st,
                                                float* __restrict__ out_h,
                                                float* __restrict__ out_loss){
  if (blockIdx.x == NN_){
    if (threadIdx.x < BB){
      unsigned int tot = 0;
      #pragma unroll
      for (int i=0;i<BB;i++) tot += g_pos[i];
      float active = (float)tot / (float)BNN;
      float addend = fmaxf(0.05f/active - 1.0f, 0.0f);
      int b = threadIdx.x;
      out_loss[b] = (float)g_kept[b] / ((float)g_pos[b] + 1e-8f) + addend;
    }
    return;
  }
  int n = blockIdx.x;
  __shared__ float Xg[256*20];
  int t = threadIdx.x;
  for (int q=t; q<4096; q+=128){
    int b = q>>8, i = q&255;
    float v;
    if (i < 64)       v = x[((size_t)b*NN_+n)*64 + i];
    else if (i < 128) v = g_zs[((size_t)b*NN_+n)*64 + (i-64)];
    else if (i < 192) v = g_xb[((size_t)b*NN_+n)*128 + (i-128)];
    else              v = g_c2[((size_t)b*NN_+n)*64 + (i-192)];
    Xg[i*20 + b] = v;
  }
  __syncthreads();
  int og = t>>3, bg = t&7;
  int o0 = og*4, b0 = bg*2;
  float acc[2][4] = {};
  const float* W = g_Wn_u + (size_t)n*256*64 + o0;
  #pragma unroll 2
  for (int i=0;i<256;i++){
    float2 xv = *(float2*)&Xg[i*20 + b0];
    float4 wv = *(const float4*)&W[(size_t)i*64];
    float xs[2] = {xv.x,xv.y};
    float ws[4] = {wv.x,wv.y,wv.z,wv.w};
    #pragma unroll
    for (int bi=0;bi<2;bi++)
      #pragma unroll
      for (int oi=0;oi<4;oi++)
        acc[bi][oi] += xs[bi]*ws[oi];
  }
  float4 bias = *(const float4*)&g_bias_u[n*64 + o0];
  float bs[4] = {bias.x,bias.y,bias.z,bias.w};
  #pragma unroll
  for (int bi=0;bi<2;bi++){
    int b = b0+bi;
    size_t idx = ((size_t)b*NN_+n)*64;
    #pragma unroll
    for (int oi=0;oi<4;oi++){
      int o = o0+oi;
      float hc = tanhf(acc[bi][oi]+bs[oi]);
      float r = g_rb[idx + o];
      float sv = st[idx + o];
      out_h[idx + o] = r*sv + (1.0f-r)*hc;
    }
  }
}

// ---------------- launch ----------------
extern "C" void kernel_launch(void* const* d_in, const int* in_sizes, int n_in,
                              void* d_out, int out_size){
  const float* x    = (const float*)d_in[0];
  const float* st   = (const float*)d_in[1];
  const float* we   = (const float*)d_in[2];
  const float* T    = (const float*)d_in[3];
  const float* Wpr  = (const float*)d_in[4];
  const float* bpr  = (const float*)d_in[5];
  const float* Wpu  = (const float*)d_in[6];
  const float* bpu  = (const float*)d_in[7];
  const float* mp   = (const float*)d_in[8];
  const float* tp   = (const float*)d_in[9];
  const float* gmm  = (const float*)d_in[10];
  const float* bta  = (const float*)d_in[11];
  const int*   itp  = (const int*)d_in[12];
  float* out = (float*)d_out;
  float* out_mask = out + OFF_MASK;

  static __nv_bfloat16 *xh_p=nullptr, *xl_p=nullptr, *zh_p=nullptr, *zl_p=nullptr;
  static float *xb_p=nullptr, *c2_p=nullptr;
  static cudaStream_t s2 = nullptr;
  static cudaEvent_t evFork = nullptr, evJoin = nullptr;
  if (!xh_p){
    cudaGetSymbolAddress((void**)&xh_p, g_xh);
    cudaGetSymbolAddress((void**)&xl_p, g_xl);
    cudaGetSymbolAddress((void**)&zh_p, g_zh);
    cudaGetSymbolAddress((void**)&zl_p, g_zl);
    cudaGetSymbolAddress((void**)&xb_p, g_xb);
    cudaGetSymbolAddress((void**)&c2_p, g_c2);
    size_t smem_sup = (size_t)(2*WINDOW*NN_)*sizeof(float);
    cudaFuncSetAttribute(k_sup_wgen, cudaFuncAttributeMaxDynamicSharedMemorySize, (int)smem_sup);
    cudaStreamCreateWithFlags(&s2, cudaStreamNonBlocking);
    cudaEventCreateWithFlags(&evFork, cudaEventDisableTiming);
    cudaEventCreateWithFlags(&evJoin, cudaEventDisableTiming);
  }
  size_t smem_sup = (size_t)(2*WINDOW*NN_)*sizeof(float);

  k_setup<<<64,256>>>(we, itp);                        // 1
  k_pre<<<4096,256>>>(mp, bpr, bpu, x, st);            // 2
  k_sup_wgen<<<2560,256,smem_sup>>>(T, tp, gmm, bta, out_mask, Wpr, Wpu); // 3
  // fork: kept-count runs concurrently with the GEMM/gate chain
  cudaEventRecord(evFork, 0);
  cudaStreamWaitEvent(s2, evFork, 0);
  k_kept<<<8192,256,0,s2>>>();
  k_mma128<<<128,512>>>(xh_p, xl_p, xb_p);             // 4
  k_gate_r<<<NN_,128>>>(x, st);                        // 5
  k_mma64<<<dim3(8,16),256>>>(zh_p, zl_p, c2_p);       // 6
  // join before gate_u (needs g_kept)
  cudaEventRecord(evJoin, s2);
  cudaStreamWaitEvent(0, evJoin, 0);
  k_gate_u<<<NN_+1,128>>>(x, st, out, out + OFF_LOSS); // 7
}

// round 9
// speedup vs baseline: 2.1804x; 1.0319x over previous
#include <cuda_runtime.h>
#include <cuda_bf16.h>
#include <cuda_fp16.h>
#include <cstdint>
#include <math.h>

#define BB 16
#define NN_ 1024
#define EDIM 16
#define WINDOW 12
#define NNSQ (NN_*NN_)
#define BNN (BB*NNSQ)
#define HALF_BNN (BNN/2)
#define OFF_MASK (BB*NN_*64)
#define OFF_LOSS (OFF_MASK + BNN)
#define MASK_THR (-2.66352776f)   /* ln(1.4) - 3 */

// ---------------- scratch ----------------
__device__ float g_E[NN_*EDIM];
__device__ float g_Et[EDIM*NN_];
__device__ float g_EM[NNSQ];
__device__ float g_supports[NNSQ];
__device__ __half g_sh[(size_t)BNN];                 // sup fp16 (single)
__device__ uint32_t g_bits[BNN/32];
__device__ __half g_xh[(size_t)BB*NN_*128];          // cat(x,state) fp16 hi
__device__ __half g_xl[(size_t)BB*NN_*128];          // fp16 lo residual
__device__ __half g_zh[(size_t)BB*NN_*64];
__device__ __half g_zl[(size_t)BB*NN_*64];
__device__ float g_Wn_r[(size_t)NN_*256*128];
__device__ float g_Wn_u[(size_t)NN_*256*64];
__device__ float g_bias_r[NN_*128];
__device__ float g_bias_u[NN_*64];
__device__ float g_xb[(size_t)BB*NN_*128];
__device__ float g_zs[(size_t)BB*NN_*64];
__device__ float g_rb[(size_t)BB*NN_*64];
__device__ float g_c2[(size_t)BB*NN_*64];
__device__ unsigned int g_pos[BB];
__device__ unsigned int g_kept[BB];

// ---------------- helpers ----------------
__device__ __forceinline__ float warpSum(float v){
  #pragma unroll
  for (int o=16;o;o>>=1) v += __shfl_xor_sync(0xffffffffu, v, o);
  return v;
}
__device__ __forceinline__ float blockSum(float v, float* red){
  int lane = threadIdx.x & 31, w = threadIdx.x >> 5;
  int nw = blockDim.x >> 5;
  v = warpSum(v);
  __syncthreads();
  if (lane==0) red[w] = v;
  __syncthreads();
  float r = (threadIdx.x < (unsigned)nw) ? red[threadIdx.x] : 0.0f;
  if (w==0) r = warpSum(r);
  if (threadIdx.x==0) red[0] = r;
  __syncthreads();
  return red[0];
}
__device__ __forceinline__ uint32_t rotl32(uint32_t x, int r){
  return __funnelshift_l(x, x, r);
}
__device__ __forceinline__ void threefry2x32(uint32_t k0, uint32_t k1,
                                             uint32_t& x0, uint32_t& x1){
  uint32_t ks0 = k0, ks1 = k1, ks2 = k0 ^ k1 ^ 0x1BD11BDAu;
  x0 += ks0; x1 += ks1;
  const int R0[4] = {13,15,26,6};
  const int R1[4] = {17,29,16,24};
  uint32_t ks[3] = {ks0, ks1, ks2};
  #pragma unroll
  for (int i=0;i<5;i++){
    #pragma unroll
    for (int j=0;j<4;j++){
      int r = (i & 1) ? R1[j] : R0[j];
      x0 += x1; x1 = rotl32(x1, r); x1 ^= x0;
    }
    x0 += ks[(i+1)%3];
    x1 += ks[(i+2)%3] + (uint32_t)(i+1);
  }
}
__device__ __forceinline__ void split_h16(float v, __half& h, __half& l){
  h = __float2half_rn(v);
  l = __float2half_rn(v - __half2float(h));
}
__device__ __forceinline__ uint32_t pack_h2(__half a, __half b){
  __half2 p(a, b);
  return *reinterpret_cast<uint32_t*>(&p);
}
__device__ __forceinline__ void ldsm4(uint32_t& r0,uint32_t& r1,uint32_t& r2,uint32_t& r3,
                                      const __half* p){
  uint32_t a = (uint32_t)__cvta_generic_to_shared(p);
  asm volatile("ldmatrix.sync.aligned.m8n8.x4.shared.b16 {%0,%1,%2,%3},[%4];"
    : "=r"(r0),"=r"(r1),"=r"(r2),"=r"(r3) : "r"(a));
}
__device__ __forceinline__ void ldsm2t(uint32_t& r0,uint32_t& r1, const __half* p){
  uint32_t a = (uint32_t)__cvta_generic_to_shared(p);
  asm volatile("ldmatrix.sync.aligned.m8n8.x2.trans.shared.b16 {%0,%1},[%2];"
    : "=r"(r0),"=r"(r1) : "r"(a));
}
__device__ __forceinline__ void mma16816h(float* c, const uint32_t* a, const uint32_t* b){
  asm volatile("mma.sync.aligned.m16n8k16.row.col.f32.f16.f16.f32 "
    "{%0,%1,%2,%3},{%4,%5,%6,%7},{%8,%9},{%0,%1,%2,%3};"
    : "+f"(c[0]),"+f"(c[1]),"+f"(c[2]),"+f"(c[3])
    : "r"(a[0]),"r"(a[1]),"r"(a[2]),"r"(a[3]), "r"(b[0]),"r"(b[1]));
}
__device__ __forceinline__ float prob_from_pos(){
  unsigned int tot = 0;
  #pragma unroll
  for (int i=0;i<BB;i++) tot += g_pos[i];
  float active = (float)tot / (float)BNN;
  return fminf(0.05f/active + 1e-8f, 1.0f);
}

// ---------------- kernels ----------------

__global__ void k_setup(const float* __restrict__ we, const int* __restrict__ itp){
  int tid = blockIdx.x*blockDim.x + threadIdx.x;
  float it = (float)itp[0];
  if (tid < NN_*EDIM){
    int d = tid & 15;
    int pair = d >> 1;
    float arg = (float)((double)(2*pair) * (-9.210340371976184/16.0));
    float div = expf(arg);
    float pe = (d & 1) ? cosf(it*div) : sinf(it*div);
    float e = we[tid] + pe;
    g_E[tid] = e;
    g_Et[d*NN_ + (tid>>4)] = e;
  }
  if (blockIdx.x==0 && threadIdx.x < 2*BB){
    if (threadIdx.x < BB) g_pos[threadIdx.x] = 0u;
    else                  g_kept[threadIdx.x-BB] = 0u;
  }
}

// Merged: [0,1024) em+bias, [1024,2048) supports, [2048,4096) prep.
__global__ void k_pre(const float* __restrict__ mp,
                      const float* __restrict__ bpr, const float* __restrict__ bpu,
                      const float* __restrict__ x, const float* __restrict__ st){
  int g = blockIdx.x;
  if (g < NN_){
    int n = g;
    __shared__ float en[EDIM];
    if (threadIdx.x < EDIM) en[threadIdx.x] = g_E[n*EDIM+threadIdx.x];
    __syncthreads();
    int m0 = threadIdx.x*4;
    float4 a = make_float4(0.f,0.f,0.f,0.f);
    #pragma unroll
    for (int d=0; d<EDIM; d++){
      float4 mv = *(const float4*)&mp[d*NN_+m0];
      float e = en[d];
      a.x += e*mv.x; a.y += e*mv.y; a.z += e*mv.z; a.w += e*mv.w;
    }
    *(float4*)&g_EM[n*NN_+m0] = a;
    int o = threadIdx.x;
    if (o < 128){
      float br = 0.f;
      #pragma unroll
      for (int d=0; d<EDIM; d++) br += en[d]*bpr[d*128+o];
      g_bias_r[n*128+o] = br;
      if (o < 64){
        float bu = 0.f;
        #pragma unroll
        for (int d=0; d<EDIM; d++) bu += en[d]*bpu[d*64+o];
        g_bias_u[n*64+o] = bu;
      }
    }
  } else if (g < 2*NN_){
    int n = g - NN_;
    __shared__ float row[NN_];
    __shared__ float red[32];
    float en[EDIM];
    #pragma unroll
    for (int d=0; d<EDIM; d++) en[d] = g_E[n*EDIM+d];
    int m0 = threadIdx.x*4;
    float4 a = make_float4(0.f,0.f,0.f,0.f);
    #pragma unroll
    for (int d=0; d<EDIM; d++){
      float4 ev = *(const float4*)&g_Et[d*NN_+m0];
      float e = en[d];
      a.x += e*ev.x; a.y += e*ev.y; a.z += e*ev.z; a.w += e*ev.w;
    }
    a.x = __expf(fmaxf(a.x,0.f)); a.y = __expf(fmaxf(a.y,0.f));
    a.z = __expf(fmaxf(a.z,0.f)); a.w = __expf(fmaxf(a.w,0.f));
    *(float4*)&row[m0] = a;
    float s = blockSum(a.x+a.y+a.z+a.w, red);
    float inv = 1.0f/s;
    float4 r4 = *(float4*)&row[m0];
    r4.x *= inv; r4.y *= inv; r4.z *= inv; r4.w *= inv;
    *(float4*)&g_supports[n*NN_+m0] = r4;
  } else {
    int q = (g - 2*NN_)*256 + threadIdx.x;
    int t4 = q*4;
    int j = t4 & 127; int bn = t4 >> 7;
    float4 v = (j < 64) ? *(const float4*)&x[(size_t)bn*64 + j]
                        : *(const float4*)&st[(size_t)bn*64 + (j-64)];
    __half h0,l0,h1,l1,h2,l2,h3,l3;
    split_h16(v.x,h0,l0); split_h16(v.y,h1,l1);
    split_h16(v.z,h2,l2); split_h16(v.w,h3,l3);
    *(uint2*)&g_xh[t4] = make_uint2(pack_h2(h0,h1), pack_h2(h2,h3));
    *(uint2*)&g_xl[t4] = make_uint2(pack_h2(l0,l1), pack_h2(l2,l3));
  }
}

// Wn[n,i2,o] = sum_d E[n,d] * Wp[d,i2,o]  (256 threads)
template<int OC>
__device__ __forceinline__ void wgen_body(const float* __restrict__ Wp, float* __restrict__ Wn,
                                          int lb, float* Esm){
  constexpr int NQ = OC/4;
  constexpr int NI = 256/NQ;
  int n0 = (lb>>4)*64;
  int i20 = (lb&15)*16;
  int t = threadIdx.x;
  int oq = t % NQ, ig = t / NQ;
  for (int q=t; q<64*EDIM; q+=256)
    Esm[q] = g_E[(n0 + (q>>4))*EDIM + (q&15)];
  __syncthreads();
  for (int ii=ig; ii<16; ii+=NI){
    int i2 = i20+ii;
    float4 w[EDIM];
    #pragma unroll
    for (int d=0; d<EDIM; d++)
      w[d] = *(const float4*)&Wp[((size_t)d*256 + i2)*OC + oq*4];
    #pragma unroll 4
    for (int nn=0; nn<64; nn++){
      float4 a = make_float4(0.f,0.f,0.f,0.f);
      #pragma unroll
      for (int d=0; d<EDIM; d++){
        float e = Esm[nn*EDIM + d];
        a.x += e*w[d].x; a.y += e*w[d].y; a.z += e*w[d].z; a.w += e*w[d].w;
      }
      *(float4*)&Wn[((size_t)(n0+nn)*256 + i2)*OC + oq*4] = a;
    }
  }
}

// Combined: every 5th block wgen (512), rest supmask (2048), 8 rows/block register-blocked.
__global__ void __launch_bounds__(256) k_sup_wgen(
    const float* __restrict__ T, const float* __restrict__ TP,
    const float* __restrict__ gamma, const float* __restrict__ beta,
    float* __restrict__ out_mask,
    const float* __restrict__ Wpr, const float* __restrict__ Wpu){
  __shared__ float Esm[64*EDIM];
  __shared__ float red[8][8];
  __shared__ float inv8[8];
  int bid = blockIdx.x;
  if (bid % 5 == 0){
    int lb = bid/5;
    if (lb < 256) wgen_body<128>(Wpr, g_Wn_r, lb, Esm);
    else          wgen_body<64>(Wpu, g_Wn_u, lb-256, Esm);
    return;
  }
  int id = bid - bid/5 - 1;
  int b = id >> 7;
  int n0 = (id & 127)*8;
  extern __shared__ float sm[];
  float* Tsm  = sm;
  float* TPsm = sm + WINDOW*NN_;
  int tid = threadIdx.x, lane = tid & 31, wrp = tid >> 5;
  for (int t=tid; t<WINDOW*NN_; t+=256){
    Tsm[t]  = T[(size_t)b*WINDOW*NN_ + t];
    TPsm[t] = TP[t];
  }
  __syncthreads();
  int m0 = tid*4;
  float tg[8][4];
  #pragma unroll
  for (int r=0;r<8;r++){ tg[r][0]=0.f; tg[r][1]=0.f; tg[r][2]=0.f; tg[r][3]=0.f; }
  #pragma unroll
  for (int w=0; w<WINDOW; w++){
    float4 tw = *(float4*)&Tsm[w*NN_+m0];
    #pragma unroll
    for (int r=0;r<8;r++){
      float tvs = Tsm[w*NN_ + n0 + r];
      tg[r][0] += tvs*tw.x; tg[r][1] += tvs*tw.y;
      tg[r][2] += tvs*tw.z; tg[r][3] += tvs*tw.w;
    }
  }
  float psum[8];
  #pragma unroll
  for (int r=0;r<8;r++){
    tg[r][0] = __expf(fmaxf(tg[r][0],0.f));
    tg[r][1] = __expf(fmaxf(tg[r][1],0.f));
    tg[r][2] = __expf(fmaxf(tg[r][2],0.f));
    tg[r][3] = __expf(fmaxf(tg[r][3],0.f));
    psum[r] = (tg[r][0]+tg[r][1])+(tg[r][2]+tg[r][3]);
  }
  #pragma unroll
  for (int r=0;r<8;r++) psum[r] = warpSum(psum[r]);
  if (lane==0){
    #pragma unroll
    for (int r=0;r<8;r++) red[r][wrp] = psum[r];
  }
  __syncthreads();
  if (tid < 8){
    float s = 0.f;
    #pragma unroll
    for (int k=0;k<8;k++) s += red[tid][k];
    inv8[tid] = 1.0f/s;
  }
  __syncthreads();
  float rm[8][4];
  #pragma unroll
  for (int r=0;r<8;r++){
    float4 t = *(const float4*)&g_EM[(size_t)(n0+r)*NN_ + m0];
    rm[r][0]=t.x; rm[r][1]=t.y; rm[r][2]=t.z; rm[r][3]=t.w;
  }
  #pragma unroll
  for (int w=0; w<WINDOW; w++){
    float4 tp = *(float4*)&TPsm[w*NN_+m0];
    #pragma unroll
    for (int r=0;r<8;r++){
      float tvs = Tsm[w*NN_ + n0 + r];
      rm[r][0] += tvs*tp.x; rm[r][1] += tvs*tp.y;
      rm[r][2] += tvs*tp.z; rm[r][3] += tvs*tp.w;
    }
  }
  const float bni = 1.0f/sqrtf(1.0f + 1e-5f);
  unsigned int cnt = 0;
  #pragma unroll
  for (int r=0;r<8;r++){
    int n = n0 + r;
    float sc = bni*gamma[n], bt = beta[n];
    float v0 = rm[r][0]*sc + bt, v1 = rm[r][1]*sc + bt;
    float v2 = rm[r][2]*sc + bt, v3 = rm[r][3]*sc + bt;
    uint32_t nib = (v0 > MASK_THR ? 1u:0u) | (v1 > MASK_THR ? 2u:0u)
                 | (v2 > MASK_THR ? 4u:0u) | (v3 > MASK_THR ? 8u:0u);
    float4 mk = make_float4(nib&1u?1.f:0.f, nib&2u?1.f:0.f, nib&4u?1.f:0.f, nib&8u?1.f:0.f);
    size_t idx = (size_t)b*NNSQ + (size_t)n*NN_ + m0;
    *(float4*)&out_mask[idx] = mk;
    float inv = inv8[r];
    float4 sp = *(const float4*)&g_supports[n*NN_+m0];
    sp.x = (sp.x + tg[r][0]*inv)*0.5f*mk.x;
    sp.y = (sp.y + tg[r][1]*inv)*0.5f*mk.y;
    sp.z = (sp.z + tg[r][2]*inv)*0.5f*mk.z;
    sp.w = (sp.w + tg[r][3]*inv)*0.5f*mk.w;
    *(uint2*)&g_sh[idx] = make_uint2(
        pack_h2(__float2half_rn(sp.x), __float2half_rn(sp.y)),
        pack_h2(__float2half_rn(sp.z), __float2half_rn(sp.w)));
    cnt += __popc(nib);
    uint32_t v = nib << ((lane&7)*4);
    v |= __shfl_xor_sync(0xffffffffu, v, 1);
    v |= __shfl_xor_sync(0xffffffffu, v, 2);
    v |= __shfl_xor_sync(0xffffffffu, v, 4);
    if ((lane&7)==0) g_bits[idx>>5] = v;
  }
  float fc = blockSum((float)cnt, (float*)red);
  if (tid==0) atomicAdd(&g_pos[b], (unsigned int)(fc + 0.5f));
}

// kept-count: standalone, low-reg, overlapped on a forked stream.
__global__ void __launch_bounds__(256) k_kept(){
  __shared__ unsigned int cnt[BB];
  if (threadIdx.x < BB) cnt[threadIdx.x] = 0u;
  __syncthreads();
  float prob = prob_from_pos();
  int lane = threadIdx.x & 31;
  unsigned int base = blockIdx.x*1024u + threadIdx.x;
  #pragma unroll
  for (int k=0;k<4;k++){
    unsigned int t = base + (unsigned)k*256u;
    uint32_t x0 = t, x1 = t + (uint32_t)HALF_BNN;
    threefry2x32(0u, 42u, x0, x1);
    float u0 = __uint_as_float((x0>>9) | 0x3f800000u) - 1.0f;
    float u1 = __uint_as_float((x1>>9) | 0x3f800000u) - 1.0f;
    uint32_t w0 = g_bits[t>>5];
    uint32_t w1 = g_bits[(t + HALF_BNN)>>5];
    int b0 = (int)(t >> 20);
    bool keep0 = ((w0>>lane)&1u) && !(u0 < prob);
    bool keep1 = ((w1>>lane)&1u) && !(u1 < prob);
    unsigned bal0 = __ballot_sync(0xffffffffu, keep0);
    unsigned bal1 = __ballot_sync(0xffffffffu, keep1);
    if (lane==0){
      if (bal0) atomicAdd(&cnt[b0],   __popc(bal0));
      if (bal1) atomicAdd(&cnt[b0+8], __popc(bal1));
    }
  }
  __syncthreads();
  if (threadIdx.x < BB && cnt[threadIdx.x]) atomicAdd(&g_kept[threadIdx.x], cnt[threadIdx.x]);
}

// mma<128>: 512 threads, A=fp16 sup (single), B=fp16 hi/lo; double-buffered + prefetch.
__global__ void __launch_bounds__(512) k_mma128(const __half* __restrict__ Bh,
                                                const __half* __restrict__ Bl,
                                                float* __restrict__ C){
  constexpr int NO = 128;
  constexpr int BST = NO+8;
  constexpr int APITCH = 40;
  __shared__ __half Ash[2][128*APITCH];
  __shared__ __half Bsh[2][32*BST], Bsl[2][32*BST];
  int b = blockIdx.x >> 3;
  int m0 = (blockIdx.x & 7)*128;
  int w = threadIdx.x>>5, lane = threadIdx.x&31;
  int wm = (w>>1)*16;
  int wn = (w&1)*64;
  float acc[8][4];
  #pragma unroll
  for (int j=0;j<8;j++){ acc[j][0]=0.f; acc[j][1]=0.f; acc[j][2]=0.f; acc[j][3]=0.f; }
  const __half* Ahb = g_sh + (size_t)b*NNSQ;
  const __half* Bhb = Bh + (size_t)b*NN_*NO;
  const __half* Blb = Bl + (size_t)b*NN_*NO;
  int ar = threadIdx.x>>2, ac = threadIdx.x&3;
  int brr = threadIdx.x>>4, bc = threadIdx.x&15;
  uint4 pAh, pBh, pBl;
  auto ldtile = [&](int k0){
    pAh = *(const uint4*)&Ahb[(size_t)(m0+ar)*NN_ + k0 + ac*8];
    pBh = *(const uint4*)&Bhb[(size_t)(k0+brr)*NO + bc*8];
    pBl = *(const uint4*)&Blb[(size_t)(k0+brr)*NO + bc*8];
  };
  auto sttile = [&](int buf){
    *(uint4*)&Ash[buf][ar*APITCH + ac*8] = pAh;
    *(uint4*)&Bsh[buf][brr*BST + bc*8] = pBh;
    *(uint4*)&Bsl[buf][brr*BST + bc*8] = pBl;
  };
  ldtile(0);
  sttile(0);
  __syncthreads();
  #pragma unroll 1
  for (int t=0;t<32;t++){
    if (t+1 < 32) ldtile((t+1)*32);
    int buf = t & 1;
    #pragma unroll
    for (int kk=0; kk<2; kk++){
      uint32_t ah[4];
      int aoff = (wm + (lane&15))*APITCH + kk*16 + (lane>>4)*8;
      ldsm4(ah[0],ah[1],ah[2],ah[3], &Ash[buf][aoff]);
      #pragma unroll
      for (int j=0;j<8;j++){
        uint32_t bh[2], bl[2];
        int boff = (kk*16 + (lane&15))*BST + wn + j*8;
        ldsm2t(bh[0],bh[1], &Bsh[buf][boff]);
        ldsm2t(bl[0],bl[1], &Bsl[buf][boff]);
        mma16816h(acc[j], ah, bh);
        mma16816h(acc[j], ah, bl);
      }
    }
    if (t+1 < 32){
      __syncthreads();
      sttile((t+1)&1);
      __syncthreads();
    }
  }
  #pragma unroll
  for (int j=0;j<8;j++){
    int r0 = m0 + wm + (lane>>2);
    int c0 = wn + j*8 + (lane&3)*2;
    float* Cp = C + ((size_t)b*NN_ + r0)*NO + c0;
    Cp[0] = acc[j][0]; Cp[1] = acc[j][1];
    Cp[(size_t)8*NO] = acc[j][2]; Cp[(size_t)8*NO+1] = acc[j][3];
  }
}

// mma<64>: 256 threads, A=fp16 single, B=fp16 hi/lo.
__global__ void k_mma64(const __half* __restrict__ Bh,
                        const __half* __restrict__ Bl,
                        float* __restrict__ C){
  constexpr int NO = 64;
  constexpr int BST = NO+8;
  __shared__ __half Ash[128*40];
  __shared__ __half Bsh[32*BST], Bsl[32*BST];
  int b = blockIdx.y;
  int m0 = blockIdx.x*128;
  int w = threadIdx.x>>5, lane = threadIdx.x&31;
  int wm = w*16;
  float acc[8][4];
  #pragma unroll
  for (int j=0;j<8;j++){ acc[j][0]=0.f; acc[j][1]=0.f; acc[j][2]=0.f; acc[j][3]=0.f; }
  const __half* Ahb = g_sh + (size_t)b*NNSQ;
  const __half* Bhb = Bh + (size_t)b*NN_*NO;
  const __half* Blb = Bl + (size_t)b*NN_*NO;
  for (int k0=0;k0<NN_;k0+=32){
    #pragma unroll
    for (int i = threadIdx.x; i<512; i+=256){
      int r = i>>2, c = i&3;
      *(uint4*)&Ash[r*40 + c*8] = *(const uint4*)&Ahb[(size_t)(m0+r)*NN_ + k0 + c*8];
    }
    {
      int i = threadIdx.x;
      int r = i>>3, c = i&7;
      *(uint4*)&Bsh[r*BST + c*8] = *(const uint4*)&Bhb[(size_t)(k0+r)*NO + c*8];
      *(uint4*)&Bsl[r*BST + c*8] = *(const uint4*)&Blb[(size_t)(k0+r)*NO + c*8];
    }
    __syncthreads();
    #pragma unroll
    for (int kk=0; kk<2; kk++){
      uint32_t ah[4];
      int aoff = (wm + (lane&15))*40 + kk*16 + (lane>>4)*8;
      ldsm4(ah[0],ah[1],ah[2],ah[3], &Ash[aoff]);
      #pragma unroll
      for (int j=0;j<8;j++){
        uint32_t bh[2], bl[2];
        int boff = (kk*16 + (lane&15))*BST + j*8;
        ldsm2t(bh[0],bh[1], &Bsh[boff]);
        ldsm2t(bl[0],bl[1], &Bsl[boff]);
        mma16816h(acc[j], ah, bh);
        mma16816h(acc[j], ah, bl);
      }
    }
    __syncthreads();
  }
  #pragma unroll
  for (int j=0;j<8;j++){
    int r0 = m0 + wm + (lane>>2);
    int c0 = j*8 + (lane&3)*2;
    float* Cp = C + ((size_t)b*NN_ + r0)*NO + c0;
    Cp[0] = acc[j][0]; Cp[1] = acc[j][1];
    Cp[(size_t)8*NO] = acc[j][2]; Cp[(size_t)8*NO+1] = acc[j][3];
  }
}

// r-gate: 4b x 4o register tile per thread.
__global__ void __launch_bounds__(128) k_gate_r(const float* __restrict__ x,
                                                const float* __restrict__ st){
  int n = blockIdx.x;
  __shared__ float Xg[256*20];
  int t = threadIdx.x;
  for (int q=t; q<4096; q+=128){
    int b = q>>8, i = q&255;
    float v;
    if (i < 64)       v = x[((size_t)b*NN_+n)*64 + i];
    else if (i < 128) v = st[((size_t)b*NN_+n)*64 + (i-64)];
    else              v = g_xb[((size_t)b*NN_+n)*128 + (i-128)];
    Xg[i*20 + b] = v;
  }
  __syncthreads();
  int og = t>>2, bg = t&3;
  int o0 = og*4, b0 = bg*4;
  float acc[4][4] = {};
  const float* W = g_Wn_r + (size_t)n*256*128 + o0;
  #pragma unroll 2
  for (int i=0;i<256;i++){
    float4 xv = *(float4*)&Xg[i*20 + b0];
    float4 wv = *(const float4*)&W[(size_t)i*128];
    float xs[4] = {xv.x,xv.y,xv.z,xv.w};
    float ws[4] = {wv.x,wv.y,wv.z,wv.w};
    #pragma unroll
    for (int bi=0;bi<4;bi++)
      #pragma unroll
      for (int oi=0;oi<4;oi++)
        acc[bi][oi] += xs[bi]*ws[oi];
  }
  float4 bias = *(const float4*)&g_bias_r[n*128 + o0];
  float bs[4] = {bias.x,bias.y,bias.z,bias.w};
  #pragma unroll
  for (int bi=0;bi<4;bi++){
    int b = b0+bi;
    size_t idx = ((size_t)b*NN_+n)*64;
    #pragma unroll
    for (int oi=0;oi<4;oi++){
      int o = o0+oi;
      float g = 1.0f/(1.0f+__expf(-(acc[bi][oi]+bs[oi])));
      if (o < 64){
        float zsv = g * st[idx + o];
        g_zs[idx + o] = zsv;
        __half h, l; split_h16(zsv, h, l);
        g_zh[idx + o] = h; g_zl[idx + o] = l;
      } else {
        g_rb[idx + (o-64)] = g;
      }
    }
  }
}

// u-gate + GRU output; block 1024 computes mask_loss.
__global__ void __launch_bounds__(128) k_gate_u(const float* __restrict__ x,
                                                const float* __restrict__ st,
                                                float* __restrict__ out_h,
                                                float* __restrict__ out_loss){
  if (blockIdx.x == NN_){
    if (threadIdx.x < BB){
      unsigned int tot = 0;
      #pragma unroll
      for (int i=0;i<BB;i++) tot += g_pos[i];
      float active = (float)tot / (float)BNN;
      float addend = fmaxf(0.05f/active - 1.0f, 0.0f);
      int b = threadIdx.x;
      out_loss[b] = (float)g_kept[b] / ((float)g_pos[b] + 1e-8f) + addend;
    }
    return;
  }
  int n = blockIdx.x;
  __shared__ float Xg[256*20];
  int t = threadIdx.x;
  for (int q=t; q<4096; q+=128){
    int b = q>>8, i = q&255;
    float v;
    if (i < 64)       v = x[((size_t)b*NN_+n)*64 + i];
    else if (i < 128) v = g_zs[((size_t)b*NN_+n)*64 + (i-64)];
    else if (i < 192) v = g_xb[((size_t)b*NN_+n)*128 + (i-128)];
    else              v = g_c2[((size_t)b*NN_+n)*64 + (i-192)];
    Xg[i*20 + b] = v;
  }
  __syncthreads();
  int og = t>>3, bg = t&7;
  int o0 = og*4, b0 = bg*2;
  float acc[2][4] = {};
  const float* W = g_Wn_u + (size_t)n*256*64 + o0;
  #pragma unroll 2
  for (int i=0;i<256;i++){
    float2 xv = *(float2*)&Xg[i*20 + b0];
    float4 wv = *(const float4*)&W[(size_t)i*64];
    float xs[2] = {xv.x,xv.y};
    float ws[4] = {wv.x,wv.y,wv.z,wv.w};
    #pragma unroll
    for (int bi=0;bi<2;bi++)
      #pragma unroll
      for (int oi=0;oi<4;oi++)
        acc[bi][oi] += xs[bi]*ws[oi];
  }
  float4 bias = *(const float4*)&g_bias_u[n*64 + o0];
  float bs[4] = {bias.x,bias.y,bias.z,bias.w};
  #pragma unroll
  for (int bi=0;bi<2;bi++){
    int b = b0+bi;
    size_t idx = ((size_t)b*NN_+n)*64;
    #pragma unroll
    for (int oi=0;oi<4;oi++){
      int o = o0+oi;
      float hc = tanhf(acc[bi][oi]+bs[oi]);
      float r = g_rb[idx + o];
      float sv = st[idx + o];
      out_h[idx + o] = r*sv + (1.0f-r)*hc;
    }
  }
}

// ---------------- launch ----------------
extern "C" void kernel_launch(void* const* d_in, const int* in_sizes, int n_in,
                              void* d_out, int out_size){
  const float* x    = (const float*)d_in[0];
  const float* st   = (const float*)d_in[1];
  const float* we   = (const float*)d_in[2];
  const float* T    = (const float*)d_in[3];
  const float* Wpr  = (const float*)d_in[4];
  const float* bpr  = (const float*)d_in[5];
  const float* Wpu  = (const float*)d_in[6];
  const float* bpu  = (const float*)d_in[7];
  const float* mp   = (const float*)d_in[8];
  const float* tp   = (const float*)d_in[9];
  const float* gmm  = (const float*)d_in[10];
  const float* bta  = (const float*)d_in[11];
  const int*   itp  = (const int*)d_in[12];
  float* out = (float*)d_out;
  float* out_mask = out + OFF_MASK;

  static __half *xh_p=nullptr, *xl_p=nullptr, *zh_p=nullptr, *zl_p=nullptr;
  static float *xb_p=nullptr, *c2_p=nullptr;
  static cudaStream_t s2 = nullptr;
  static cudaEvent_t evFork = nullptr, evJoin = nullptr;
  if (!xh_p){
    cudaGetSymbolAddress((void**)&xh_p, g_xh);
    cudaGetSymbolAddress((void**)&xl_p, g_xl);
    cudaGetSymbolAddress((void**)&zh_p, g_zh);
    cudaGetSymbolAddress((void**)&zl_p, g_zl);
    cudaGetSymbolAddress((void**)&xb_p, g_xb);
    cudaGetSymbolAddress((void**)&c2_p, g_c2);
    size_t smem_sup = (size_t)(2*WINDOW*NN_)*sizeof(float);
    cudaFuncSetAttribute(k_sup_wgen, cudaFuncAttributeMaxDynamicSharedMemorySize, (int)smem_sup);
    cudaStreamCreateWithFlags(&s2, cudaStreamNonBlocking);
    cudaEventCreateWithFlags(&evFork, cudaEventDisableTiming);
    cudaEventCreateWithFlags(&evJoin, cudaEventDisableTiming);
  }
  size_t smem_sup = (size_t)(2*WINDOW*NN_)*sizeof(float);

  k_setup<<<64,256>>>(we, itp);
  k_pre<<<4096,256>>>(mp, bpr, bpu, x, st);
  k_sup_wgen<<<2560,256,smem_sup>>>(T, tp, gmm, bta, out_mask, Wpr, Wpu);
  cudaEventRecord(evFork, 0);
  cudaStreamWaitEvent(s2, evFork, 0);
  k_kept<<<8192,256,0,s2>>>();
  k_mma128<<<128,512>>>(xh_p, xl_p, xb_p);
  k_gate_r<<<NN_,128>>>(x, st);
  k_mma64<<<dim3(8,16),256>>>(zh_p, zl_p, c2_p);
  cudaEventRecord(evJoin, s2);
  cudaStreamWaitEvent(0, evJoin, 0);
  k_gate_u<<<NN_+1,128>>>(x, st, out, out + OFF_LOSS);
}

// round 10
// speedup vs baseline: 2.3977x; 1.0997x over previous
#include <cuda_runtime.h>
#include <cuda_bf16.h>
#include <cuda_fp16.h>
#include <cstdint>
#include <math.h>

#define BB 16
#define NN_ 1024
#define EDIM 16
#define WINDOW 12
#define NNSQ (NN_*NN_)
#define BNN (BB*NNSQ)
#define HALF_BNN (BNN/2)
#define OFF_MASK (BB*NN_*64)
#define OFF_LOSS (OFF_MASK + BNN)
#define MASK_THR (-2.66352776f)   /* ln(1.4) - 3 */

// ---------------- scratch ----------------
__device__ float g_E[NN_*EDIM];
__device__ float g_Et[EDIM*NN_];
__device__ float g_EM[NNSQ];
__device__ float g_supports[NNSQ];
__device__ __half g_sh[(size_t)BNN];                 // sup fp16 (single)
__device__ uint32_t g_bits[BNN/32];
__device__ __half g_xh[(size_t)BB*NN_*128];
__device__ __half g_xl[(size_t)BB*NN_*128];
__device__ __half g_zh[(size_t)BB*NN_*64];
__device__ __half g_zl[(size_t)BB*NN_*64];
__device__ float g_Wn_r[(size_t)NN_*256*128];
__device__ float g_Wn_u[(size_t)NN_*256*64];
__device__ float g_bias_r[NN_*128];
__device__ float g_bias_u[NN_*64];
__device__ float g_xb[(size_t)BB*NN_*128];
__device__ float g_zs[(size_t)BB*NN_*64];
__device__ float g_rb[(size_t)BB*NN_*64];
__device__ float g_c2[(size_t)BB*NN_*64];
__device__ unsigned int g_pos[BB];
__device__ unsigned int g_kept[BB];

// ---------------- helpers ----------------
__device__ __forceinline__ float warpSum(float v){
  #pragma unroll
  for (int o=16;o;o>>=1) v += __shfl_xor_sync(0xffffffffu, v, o);
  return v;
}
__device__ __forceinline__ float blockSum(float v, float* red){
  int lane = threadIdx.x & 31, w = threadIdx.x >> 5;
  int nw = blockDim.x >> 5;
  v = warpSum(v);
  __syncthreads();
  if (lane==0) red[w] = v;
  __syncthreads();
  float r = (threadIdx.x < (unsigned)nw) ? red[threadIdx.x] : 0.0f;
  if (w==0) r = warpSum(r);
  if (threadIdx.x==0) red[0] = r;
  __syncthreads();
  return red[0];
}
__device__ __forceinline__ uint32_t rotl32(uint32_t x, int r){
  return __funnelshift_l(x, x, r);
}
__device__ __forceinline__ void threefry2x32(uint32_t k0, uint32_t k1,
                                             uint32_t& x0, uint32_t& x1){
  uint32_t ks0 = k0, ks1 = k1, ks2 = k0 ^ k1 ^ 0x1BD11BDAu;
  x0 += ks0; x1 += ks1;
  const int R0[4] = {13,15,26,6};
  const int R1[4] = {17,29,16,24};
  uint32_t ks[3] = {ks0, ks1, ks2};
  #pragma unroll
  for (int i=0;i<5;i++){
    #pragma unroll
    for (int j=0;j<4;j++){
      int r = (i & 1) ? R1[j] : R0[j];
      x0 += x1; x1 = rotl32(x1, r); x1 ^= x0;
    }
    x0 += ks[(i+1)%3];
    x1 += ks[(i+2)%3] + (uint32_t)(i+1);
  }
}
__device__ __forceinline__ void split_h16(float v, __half& h, __half& l){
  h = __float2half_rn(v);
  l = __float2half_rn(v - __half2float(h));
}
__device__ __forceinline__ uint32_t pack_h2(__half a, __half b){
  __half2 p(a, b);
  return *reinterpret_cast<uint32_t*>(&p);
}
__device__ __forceinline__ void ldsm4(uint32_t& r0,uint32_t& r1,uint32_t& r2,uint32_t& r3,
                                      const __half* p){
  uint32_t a = (uint32_t)__cvta_generic_to_shared(p);
  asm volatile("ldmatrix.sync.aligned.m8n8.x4.shared.b16 {%0,%1,%2,%3},[%4];"
    : "=r"(r0),"=r"(r1),"=r"(r2),"=r"(r3) : "r"(a));
}
__device__ __forceinline__ void ldsm2t(uint32_t& r0,uint32_t& r1, const __half* p){
  uint32_t a = (uint32_t)__cvta_generic_to_shared(p);
  asm volatile("ldmatrix.sync.aligned.m8n8.x2.trans.shared.b16 {%0,%1},[%2];"
    : "=r"(r0),"=r"(r1) : "r"(a));
}
__device__ __forceinline__ void mma16816h(float* c, const uint32_t* a, const uint32_t* b){
  asm volatile("mma.sync.aligned.m16n8k16.row.col.f32.f16.f16.f32 "
    "{%0,%1,%2,%3},{%4,%5,%6,%7},{%8,%9},{%0,%1,%2,%3};"
    : "+f"(c[0]),"+f"(c[1]),"+f"(c[2]),"+f"(c[3])
    : "r"(a[0]),"r"(a[1]),"r"(a[2]),"r"(a[3]), "r"(b[0]),"r"(b[1]));
}
__device__ __forceinline__ float prob_from_pos(){
  unsigned int tot = 0;
  #pragma unroll
  for (int i=0;i<BB;i++) tot += g_pos[i];
  float active = (float)tot / (float)BNN;
  return fminf(0.05f/active + 1e-8f, 1.0f);
}

// ---------------- kernels ----------------

__global__ void k_setup(const float* __restrict__ we, const int* __restrict__ itp){
  int tid = blockIdx.x*blockDim.x + threadIdx.x;
  float it = (float)itp[0];
  if (tid < NN_*EDIM){
    int d = tid & 15;
    int pair = d >> 1;
    float arg = (float)((double)(2*pair) * (-9.210340371976184/16.0));
    float div = expf(arg);
    float pe = (d & 1) ? cosf(it*div) : sinf(it*div);
    float e = we[tid] + pe;
    g_E[tid] = e;
    g_Et[d*NN_ + (tid>>4)] = e;
  }
  if (blockIdx.x==0 && threadIdx.x < 2*BB){
    if (threadIdx.x < BB) g_pos[threadIdx.x] = 0u;
    else                  g_kept[threadIdx.x-BB] = 0u;
  }
}

// Merged: [0,1024) em+bias, [1024,2048) supports, [2048,4096) prep.
__global__ void k_pre(const float* __restrict__ mp,
                      const float* __restrict__ bpr, const float* __restrict__ bpu,
                      const float* __restrict__ x, const float* __restrict__ st){
  int g = blockIdx.x;
  if (g < NN_){
    int n = g;
    __shared__ float en[EDIM];
    if (threadIdx.x < EDIM) en[threadIdx.x] = g_E[n*EDIM+threadIdx.x];
    __syncthreads();
    int m0 = threadIdx.x*4;
    float4 a = make_float4(0.f,0.f,0.f,0.f);
    #pragma unroll
    for (int d=0; d<EDIM; d++){
      float4 mv = *(const float4*)&mp[d*NN_+m0];
      float e = en[d];
      a.x += e*mv.x; a.y += e*mv.y; a.z += e*mv.z; a.w += e*mv.w;
    }
    *(float4*)&g_EM[n*NN_+m0] = a;
    int o = threadIdx.x;
    if (o < 128){
      float br = 0.f;
      #pragma unroll
      for (int d=0; d<EDIM; d++) br += en[d]*bpr[d*128+o];
      g_bias_r[n*128+o] = br;
      if (o < 64){
        float bu = 0.f;
        #pragma unroll
        for (int d=0; d<EDIM; d++) bu += en[d]*bpu[d*64+o];
        g_bias_u[n*64+o] = bu;
      }
    }
  } else if (g < 2*NN_){
    int n = g - NN_;
    __shared__ float row[NN_];
    __shared__ float red[32];
    float en[EDIM];
    #pragma unroll
    for (int d=0; d<EDIM; d++) en[d] = g_E[n*EDIM+d];
    int m0 = threadIdx.x*4;
    float4 a = make_float4(0.f,0.f,0.f,0.f);
    #pragma unroll
    for (int d=0; d<EDIM; d++){
      float4 ev = *(const float4*)&g_Et[d*NN_+m0];
      float e = en[d];
      a.x += e*ev.x; a.y += e*ev.y; a.z += e*ev.z; a.w += e*ev.w;
    }
    a.x = __expf(fmaxf(a.x,0.f)); a.y = __expf(fmaxf(a.y,0.f));
    a.z = __expf(fmaxf(a.z,0.f)); a.w = __expf(fmaxf(a.w,0.f));
    *(float4*)&row[m0] = a;
    float s = blockSum(a.x+a.y+a.z+a.w, red);
    float inv = 1.0f/s;
    float4 r4 = *(float4*)&row[m0];
    r4.x *= inv; r4.y *= inv; r4.z *= inv; r4.w *= inv;
    *(float4*)&g_supports[n*NN_+m0] = r4;
  } else {
    int q = (g - 2*NN_)*256 + threadIdx.x;
    int t4 = q*4;
    int j = t4 & 127; int bn = t4 >> 7;
    float4 v = (j < 64) ? *(const float4*)&x[(size_t)bn*64 + j]
                        : *(const float4*)&st[(size_t)bn*64 + (j-64)];
    __half h0,l0,h1,l1,h2,l2,h3,l3;
    split_h16(v.x,h0,l0); split_h16(v.y,h1,l1);
    split_h16(v.z,h2,l2); split_h16(v.w,h3,l3);
    *(uint2*)&g_xh[t4] = make_uint2(pack_h2(h0,h1), pack_h2(h2,h3));
    *(uint2*)&g_xl[t4] = make_uint2(pack_h2(l0,l1), pack_h2(l2,l3));
  }
}

// Wn[n,i2,o] = sum_d E[n,d] * Wp[d,i2,o]  (256 threads)
template<int OC>
__device__ __forceinline__ void wgen_body(const float* __restrict__ Wp, float* __restrict__ Wn,
                                          int lb, float* Esm){
  constexpr int NQ = OC/4;
  constexpr int NI = 256/NQ;
  int n0 = (lb>>4)*64;
  int i20 = (lb&15)*16;
  int t = threadIdx.x;
  int oq = t % NQ, ig = t / NQ;
  for (int q=t; q<64*EDIM; q+=256)
    Esm[q] = g_E[(n0 + (q>>4))*EDIM + (q&15)];
  __syncthreads();
  for (int ii=ig; ii<16; ii+=NI){
    int i2 = i20+ii;
    float4 w[EDIM];
    #pragma unroll
    for (int d=0; d<EDIM; d++)
      w[d] = *(const float4*)&Wp[((size_t)d*256 + i2)*OC + oq*4];
    #pragma unroll 4
    for (int nn=0; nn<64; nn++){
      float4 a = make_float4(0.f,0.f,0.f,0.f);
      #pragma unroll
      for (int d=0; d<EDIM; d++){
        float e = Esm[nn*EDIM + d];
        a.x += e*w[d].x; a.y += e*w[d].y; a.z += e*w[d].z; a.w += e*w[d].w;
      }
      *(float4*)&Wn[((size_t)(n0+nn)*256 + i2)*OC + oq*4] = a;
    }
  }
}

// Combined: every 3rd block wgen (512), rest supmask (1024 blocks x 16 rows, 2 passes).
// Tsm in smem (48 KB); TP read via __ldg (shared across all blocks in L1/L2).
__global__ void __launch_bounds__(256) k_sup_wgen(
    const float* __restrict__ T, const float* __restrict__ TP,
    const float* __restrict__ gamma, const float* __restrict__ beta,
    float* __restrict__ out_mask,
    const float* __restrict__ Wpr, const float* __restrict__ Wpu){
  __shared__ float Esm[64*EDIM];
  __shared__ float red[8][8];
  __shared__ float inv8[8];
  int bid = blockIdx.x;
  if (bid % 3 == 0){
    int lb = bid/3;
    if (lb < 256) wgen_body<128>(Wpr, g_Wn_r, lb, Esm);
    else          wgen_body<64>(Wpu, g_Wn_u, lb-256, Esm);
    return;
  }
  int id = bid - bid/3 - 1;                 // [0,1024)
  int b = id >> 6;
  int n0base = (id & 63)*16;
  extern __shared__ float sm[];
  float* Tsm = sm;                          // 12*1024 floats = 48 KB
  int tid = threadIdx.x, lane = tid & 31, wrp = tid >> 5;
  {
    const float4* Tg = (const float4*)(T + (size_t)b*WINDOW*NN_);
    float4* T4 = (float4*)Tsm;
    #pragma unroll
    for (int i=0;i<12;i++) T4[tid + i*256] = Tg[tid + i*256];
  }
  __syncthreads();
  int m0 = tid*4;
  const float bni = 1.0f/sqrtf(1.0f + 1e-5f);
  unsigned int cnt = 0;
  #pragma unroll 1
  for (int half=0; half<2; half++){
    int n0 = n0base + half*8;
    // Phase A: time-gram for 8 rows
    float tg[8][4];
    #pragma unroll
    for (int r=0;r<8;r++){ tg[r][0]=0.f; tg[r][1]=0.f; tg[r][2]=0.f; tg[r][3]=0.f; }
    #pragma unroll
    for (int w=0; w<WINDOW; w++){
      float4 tw = *(float4*)&Tsm[w*NN_+m0];
      #pragma unroll
      for (int r=0;r<8;r++){
        float tvs = Tsm[w*NN_ + n0 + r];
        tg[r][0] += tvs*tw.x; tg[r][1] += tvs*tw.y;
        tg[r][2] += tvs*tw.z; tg[r][3] += tvs*tw.w;
      }
    }
    float psum[8];
    #pragma unroll
    for (int r=0;r<8;r++){
      tg[r][0] = __expf(fmaxf(tg[r][0],0.f));
      tg[r][1] = __expf(fmaxf(tg[r][1],0.f));
      tg[r][2] = __expf(fmaxf(tg[r][2],0.f));
      tg[r][3] = __expf(fmaxf(tg[r][3],0.f));
      psum[r] = (tg[r][0]+tg[r][1])+(tg[r][2]+tg[r][3]);
    }
    #pragma unroll
    for (int r=0;r<8;r++) psum[r] = warpSum(psum[r]);
    __syncthreads();                         // red reuse across halves
    if (lane==0){
      #pragma unroll
      for (int r=0;r<8;r++) red[r][wrp] = psum[r];
    }
    __syncthreads();
    if (tid < 8){
      float s = 0.f;
      #pragma unroll
      for (int k=0;k<8;k++) s += red[tid][k];
      inv8[tid] = 1.0f/s;
    }
    __syncthreads();
    // Phase B: raw mask (TP via global/L1)
    float rm[8][4];
    #pragma unroll
    for (int r=0;r<8;r++){
      float4 t = *(const float4*)&g_EM[(size_t)(n0+r)*NN_ + m0];
      rm[r][0]=t.x; rm[r][1]=t.y; rm[r][2]=t.z; rm[r][3]=t.w;
    }
    #pragma unroll
    for (int w=0; w<WINDOW; w++){
      float4 tp = __ldg((const float4*)&TP[w*NN_+m0]);
      #pragma unroll
      for (int r=0;r<8;r++){
        float tvs = Tsm[w*NN_ + n0 + r];
        rm[r][0] += tvs*tp.x; rm[r][1] += tvs*tp.y;
        rm[r][2] += tvs*tp.z; rm[r][3] += tvs*tp.w;
      }
    }
    #pragma unroll
    for (int r=0;r<8;r++){
      int n = n0 + r;
      float sc = bni*gamma[n], bt = beta[n];
      float v0 = rm[r][0]*sc + bt, v1 = rm[r][1]*sc + bt;
      float v2 = rm[r][2]*sc + bt, v3 = rm[r][3]*sc + bt;
      uint32_t nib = (v0 > MASK_THR ? 1u:0u) | (v1 > MASK_THR ? 2u:0u)
                   | (v2 > MASK_THR ? 4u:0u) | (v3 > MASK_THR ? 8u:0u);
      float4 mk = make_float4(nib&1u?1.f:0.f, nib&2u?1.f:0.f, nib&4u?1.f:0.f, nib&8u?1.f:0.f);
      size_t idx = (size_t)b*NNSQ + (size_t)n*NN_ + m0;
      *(float4*)&out_mask[idx] = mk;
      float inv = inv8[r];
      float4 sp = *(const float4*)&g_supports[n*NN_+m0];
      sp.x = (sp.x + tg[r][0]*inv)*0.5f*mk.x;
      sp.y = (sp.y + tg[r][1]*inv)*0.5f*mk.y;
      sp.z = (sp.z + tg[r][2]*inv)*0.5f*mk.z;
      sp.w = (sp.w + tg[r][3]*inv)*0.5f*mk.w;
      *(uint2*)&g_sh[idx] = make_uint2(
          pack_h2(__float2half_rn(sp.x), __float2half_rn(sp.y)),
          pack_h2(__float2half_rn(sp.z), __float2half_rn(sp.w)));
      cnt += __popc(nib);
      uint32_t v = nib << ((lane&7)*4);
      v |= __shfl_xor_sync(0xffffffffu, v, 1);
      v |= __shfl_xor_sync(0xffffffffu, v, 2);
      v |= __shfl_xor_sync(0xffffffffu, v, 4);
      if ((lane&7)==0) g_bits[idx>>5] = v;
    }
  }
  __syncthreads();
  float fc = blockSum((float)cnt, (float*)red);
  if (tid==0) atomicAdd(&g_pos[b], (unsigned int)(fc + 0.5f));
}

// kept-count: standalone, low-reg, overlapped on a forked stream.
__global__ void __launch_bounds__(256) k_kept(){
  __shared__ unsigned int cnt[BB];
  if (threadIdx.x < BB) cnt[threadIdx.x] = 0u;
  __syncthreads();
  float prob = prob_from_pos();
  int lane = threadIdx.x & 31;
  unsigned int base = blockIdx.x*1024u + threadIdx.x;
  #pragma unroll
  for (int k=0;k<4;k++){
    unsigned int t = base + (unsigned)k*256u;
    uint32_t x0 = t, x1 = t + (uint32_t)HALF_BNN;
    threefry2x32(0u, 42u, x0, x1);
    float u0 = __uint_as_float((x0>>9) | 0x3f800000u) - 1.0f;
    float u1 = __uint_as_float((x1>>9) | 0x3f800000u) - 1.0f;
    uint32_t w0 = g_bits[t>>5];
    uint32_t w1 = g_bits[(t + HALF_BNN)>>5];
    int b0 = (int)(t >> 20);
    bool keep0 = ((w0>>lane)&1u) && !(u0 < prob);
    bool keep1 = ((w1>>lane)&1u) && !(u1 < prob);
    unsigned bal0 = __ballot_sync(0xffffffffu, keep0);
    unsigned bal1 = __ballot_sync(0xffffffffu, keep1);
    if (lane==0){
      if (bal0) atomicAdd(&cnt[b0],   __popc(bal0));
      if (bal1) atomicAdd(&cnt[b0+8], __popc(bal1));
    }
  }
  __syncthreads();
  if (threadIdx.x < BB && cnt[threadIdx.x]) atomicAdd(&g_kept[threadIdx.x], cnt[threadIdx.x]);
}

// mma<128>: 512 threads, A=fp16 sup, B=fp16 hi/lo; double-buffered + prefetch.
__global__ void __launch_bounds__(512) k_mma128(const __half* __restrict__ Bh,
                                                const __half* __restrict__ Bl,
                                                float* __restrict__ C){
  constexpr int NO = 128;
  constexpr int BST = NO+8;
  constexpr int APITCH = 40;
  __shared__ __half Ash[2][128*APITCH];
  __shared__ __half Bsh[2][32*BST], Bsl[2][32*BST];
  int b = blockIdx.x >> 3;
  int m0 = (blockIdx.x & 7)*128;
  int w = threadIdx.x>>5, lane = threadIdx.x&31;
  int wm = (w>>1)*16;
  int wn = (w&1)*64;
  float acc[8][4];
  #pragma unroll
  for (int j=0;j<8;j++){ acc[j][0]=0.f; acc[j][1]=0.f; acc[j][2]=0.f; acc[j][3]=0.f; }
  const __half* Ahb = g_sh + (size_t)b*NNSQ;
  const __half* Bhb = Bh + (size_t)b*NN_*NO;
  const __half* Blb = Bl + (size_t)b*NN_*NO;
  int ar = threadIdx.x>>2, ac = threadIdx.x&3;
  int brr = threadIdx.x>>4, bc = threadIdx.x&15;
  uint4 pAh, pBh, pBl;
  auto ldtile = [&](int k0){
    pAh = *(const uint4*)&Ahb[(size_t)(m0+ar)*NN_ + k0 + ac*8];
    pBh = *(const uint4*)&Bhb[(size_t)(k0+brr)*NO + bc*8];
    pBl = *(const uint4*)&Blb[(size_t)(k0+brr)*NO + bc*8];
  };
  auto sttile = [&](int buf){
    *(uint4*)&Ash[buf][ar*APITCH + ac*8] = pAh;
    *(uint4*)&Bsh[buf][brr*BST + bc*8] = pBh;
    *(uint4*)&Bsl[buf][brr*BST + bc*8] = pBl;
  };
  ldtile(0);
  sttile(0);
  __syncthreads();
  #pragma unroll 1
  for (int t=0;t<32;t++){
    if (t+1 < 32) ldtile((t+1)*32);
    int buf = t & 1;
    #pragma unroll
    for (int kk=0; kk<2; kk++){
      uint32_t ah[4];
      int aoff = (wm + (lane&15))*APITCH + kk*16 + (lane>>4)*8;
      ldsm4(ah[0],ah[1],ah[2],ah[3], &Ash[buf][aoff]);
      #pragma unroll
      for (int j=0;j<8;j++){
        uint32_t bh[2], bl[2];
        int boff = (kk*16 + (lane&15))*BST + wn + j*8;
        ldsm2t(bh[0],bh[1], &Bsh[buf][boff]);
        ldsm2t(bl[0],bl[1], &Bsl[buf][boff]);
        mma16816h(acc[j], ah, bh);
        mma16816h(acc[j], ah, bl);
      }
    }
    if (t+1 < 32){
      __syncthreads();
      sttile((t+1)&1);
      __syncthreads();
    }
  }
  #pragma unroll
  for (int j=0;j<8;j++){
    int r0 = m0 + wm + (lane>>2);
    int c0 = wn + j*8 + (lane&3)*2;
    float* Cp = C + ((size_t)b*NN_ + r0)*NO + c0;
    Cp[0] = acc[j][0]; Cp[1] = acc[j][1];
    Cp[(size_t)8*NO] = acc[j][2]; Cp[(size_t)8*NO+1] = acc[j][3];
  }
}

// mma<64>: 256 threads, A=fp16 single, B=fp16 hi/lo.
__global__ void k_mma64(const __half* __restrict__ Bh,
                        const __half* __restrict__ Bl,
                        float* __restrict__ C){
  constexpr int NO = 64;
  constexpr int BST = NO+8;
  __shared__ __half Ash[128*40];
  __shared__ __half Bsh[32*BST], Bsl[32*BST];
  int b = blockIdx.y;
  int m0 = blockIdx.x*128;
  int w = threadIdx.x>>5, lane = threadIdx.x&31;
  int wm = w*16;
  float acc[8][4];
  #pragma unroll
  for (int j=0;j<8;j++){ acc[j][0]=0.f; acc[j][1]=0.f; acc[j][2]=0.f; acc[j][3]=0.f; }
  const __half* Ahb = g_sh + (size_t)b*NNSQ;
  const __half* Bhb = Bh + (size_t)b*NN_*NO;
  const __half* Blb = Bl + (size_t)b*NN_*NO;
  for (int k0=0;k0<NN_;k0+=32){
    #pragma unroll
    for (int i = threadIdx.x; i<512; i+=256){
      int r = i>>2, c = i&3;
      *(uint4*)&Ash[r*40 + c*8] = *(const uint4*)&Ahb[(size_t)(m0+r)*NN_ + k0 + c*8];
    }
    {
      int i = threadIdx.x;
      int r = i>>3, c = i&7;
      *(uint4*)&Bsh[r*BST + c*8] = *(const uint4*)&Bhb[(size_t)(k0+r)*NO + c*8];
      *(uint4*)&Bsl[r*BST + c*8] = *(const uint4*)&Blb[(size_t)(k0+r)*NO + c*8];
    }
    __syncthreads();
    #pragma unroll
    for (int kk=0; kk<2; kk++){
      uint32_t ah[4];
      int aoff = (wm + (lane&15))*40 + kk*16 + (lane>>4)*8;
      ldsm4(ah[0],ah[1],ah[2],ah[3], &Ash[aoff]);
      #pragma unroll
      for (int j=0;j<8;j++){
        uint32_t bh[2], bl[2];
        int boff = (kk*16 + (lane&15))*BST + j*8;
        ldsm2t(bh[0],bh[1], &Bsh[boff]);
        ldsm2t(bl[0],bl[1], &Bsl[boff]);
        mma16816h(acc[j], ah, bh);
        mma16816h(acc[j], ah, bl);
      }
    }
    __syncthreads();
  }
  #pragma unroll
  for (int j=0;j<8;j++){
    int r0 = m0 + wm + (lane>>2);
    int c0 = j*8 + (lane&3)*2;
    float* Cp = C + ((size_t)b*NN_ + r0)*NO + c0;
    Cp[0] = acc[j][0]; Cp[1] = acc[j][1];
    Cp[(size_t)8*NO] = acc[j][2]; Cp[(size_t)8*NO+1] = acc[j][3];
  }
}

// r-gate: 4b x 4o register tile per thread.
__global__ void __launch_bounds__(128) k_gate_r(const float* __restrict__ x,
                                                const float* __restrict__ st){
  int n = blockIdx.x;
  __shared__ float Xg[256*20];
  int t = threadIdx.x;
  for (int q=t; q<4096; q+=128){
    int b = q>>8, i = q&255;
    float v;
    if (i < 64)       v = x[((size_t)b*NN_+n)*64 + i];
    else if (i < 128) v = st[((size_t)b*NN_+n)*64 + (i-64)];
    else              v = g_xb[((size_t)b*NN_+n)*128 + (i-128)];
    Xg[i*20 + b] = v;
  }
  __syncthreads();
  int og = t>>2, bg = t&3;
  int o0 = og*4, b0 = bg*4;
  float acc[4][4] = {};
  const float* W = g_Wn_r + (size_t)n*256*128 + o0;
  #pragma unroll 2
  for (int i=0;i<256;i++){
    float4 xv = *(float4*)&Xg[i*20 + b0];
    float4 wv = *(const float4*)&W[(size_t)i*128];
    float xs[4] = {xv.x,xv.y,xv.z,xv.w};
    float ws[4] = {wv.x,wv.y,wv.z,wv.w};
    #pragma unroll
    for (int bi=0;bi<4;bi++)
      #pragma unroll
      for (int oi=0;oi<4;oi++)
        acc[bi][oi] += xs[bi]*ws[oi];
  }
  float4 bias = *(const float4*)&g_bias_r[n*128 + o0];
  float bs[4] = {bias.x,bias.y,bias.z,bias.w};
  #pragma unroll
  for (int bi=0;bi<4;bi++){
    int b = b0+bi;
    size_t idx = ((size_t)b*NN_+n)*64;
    #pragma unroll
    for (int oi=0;oi<4;oi++){
      int o = o0+oi;
      float g = 1.0f/(1.0f+__expf(-(acc[bi][oi]+bs[oi])));
      if (o < 64){
        float zsv = g * st[idx + o];
        g_zs[idx + o] = zsv;
        __half h, l; split_h16(zsv, h, l);
        g_zh[idx + o] = h; g_zl[idx + o] = l;
      } else {
        g_rb[idx + (o-64)] = g;
      }
    }
  }
}

// u-gate + GRU output; block 1024 computes mask_loss.
__global__ void __launch_bounds__(128) k_gate_u(const float* __restrict__ x,
                                                const float* __restrict__ st,
                                                float* __restrict__ out_h,
                                                float* __restrict__ out_loss){
  if (blockIdx.x == NN_){
    if (threadIdx.x < BB){
      unsigned int tot = 0;
      #pragma unroll
      for (int i=0;i<BB;i++) tot += g_pos[i];
      float active = (float)tot / (float)BNN;
      float addend = fmaxf(0.05f/active - 1.0f, 0.0f);
      int b = threadIdx.x;
      out_loss[b] = (float)g_kept[b] / ((float)g_pos[b] + 1e-8f) + addend;
    }
    return;
  }
  int n = blockIdx.x;
  __shared__ float Xg[256*20];
  int t = threadIdx.x;
  for (int q=t; q<4096; q+=128){
    int b = q>>8, i = q&255;
    float v;
    if (i < 64)       v = x[((size_t)b*NN_+n)*64 + i];
    else if (i < 128) v = g_zs[((size_t)b*NN_+n)*64 + (i-64)];
    else if (i < 192) v = g_xb[((size_t)b*NN_+n)*128 + (i-128)];
    else              v = g_c2[((size_t)b*NN_+n)*64 + (i-192)];
    Xg[i*20 + b] = v;
  }
  __syncthreads();
  int og = t>>3, bg = t&7;
  int o0 = og*4, b0 = bg*2;
  float acc[2][4] = {};
  const float* W = g_Wn_u + (size_t)n*256*64 + o0;
  #pragma unroll 2
  for (int i=0;i<256;i++){
    float2 xv = *(float2*)&Xg[i*20 + b0];
    float4 wv = *(const float4*)&W[(size_t)i*64];
    float xs[2] = {xv.x,xv.y};
    float ws[4] = {wv.x,wv.y,wv.z,wv.w};
    #pragma unroll
    for (int bi=0;bi<2;bi++)
      #pragma unroll
      for (int oi=0;oi<4;oi++)
        acc[bi][oi] += xs[bi]*ws[oi];
  }
  float4 bias = *(const float4*)&g_bias_u[n*64 + o0];
  float bs[4] = {bias.x,bias.y,bias.z,bias.w};
  #pragma unroll
  for (int bi=0;bi<2;bi++){
    int b = b0+bi;
    size_t idx = ((size_t)b*NN_+n)*64;
    #pragma unroll
    for (int oi=0;oi<4;oi++){
      int o = o0+oi;
      float hc = tanhf(acc[bi][oi]+bs[oi]);
      float r = g_rb[idx + o];
      float sv = st[idx + o];
      out_h[idx + o] = r*sv + (1.0f-r)*hc;
    }
  }
}

// ---------------- launch ----------------
extern "C" void kernel_launch(void* const* d_in, const int* in_sizes, int n_in,
                              void* d_out, int out_size){
  const float* x    = (const float*)d_in[0];
  const float* st   = (const float*)d_in[1];
  const float* we   = (const float*)d_in[2];
  const float* T    = (const float*)d_in[3];
  const float* Wpr  = (const float*)d_in[4];
  const float* bpr  = (const float*)d_in[5];
  const float* Wpu  = (const float*)d_in[6];
  const float* bpu  = (const float*)d_in[7];
  const float* mp   = (const float*)d_in[8];
  const float* tp   = (const float*)d_in[9];
  const float* gmm  = (const float*)d_in[10];
  const float* bta  = (const float*)d_in[11];
  const int*   itp  = (const int*)d_in[12];
  float* out = (float*)d_out;
  float* out_mask = out + OFF_MASK;

  static __half *xh_p=nullptr, *xl_p=nullptr, *zh_p=nullptr, *zl_p=nullptr;
  static float *xb_p=nullptr, *c2_p=nullptr;
  static cudaStream_t s2 = nullptr;
  static cudaEvent_t evFork = nullptr, evJoin = nullptr;
  if (!xh_p){
    cudaGetSymbolAddress((void**)&xh_p, g_xh);
    cudaGetSymbolAddress((void**)&xl_p, g_xl);
    cudaGetSymbolAddress((void**)&zh_p, g_zh);
    cudaGetSymbolAddress((void**)&zl_p, g_zl);
    cudaGetSymbolAddress((void**)&xb_p, g_xb);
    cudaGetSymbolAddress((void**)&c2_p, g_c2);
    size_t smem_sup = (size_t)(WINDOW*NN_)*sizeof(float);   // 48 KB
    cudaFuncSetAttribute(k_sup_wgen, cudaFuncAttributeMaxDynamicSharedMemorySize, (int)smem_sup);
    cudaStreamCreateWithFlags(&s2, cudaStreamNonBlocking);
    cudaEventCreateWithFlags(&evFork, cudaEventDisableTiming);
    cudaEventCreateWithFlags(&evJoin, cudaEventDisableTiming);
  }
  size_t smem_sup = (size_t)(WINDOW*NN_)*sizeof(float);

  k_setup<<<64,256>>>(we, itp);
  k_pre<<<4096,256>>>(mp, bpr, bpu, x, st);
  k_sup_wgen<<<1536,256,smem_sup>>>(T, tp, gmm, bta, out_mask, Wpr, Wpu);
  cudaEventRecord(evFork, 0);
  cudaStreamWaitEvent(s2, evFork, 0);
  k_kept<<<8192,256,0,s2>>>();
  k_mma128<<<128,512>>>(xh_p, xl_p, xb_p);
  k_gate_r<<<NN_,128>>>(x, st);
  k_mma64<<<dim3(8,16),256>>>(zh_p, zl_p, c2_p);
  cudaEventRecord(evJoin, s2);
  cudaStreamWaitEvent(0, evJoin, 0);
  k_gate_u<<<NN_+1,128>>>(x, st, out, out + OFF_LOSS);
}

// round 11
// speedup vs baseline: 2.4129x; 1.0063x over previous
#include <cuda_runtime.h>
#include <cuda_bf16.h>
#include <cuda_fp16.h>
#include <cstdint>
#include <math.h>

#define BB 16
#define NN_ 1024
#define EDIM 16
#define WINDOW 12
#define NNSQ (NN_*NN_)
#define BNN (BB*NNSQ)
#define HALF_BNN (BNN/2)
#define OFF_MASK (BB*NN_*64)
#define OFF_LOSS (OFF_MASK + BNN)
#define MASK_THR (-2.66352776f)   /* ln(1.4) - 3 */

// ---------------- scratch ----------------
__device__ float g_E[NN_*EDIM];
__device__ float g_Et[EDIM*NN_];
__device__ float g_EM[NNSQ];
__device__ float g_supports[NNSQ];
__device__ __half g_sh[(size_t)BNN];                 // sup fp16 (single)
__device__ uint32_t g_bits[BNN/32];
__device__ __half g_xh[(size_t)BB*NN_*128];
__device__ __half g_xl[(size_t)BB*NN_*128];
__device__ __half g_zh[(size_t)BB*NN_*64];
__device__ __half g_zl[(size_t)BB*NN_*64];
__device__ __half g_Wn_r[(size_t)NN_*256*128];       // fp16 per-node weights (67 MB)
__device__ __half g_Wn_u[(size_t)NN_*256*64];        // 33.5 MB
__device__ float g_bias_r[NN_*128];
__device__ float g_bias_u[NN_*64];
__device__ float g_xb[(size_t)BB*NN_*128];
__device__ float g_zs[(size_t)BB*NN_*64];
__device__ float g_rb[(size_t)BB*NN_*64];
__device__ float g_c2[(size_t)BB*NN_*64];
__device__ unsigned int g_pos[BB];
__device__ unsigned int g_kept[BB];

// ---------------- helpers ----------------
__device__ __forceinline__ float warpSum(float v){
  #pragma unroll
  for (int o=16;o;o>>=1) v += __shfl_xor_sync(0xffffffffu, v, o);
  return v;
}
__device__ __forceinline__ float blockSum(float v, float* red){
  int lane = threadIdx.x & 31, w = threadIdx.x >> 5;
  int nw = blockDim.x >> 5;
  v = warpSum(v);
  __syncthreads();
  if (lane==0) red[w] = v;
  __syncthreads();
  float r = (threadIdx.x < (unsigned)nw) ? red[threadIdx.x] : 0.0f;
  if (w==0) r = warpSum(r);
  if (threadIdx.x==0) red[0] = r;
  __syncthreads();
  return red[0];
}
__device__ __forceinline__ uint32_t rotl32(uint32_t x, int r){
  return __funnelshift_l(x, x, r);
}
__device__ __forceinline__ void threefry2x32(uint32_t k0, uint32_t k1,
                                             uint32_t& x0, uint32_t& x1){
  uint32_t ks0 = k0, ks1 = k1, ks2 = k0 ^ k1 ^ 0x1BD11BDAu;
  x0 += ks0; x1 += ks1;
  const int R0[4] = {13,15,26,6};
  const int R1[4] = {17,29,16,24};
  uint32_t ks[3] = {ks0, ks1, ks2};
  #pragma unroll
  for (int i=0;i<5;i++){
    #pragma unroll
    for (int j=0;j<4;j++){
      int r = (i & 1) ? R1[j] : R0[j];
      x0 += x1; x1 = rotl32(x1, r); x1 ^= x0;
    }
    x0 += ks[(i+1)%3];
    x1 += ks[(i+2)%3] + (uint32_t)(i+1);
  }
}
__device__ __forceinline__ void split_h16(float v, __half& h, __half& l){
  h = __float2half_rn(v);
  l = __float2half_rn(v - __half2float(h));
}
__device__ __forceinline__ uint32_t pack_h2(__half a, __half b){
  __half2 p(a, b);
  return *reinterpret_cast<uint32_t*>(&p);
}
__device__ __forceinline__ void ldsm4(uint32_t& r0,uint32_t& r1,uint32_t& r2,uint32_t& r3,
                                      const __half* p){
  uint32_t a = (uint32_t)__cvta_generic_to_shared(p);
  asm volatile("ldmatrix.sync.aligned.m8n8.x4.shared.b16 {%0,%1,%2,%3},[%4];"
    : "=r"(r0),"=r"(r1),"=r"(r2),"=r"(r3) : "r"(a));
}
__device__ __forceinline__ void ldsm2t(uint32_t& r0,uint32_t& r1, const __half* p){
  uint32_t a = (uint32_t)__cvta_generic_to_shared(p);
  asm volatile("ldmatrix.sync.aligned.m8n8.x2.trans.shared.b16 {%0,%1},[%2];"
    : "=r"(r0),"=r"(r1) : "r"(a));
}
__device__ __forceinline__ void mma16816h(float* c, const uint32_t* a, const uint32_t* b){
  asm volatile("mma.sync.aligned.m16n8k16.row.col.f32.f16.f16.f32 "
    "{%0,%1,%2,%3},{%4,%5,%6,%7},{%8,%9},{%0,%1,%2,%3};"
    : "+f"(c[0]),"+f"(c[1]),"+f"(c[2]),"+f"(c[3])
    : "r"(a[0]),"r"(a[1]),"r"(a[2]),"r"(a[3]), "r"(b[0]),"r"(b[1]));
}
__device__ __forceinline__ float prob_from_pos(){
  unsigned int tot = 0;
  #pragma unroll
  for (int i=0;i<BB;i++) tot += g_pos[i];
  float active = (float)tot / (float)BNN;
  return fminf(0.05f/active + 1e-8f, 1.0f);
}

// ---------------- kernels ----------------

__global__ void k_setup(const float* __restrict__ we, const int* __restrict__ itp){
  int tid = blockIdx.x*blockDim.x + threadIdx.x;
  float it = (float)itp[0];
  if (tid < NN_*EDIM){
    int d = tid & 15;
    int pair = d >> 1;
    float arg = (float)((double)(2*pair) * (-9.210340371976184/16.0));
    float div = expf(arg);
    float pe = (d & 1) ? cosf(it*div) : sinf(it*div);
    float e = we[tid] + pe;
    g_E[tid] = e;
    g_Et[d*NN_ + (tid>>4)] = e;
  }
  if (blockIdx.x==0 && threadIdx.x < 2*BB){
    if (threadIdx.x < BB) g_pos[threadIdx.x] = 0u;
    else                  g_kept[threadIdx.x-BB] = 0u;
  }
}

// Merged: [0,1024) em+bias, [1024,2048) supports, [2048,4096) prep.
__global__ void k_pre(const float* __restrict__ mp,
                      const float* __restrict__ bpr, const float* __restrict__ bpu,
                      const float* __restrict__ x, const float* __restrict__ st){
  int g = blockIdx.x;
  if (g < NN_){
    int n = g;
    __shared__ float en[EDIM];
    if (threadIdx.x < EDIM) en[threadIdx.x] = g_E[n*EDIM+threadIdx.x];
    __syncthreads();
    int m0 = threadIdx.x*4;
    float4 a = make_float4(0.f,0.f,0.f,0.f);
    #pragma unroll
    for (int d=0; d<EDIM; d++){
      float4 mv = *(const float4*)&mp[d*NN_+m0];
      float e = en[d];
      a.x += e*mv.x; a.y += e*mv.y; a.z += e*mv.z; a.w += e*mv.w;
    }
    *(float4*)&g_EM[n*NN_+m0] = a;
    int o = threadIdx.x;
    if (o < 128){
      float br = 0.f;
      #pragma unroll
      for (int d=0; d<EDIM; d++) br += en[d]*bpr[d*128+o];
      g_bias_r[n*128+o] = br;
      if (o < 64){
        float bu = 0.f;
        #pragma unroll
        for (int d=0; d<EDIM; d++) bu += en[d]*bpu[d*64+o];
        g_bias_u[n*64+o] = bu;
      }
    }
  } else if (g < 2*NN_){
    int n = g - NN_;
    __shared__ float row[NN_];
    __shared__ float red[32];
    float en[EDIM];
    #pragma unroll
    for (int d=0; d<EDIM; d++) en[d] = g_E[n*EDIM+d];
    int m0 = threadIdx.x*4;
    float4 a = make_float4(0.f,0.f,0.f,0.f);
    #pragma unroll
    for (int d=0; d<EDIM; d++){
      float4 ev = *(const float4*)&g_Et[d*NN_+m0];
      float e = en[d];
      a.x += e*ev.x; a.y += e*ev.y; a.z += e*ev.z; a.w += e*ev.w;
    }
    a.x = __expf(fmaxf(a.x,0.f)); a.y = __expf(fmaxf(a.y,0.f));
    a.z = __expf(fmaxf(a.z,0.f)); a.w = __expf(fmaxf(a.w,0.f));
    *(float4*)&row[m0] = a;
    float s = blockSum(a.x+a.y+a.z+a.w, red);
    float inv = 1.0f/s;
    float4 r4 = *(float4*)&row[m0];
    r4.x *= inv; r4.y *= inv; r4.z *= inv; r4.w *= inv;
    *(float4*)&g_supports[n*NN_+m0] = r4;
  } else {
    int q = (g - 2*NN_)*256 + threadIdx.x;
    int t4 = q*4;
    int j = t4 & 127; int bn = t4 >> 7;
    float4 v = (j < 64) ? *(const float4*)&x[(size_t)bn*64 + j]
                        : *(const float4*)&st[(size_t)bn*64 + (j-64)];
    __half h0,l0,h1,l1,h2,l2,h3,l3;
    split_h16(v.x,h0,l0); split_h16(v.y,h1,l1);
    split_h16(v.z,h2,l2); split_h16(v.w,h3,l3);
    *(uint2*)&g_xh[t4] = make_uint2(pack_h2(h0,h1), pack_h2(h2,h3));
    *(uint2*)&g_xl[t4] = make_uint2(pack_h2(l0,l1), pack_h2(l2,l3));
  }
}

// Wn[n,i2,o] = sum_d E[n,d] * Wp[d,i2,o] -> fp16 stores (256 threads)
template<int OC>
__device__ __forceinline__ void wgen_body(const float* __restrict__ Wp, __half* __restrict__ Wn,
                                          int lb, float* Esm){
  constexpr int NQ = OC/4;
  constexpr int NI = 256/NQ;
  int n0 = (lb>>4)*64;
  int i20 = (lb&15)*16;
  int t = threadIdx.x;
  int oq = t % NQ, ig = t / NQ;
  for (int q=t; q<64*EDIM; q+=256)
    Esm[q] = g_E[(n0 + (q>>4))*EDIM + (q&15)];
  __syncthreads();
  for (int ii=ig; ii<16; ii+=NI){
    int i2 = i20+ii;
    float4 w[EDIM];
    #pragma unroll
    for (int d=0; d<EDIM; d++)
      w[d] = *(const float4*)&Wp[((size_t)d*256 + i2)*OC + oq*4];
    #pragma unroll 4
    for (int nn=0; nn<64; nn++){
      float4 a = make_float4(0.f,0.f,0.f,0.f);
      #pragma unroll
      for (int d=0; d<EDIM; d++){
        float e = Esm[nn*EDIM + d];
        a.x += e*w[d].x; a.y += e*w[d].y; a.z += e*w[d].z; a.w += e*w[d].w;
      }
      __half2 h01 = __floats2half2_rn(a.x, a.y);
      __half2 h23 = __floats2half2_rn(a.z, a.w);
      *(uint2*)&Wn[((size_t)(n0+nn)*256 + i2)*OC + oq*4] =
          make_uint2(*(uint32_t*)&h01, *(uint32_t*)&h23);
    }
  }
}

// Combined: every 3rd block wgen (512), rest supmask (1024 blocks x 16 rows, 2 passes).
__global__ void __launch_bounds__(256) k_sup_wgen(
    const float* __restrict__ T, const float* __restrict__ TP,
    const float* __restrict__ gamma, const float* __restrict__ beta,
    float* __restrict__ out_mask,
    const float* __restrict__ Wpr, const float* __restrict__ Wpu){
  __shared__ float Esm[64*EDIM];
  __shared__ float red[8][8];
  __shared__ float inv8[8];
  int bid = blockIdx.x;
  if (bid % 3 == 0){
    int lb = bid/3;
    if (lb < 256) wgen_body<128>(Wpr, g_Wn_r, lb, Esm);
    else          wgen_body<64>(Wpu, g_Wn_u, lb-256, Esm);
    return;
  }
  int id = bid - bid/3 - 1;                 // [0,1024)
  int b = id >> 6;
  int n0base = (id & 63)*16;
  extern __shared__ float sm[];
  float* Tsm = sm;                          // 48 KB
  int tid = threadIdx.x, lane = tid & 31, wrp = tid >> 5;
  {
    const float4* Tg = (const float4*)(T + (size_t)b*WINDOW*NN_);
    float4* T4 = (float4*)Tsm;
    #pragma unroll
    for (int i=0;i<12;i++) T4[tid + i*256] = Tg[tid + i*256];
  }
  __syncthreads();
  int m0 = tid*4;
  const float bni = 1.0f/sqrtf(1.0f + 1e-5f);
  unsigned int cnt = 0;
  #pragma unroll 1
  for (int half=0; half<2; half++){
    int n0 = n0base + half*8;
    float tg[8][4];
    #pragma unroll
    for (int r=0;r<8;r++){ tg[r][0]=0.f; tg[r][1]=0.f; tg[r][2]=0.f; tg[r][3]=0.f; }
    #pragma unroll
    for (int w=0; w<WINDOW; w++){
      float4 tw = *(float4*)&Tsm[w*NN_+m0];
      #pragma unroll
      for (int r=0;r<8;r++){
        float tvs = Tsm[w*NN_ + n0 + r];
        tg[r][0] += tvs*tw.x; tg[r][1] += tvs*tw.y;
        tg[r][2] += tvs*tw.z; tg[r][3] += tvs*tw.w;
      }
    }
    float psum[8];
    #pragma unroll
    for (int r=0;r<8;r++){
      tg[r][0] = __expf(fmaxf(tg[r][0],0.f));
      tg[r][1] = __expf(fmaxf(tg[r][1],0.f));
      tg[r][2] = __expf(fmaxf(tg[r][2],0.f));
      tg[r][3] = __expf(fmaxf(tg[r][3],0.f));
      psum[r] = (tg[r][0]+tg[r][1])+(tg[r][2]+tg[r][3]);
    }
    #pragma unroll
    for (int r=0;r<8;r++) psum[r] = warpSum(psum[r]);
    __syncthreads();
    if (lane==0){
      #pragma unroll
      for (int r=0;r<8;r++) red[r][wrp] = psum[r];
    }
    __syncthreads();
    if (tid < 8){
      float s = 0.f;
      #pragma unroll
      for (int k=0;k<8;k++) s += red[tid][k];
      inv8[tid] = 1.0f/s;
    }
    __syncthreads();
    float rm[8][4];
    #pragma unroll
    for (int r=0;r<8;r++){
      float4 t = *(const float4*)&g_EM[(size_t)(n0+r)*NN_ + m0];
      rm[r][0]=t.x; rm[r][1]=t.y; rm[r][2]=t.z; rm[r][3]=t.w;
    }
    #pragma unroll
    for (int w=0; w<WINDOW; w++){
      float4 tp = __ldg((const float4*)&TP[w*NN_+m0]);
      #pragma unroll
      for (int r=0;r<8;r++){
        float tvs = Tsm[w*NN_ + n0 + r];
        rm[r][0] += tvs*tp.x; rm[r][1] += tvs*tp.y;
        rm[r][2] += tvs*tp.z; rm[r][3] += tvs*tp.w;
      }
    }
    #pragma unroll
    for (int r=0;r<8;r++){
      int n = n0 + r;
      float sc = bni*gamma[n], bt = beta[n];
      float v0 = rm[r][0]*sc + bt, v1 = rm[r][1]*sc + bt;
      float v2 = rm[r][2]*sc + bt, v3 = rm[r][3]*sc + bt;
      uint32_t nib = (v0 > MASK_THR ? 1u:0u) | (v1 > MASK_THR ? 2u:0u)
                   | (v2 > MASK_THR ? 4u:0u) | (v3 > MASK_THR ? 8u:0u);
      float4 mk = make_float4(nib&1u?1.f:0.f, nib&2u?1.f:0.f, nib&4u?1.f:0.f, nib&8u?1.f:0.f);
      size_t idx = (size_t)b*NNSQ + (size_t)n*NN_ + m0;
      *(float4*)&out_mask[idx] = mk;
      float inv = inv8[r];
      float4 sp = *(const float4*)&g_supports[n*NN_+m0];
      sp.x = (sp.x + tg[r][0]*inv)*0.5f*mk.x;
      sp.y = (sp.y + tg[r][1]*inv)*0.5f*mk.y;
      sp.z = (sp.z + tg[r][2]*inv)*0.5f*mk.z;
      sp.w = (sp.w + tg[r][3]*inv)*0.5f*mk.w;
      *(uint2*)&g_sh[idx] = make_uint2(
          pack_h2(__float2half_rn(sp.x), __float2half_rn(sp.y)),
          pack_h2(__float2half_rn(sp.z), __float2half_rn(sp.w)));
      cnt += __popc(nib);
      uint32_t v = nib << ((lane&7)*4);
      v |= __shfl_xor_sync(0xffffffffu, v, 1);
      v |= __shfl_xor_sync(0xffffffffu, v, 2);
      v |= __shfl_xor_sync(0xffffffffu, v, 4);
      if ((lane&7)==0) g_bits[idx>>5] = v;
    }
  }
  __syncthreads();
  float fc = blockSum((float)cnt, (float*)red);
  if (tid==0) atomicAdd(&g_pos[b], (unsigned int)(fc + 0.5f));
}

// kept-count: standalone, overlapped on a forked stream.
__global__ void __launch_bounds__(256) k_kept(){
  __shared__ unsigned int cnt[BB];
  if (threadIdx.x < BB) cnt[threadIdx.x] = 0u;
  __syncthreads();
  float prob = prob_from_pos();
  int lane = threadIdx.x & 31;
  unsigned int base = blockIdx.x*1024u + threadIdx.x;
  #pragma unroll
  for (int k=0;k<4;k++){
    unsigned int t = base + (unsigned)k*256u;
    uint32_t x0 = t, x1 = t + (uint32_t)HALF_BNN;
    threefry2x32(0u, 42u, x0, x1);
    float u0 = __uint_as_float((x0>>9) | 0x3f800000u) - 1.0f;
    float u1 = __uint_as_float((x1>>9) | 0x3f800000u) - 1.0f;
    uint32_t w0 = g_bits[t>>5];
    uint32_t w1 = g_bits[(t + HALF_BNN)>>5];
    int b0 = (int)(t >> 20);
    bool keep0 = ((w0>>lane)&1u) && !(u0 < prob);
    bool keep1 = ((w1>>lane)&1u) && !(u1 < prob);
    unsigned bal0 = __ballot_sync(0xffffffffu, keep0);
    unsigned bal1 = __ballot_sync(0xffffffffu, keep1);
    if (lane==0){
      if (bal0) atomicAdd(&cnt[b0],   __popc(bal0));
      if (bal1) atomicAdd(&cnt[b0+8], __popc(bal1));
    }
  }
  __syncthreads();
  if (threadIdx.x < BB && cnt[threadIdx.x]) atomicAdd(&g_kept[threadIdx.x], cnt[threadIdx.x]);
}

// mma<128>: 512 threads, A=fp16 sup, B=fp16 hi/lo; double-buffered + prefetch.
__global__ void __launch_bounds__(512) k_mma128(const __half* __restrict__ Bh,
                                                const __half* __restrict__ Bl,
                                                float* __restrict__ C){
  constexpr int NO = 128;
  constexpr int BST = NO+8;
  constexpr int APITCH = 40;
  __shared__ __half Ash[2][128*APITCH];
  __shared__ __half Bsh[2][32*BST], Bsl[2][32*BST];
  int b = blockIdx.x >> 3;
  int m0 = (blockIdx.x & 7)*128;
  int w = threadIdx.x>>5, lane = threadIdx.x&31;
  int wm = (w>>1)*16;
  int wn = (w&1)*64;
  float acc[8][4];
  #pragma unroll
  for (int j=0;j<8;j++){ acc[j][0]=0.f; acc[j][1]=0.f; acc[j][2]=0.f; acc[j][3]=0.f; }
  const __half* Ahb = g_sh + (size_t)b*NNSQ;
  const __half* Bhb = Bh + (size_t)b*NN_*NO;
  const __half* Blb = Bl + (size_t)b*NN_*NO;
  int ar = threadIdx.x>>2, ac = threadIdx.x&3;
  int brr = threadIdx.x>>4, bc = threadIdx.x&15;
  uint4 pAh, pBh, pBl;
  auto ldtile = [&](int k0){
    pAh = *(const uint4*)&Ahb[(size_t)(m0+ar)*NN_ + k0 + ac*8];
    pBh = *(const uint4*)&Bhb[(size_t)(k0+brr)*NO + bc*8];
    pBl = *(const uint4*)&Blb[(size_t)(k0+brr)*NO + bc*8];
  };
  auto sttile = [&](int buf){
    *(uint4*)&Ash[buf][ar*APITCH + ac*8] = pAh;
    *(uint4*)&Bsh[buf][brr*BST + bc*8] = pBh;
    *(uint4*)&Bsl[buf][brr*BST + bc*8] = pBl;
  };
  ldtile(0);
  sttile(0);
  __syncthreads();
  #pragma unroll 1
  for (int t=0;t<32;t++){
    if (t+1 < 32) ldtile((t+1)*32);
    int buf = t & 1;
    #pragma unroll
    for (int kk=0; kk<2; kk++){
      uint32_t ah[4];
      int aoff = (wm + (lane&15))*APITCH + kk*16 + (lane>>4)*8;
      ldsm4(ah[0],ah[1],ah[2],ah[3], &Ash[buf][aoff]);
      #pragma unroll
      for (int j=0;j<8;j++){
        uint32_t bh[2], bl[2];
        int boff = (kk*16 + (lane&15))*BST + wn + j*8;
        ldsm2t(bh[0],bh[1], &Bsh[buf][boff]);
        ldsm2t(bl[0],bl[1], &Bsl[buf][boff]);
        mma16816h(acc[j], ah, bh);
        mma16816h(acc[j], ah, bl);
      }
    }
    if (t+1 < 32){
      __syncthreads();
      sttile((t+1)&1);
      __syncthreads();
    }
  }
  #pragma unroll
  for (int j=0;j<8;j++){
    int r0 = m0 + wm + (lane>>2);
    int c0 = wn + j*8 + (lane&3)*2;
    float* Cp = C + ((size_t)b*NN_ + r0)*NO + c0;
    Cp[0] = acc[j][0]; Cp[1] = acc[j][1];
    Cp[(size_t)8*NO] = acc[j][2]; Cp[(size_t)8*NO+1] = acc[j][3];
  }
}

// mma<64>: 256 threads, A=fp16 single, B=fp16 hi/lo.
__global__ void k_mma64(const __half* __restrict__ Bh,
                        const __half* __restrict__ Bl,
                        float* __restrict__ C){
  constexpr int NO = 64;
  constexpr int BST = NO+8;
  __shared__ __half Ash[128*40];
  __shared__ __half Bsh[32*BST], Bsl[32*BST];
  int b = blockIdx.y;
  int m0 = blockIdx.x*128;
  int w = threadIdx.x>>5, lane = threadIdx.x&31;
  int wm = w*16;
  float acc[8][4];
  #pragma unroll
  for (int j=0;j<8;j++){ acc[j][0]=0.f; acc[j][1]=0.f; acc[j][2]=0.f; acc[j][3]=0.f; }
  const __half* Ahb = g_sh + (size_t)b*NNSQ;
  const __half* Bhb = Bh + (size_t)b*NN_*NO;
  const __half* Blb = Bl + (size_t)b*NN_*NO;
  for (int k0=0;k0<NN_;k0+=32){
    #pragma unroll
    for (int i = threadIdx.x; i<512; i+=256){
      int r = i>>2, c = i&3;
      *(uint4*)&Ash[r*40 + c*8] = *(const uint4*)&Ahb[(size_t)(m0+r)*NN_ + k0 + c*8];
    }
    {
      int i = threadIdx.x;
      int r = i>>3, c = i&7;
      *(uint4*)&Bsh[r*BST + c*8] = *(const uint4*)&Bhb[(size_t)(k0+r)*NO + c*8];
      *(uint4*)&Bsl[r*BST + c*8] = *(const uint4*)&Blb[(size_t)(k0+r)*NO + c*8];
    }
    __syncthreads();
    #pragma unroll
    for (int kk=0; kk<2; kk++){
      uint32_t ah[4];
      int aoff = (wm + (lane&15))*40 + kk*16 + (lane>>4)*8;
      ldsm4(ah[0],ah[1],ah[2],ah[3], &Ash[aoff]);
      #pragma unroll
      for (int j=0;j<8;j++){
        uint32_t bh[2], bl[2];
        int boff = (kk*16 + (lane&15))*BST + j*8;
        ldsm2t(bh[0],bh[1], &Bsh[boff]);
        ldsm2t(bl[0],bl[1], &Bsl[boff]);
        mma16816h(acc[j], ah, bh);
        mma16816h(acc[j], ah, bl);
      }
    }
    __syncthreads();
  }
  #pragma unroll
  for (int j=0;j<8;j++){
    int r0 = m0 + wm + (lane>>2);
    int c0 = j*8 + (lane&3)*2;
    float* Cp = C + ((size_t)b*NN_ + r0)*NO + c0;
    Cp[0] = acc[j][0]; Cp[1] = acc[j][1];
    Cp[(size_t)8*NO] = acc[j][2]; Cp[(size_t)8*NO+1] = acc[j][3];
  }
}

// r-gate: 4b x 4o register tile per thread; W in fp16.
__global__ void __launch_bounds__(128) k_gate_r(const float* __restrict__ x,
                                                const float* __restrict__ st){
  int n = blockIdx.x;
  __shared__ float Xg[256*20];
  int t = threadIdx.x;
  for (int q=t; q<4096; q+=128){
    int b = q>>8, i = q&255;
    float v;
    if (i < 64)       v = x[((size_t)b*NN_+n)*64 + i];
    else if (i < 128) v = st[((size_t)b*NN_+n)*64 + (i-64)];
    else              v = g_xb[((size_t)b*NN_+n)*128 + (i-128)];
    Xg[i*20 + b] = v;
  }
  __syncthreads();
  int og = t>>2, bg = t&3;
  int o0 = og*4, b0 = bg*4;
  float acc[4][4] = {};
  const __half* W = g_Wn_r + (size_t)n*256*128 + o0;
  #pragma unroll 2
  for (int i=0;i<256;i++){
    float4 xv = *(float4*)&Xg[i*20 + b0];
    uint2 wv = *(const uint2*)&W[(size_t)i*128];
    float2 f01 = __half22float2(*(__half2*)&wv.x);
    float2 f23 = __half22float2(*(__half2*)&wv.y);
    float xs[4] = {xv.x,xv.y,xv.z,xv.w};
    float ws[4] = {f01.x,f01.y,f23.x,f23.y};
    #pragma unroll
    for (int bi=0;bi<4;bi++)
      #pragma unroll
      for (int oi=0;oi<4;oi++)
        acc[bi][oi] += xs[bi]*ws[oi];
  }
  float4 bias = *(const float4*)&g_bias_r[n*128 + o0];
  float bs[4] = {bias.x,bias.y,bias.z,bias.w};
  #pragma unroll
  for (int bi=0;bi<4;bi++){
    int b = b0+bi;
    size_t idx = ((size_t)b*NN_+n)*64;
    #pragma unroll
    for (int oi=0;oi<4;oi++){
      int o = o0+oi;
      float g = 1.0f/(1.0f+__expf(-(acc[bi][oi]+bs[oi])));
      if (o < 64){
        float zsv = g * st[idx + o];
        g_zs[idx + o] = zsv;
        __half h, l; split_h16(zsv, h, l);
        g_zh[idx + o] = h; g_zl[idx + o] = l;
      } else {
        g_rb[idx + (o-64)] = g;
      }
    }
  }
}

// u-gate + GRU output; block 1024 computes mask_loss. W in fp16.
__global__ void __launch_bounds__(128) k_gate_u(const float* __restrict__ x,
                                                const float* __restrict__ st,
                                                float* __restrict__ out_h,
                                                float* __restrict__ out_loss){
  if (blockIdx.x == NN_){
    if (threadIdx.x < BB){
      unsigned int tot = 0;
      #pragma unroll
      for (int i=0;i<BB;i++) tot += g_pos[i];
      float active = (float)tot / (float)BNN;
      float addend = fmaxf(0.05f/active - 1.0f, 0.0f);
      int b = threadIdx.x;
      out_loss[b] = (float)g_kept[b] / ((float)g_pos[b] + 1e-8f) + addend;
    }
    return;
  }
  int n = blockIdx.x;
  __shared__ float Xg[256*20];
  int t = threadIdx.x;
  for (int q=t; q<4096; q+=128){
    int b = q>>8, i = q&255;
    float v;
    if (i < 64)       v = x[((size_t)b*NN_+n)*64 + i];
    else if (i < 128) v = g_zs[((size_t)b*NN_+n)*64 + (i-64)];
    else if (i < 192) v = g_xb[((size_t)b*NN_+n)*128 + (i-128)];
    else              v = g_c2[((size_t)b*NN_+n)*64 + (i-192)];
    Xg[i*20 + b] = v;
  }
  __syncthreads();
  int og = t>>3, bg = t&7;
  int o0 = og*4, b0 = bg*2;
  float acc[2][4] = {};
  const __half* W = g_Wn_u + (size_t)n*256*64 + o0;
  #pragma unroll 2
  for (int i=0;i<256;i++){
    float2 xv = *(float2*)&Xg[i*20 + b0];
    uint2 wv = *(const uint2*)&W[(size_t)i*64];
    float2 f01 = __half22float2(*(__half2*)&wv.x);
    float2 f23 = __half22float2(*(__half2*)&wv.y);
    float xs[2] = {xv.x,xv.y};
    float ws[4] = {f01.x,f01.y,f23.x,f23.y};
    #pragma unroll
    for (int bi=0;bi<2;bi++)
      #pragma unroll
      for (int oi=0;oi<4;oi++)
        acc[bi][oi] += xs[bi]*ws[oi];
  }
  float4 bias = *(const float4*)&g_bias_u[n*64 + o0];
  float bs[4] = {bias.x,bias.y,bias.z,bias.w};
  #pragma unroll
  for (int bi=0;bi<2;bi++){
    int b = b0+bi;
    size_t idx = ((size_t)b*NN_+n)*64;
    #pragma unroll
    for (int oi=0;oi<4;oi++){
      int o = o0+oi;
      float hc = tanhf(acc[bi][oi]+bs[oi]);
      float r = g_rb[idx + o];
      float sv = st[idx + o];
      out_h[idx + o] = r*sv + (1.0f-r)*hc;
    }
  }
}

// ---------------- launch ----------------
extern "C" void kernel_launch(void* const* d_in, const int* in_sizes, int n_in,
                              void* d_out, int out_size){
  const float* x    = (const float*)d_in[0];
  const float* st   = (const float*)d_in[1];
  const float* we   = (const float*)d_in[2];
  const float* T    = (const float*)d_in[3];
  const float* Wpr  = (const float*)d_in[4];
  const float* bpr  = (const float*)d_in[5];
  const float* Wpu  = (const float*)d_in[6];
  const float* bpu  = (const float*)d_in[7];
  const float* mp   = (const float*)d_in[8];
  const float* tp   = (const float*)d_in[9];
  const float* gmm  = (const float*)d_in[10];
  const float* bta  = (const float*)d_in[11];
  const int*   itp  = (const int*)d_in[12];
  float* out = (float*)d_out;
  float* out_mask = out + OFF_MASK;

  static __half *xh_p=nullptr, *xl_p=nullptr, *zh_p=nullptr, *zl_p=nullptr;
  static float *xb_p=nullptr, *c2_p=nullptr;
  static cudaStream_t s2 = nullptr;
  static cudaEvent_t evFork = nullptr, evJoin = nullptr;
  if (!xh_p){
    cudaGetSymbolAddress((void**)&xh_p, g_xh);
    cudaGetSymbolAddress((void**)&xl_p, g_xl);
    cudaGetSymbolAddress((void**)&zh_p, g_zh);
    cudaGetSymbolAddress((void**)&zl_p, g_zl);
    cudaGetSymbolAddress((void**)&xb_p, g_xb);
    cudaGetSymbolAddress((void**)&c2_p, g_c2);
    size_t smem_sup = (size_t)(WINDOW*NN_)*sizeof(float);   // 48 KB
    cudaFuncSetAttribute(k_sup_wgen, cudaFuncAttributeMaxDynamicSharedMemorySize, (int)smem_sup);
    cudaStreamCreateWithFlags(&s2, cudaStreamNonBlocking);
    cudaEventCreateWithFlags(&evFork, cudaEventDisableTiming);
    cudaEventCreateWithFlags(&evJoin, cudaEventDisableTiming);
  }
  size_t smem_sup = (size_t)(WINDOW*NN_)*sizeof(float);

  k_setup<<<64,256>>>(we, itp);
  k_pre<<<4096,256>>>(mp, bpr, bpu, x, st);
  k_sup_wgen<<<1536,256,smem_sup>>>(T, tp, gmm, bta, out_mask, Wpr, Wpu);
  cudaEventRecord(evFork, 0);
  cudaStreamWaitEvent(s2, evFork, 0);
  k_kept<<<8192,256,0,s2>>>();
  k_mma128<<<128,512>>>(xh_p, xl_p, xb_p);
  k_gate_r<<<NN_,128>>>(x, st);
  k_mma64<<<dim3(8,16),256>>>(zh_p, zl_p, c2_p);
  cudaEventRecord(evJoin, s2);
  cudaStreamWaitEvent(0, evJoin, 0);
  k_gate_u<<<NN_+1,128>>>(x, st, out, out + OFF_LOSS);
}

// round 12
// speedup vs baseline: 3.0461x; 1.2624x over previous
#include <cuda_runtime.h>
#include <cuda_bf16.h>
#include <cuda_fp16.h>
#include <cstdint>
#include <math.h>

#define BB 16
#define NN_ 1024
#define EDIM 16
#define WINDOW 12
#define NNSQ (NN_*NN_)
#define BNN (BB*NNSQ)
#define HALF_BNN (BNN/2)
#define OFF_MASK (BB*NN_*64)
#define OFF_LOSS (OFF_MASK + BNN)
#define MASK_THR (-2.66352776f)   /* ln(1.4) - 3 */

// ---------------- scratch ----------------
__device__ float g_E[NN_*EDIM];
__device__ float g_Et[EDIM*NN_];
__device__ float g_EM[NNSQ];
__device__ float g_supports[NNSQ];
__device__ __half g_sh[(size_t)BNN];
__device__ uint32_t g_bits[BNN/32];
__device__ __half g_xh[(size_t)BB*NN_*128];
__device__ __half g_xl[(size_t)BB*NN_*128];
__device__ __half g_zh[(size_t)BB*NN_*64];
__device__ __half g_zl[(size_t)BB*NN_*64];
__device__ __half g_Wn_r[(size_t)NN_*256*128];
__device__ __half g_Wn_u[(size_t)NN_*256*64];
__device__ float g_bias_r[NN_*128];
__device__ float g_bias_u[NN_*64];
__device__ float g_xb[(size_t)BB*NN_*128];
__device__ float g_zs[(size_t)BB*NN_*64];
__device__ float g_rb[(size_t)BB*NN_*64];
__device__ float g_c2[(size_t)BB*NN_*64];
__device__ unsigned int g_pos[BB];
__device__ unsigned int g_kept[BB];

// ---------------- helpers ----------------
__device__ __forceinline__ float warpSum(float v){
  #pragma unroll
  for (int o=16;o;o>>=1) v += __shfl_xor_sync(0xffffffffu, v, o);
  return v;
}
__device__ __forceinline__ float blockSum(float v, float* red){
  int lane = threadIdx.x & 31, w = threadIdx.x >> 5;
  int nw = blockDim.x >> 5;
  v = warpSum(v);
  __syncthreads();
  if (lane==0) red[w] = v;
  __syncthreads();
  float r = (threadIdx.x < (unsigned)nw) ? red[threadIdx.x] : 0.0f;
  if (w==0) r = warpSum(r);
  if (threadIdx.x==0) red[0] = r;
  __syncthreads();
  return red[0];
}
__device__ __forceinline__ uint32_t rotl32(uint32_t x, int r){
  return __funnelshift_l(x, x, r);
}
__device__ __forceinline__ void threefry2x32(uint32_t k0, uint32_t k1,
                                             uint32_t& x0, uint32_t& x1){
  uint32_t ks0 = k0, ks1 = k1, ks2 = k0 ^ k1 ^ 0x1BD11BDAu;
  x0 += ks0; x1 += ks1;
  const int R0[4] = {13,15,26,6};
  const int R1[4] = {17,29,16,24};
  uint32_t ks[3] = {ks0, ks1, ks2};
  #pragma unroll
  for (int i=0;i<5;i++){
    #pragma unroll
    for (int j=0;j<4;j++){
      int r = (i & 1) ? R1[j] : R0[j];
      x0 += x1; x1 = rotl32(x1, r); x1 ^= x0;
    }
    x0 += ks[(i+1)%3];
    x1 += ks[(i+2)%3] + (uint32_t)(i+1);
  }
}
__device__ __forceinline__ void split_h16(float v, __half& h, __half& l){
  h = __float2half_rn(v);
  l = __float2half_rn(v - __half2float(h));
}
__device__ __forceinline__ uint32_t pack_h2(__half a, __half b){
  __half2 p(a, b);
  return *reinterpret_cast<uint32_t*>(&p);
}
__device__ __forceinline__ void ldsm4(uint32_t& r0,uint32_t& r1,uint32_t& r2,uint32_t& r3,
                                      const __half* p){
  uint32_t a = (uint32_t)__cvta_generic_to_shared(p);
  asm volatile("ldmatrix.sync.aligned.m8n8.x4.shared.b16 {%0,%1,%2,%3},[%4];"
    : "=r"(r0),"=r"(r1),"=r"(r2),"=r"(r3) : "r"(a));
}
__device__ __forceinline__ void ldsm2t(uint32_t& r0,uint32_t& r1, const __half* p){
  uint32_t a = (uint32_t)__cvta_generic_to_shared(p);
  asm volatile("ldmatrix.sync.aligned.m8n8.x2.trans.shared.b16 {%0,%1},[%2];"
    : "=r"(r0),"=r"(r1) : "r"(a));
}
__device__ __forceinline__ void mma16816h(float* c, const uint32_t* a, const uint32_t* b){
  asm volatile("mma.sync.aligned.m16n8k16.row.col.f32.f16.f16.f32 "
    "{%0,%1,%2,%3},{%4,%5,%6,%7},{%8,%9},{%0,%1,%2,%3};"
    : "+f"(c[0]),"+f"(c[1]),"+f"(c[2]),"+f"(c[3])
    : "r"(a[0]),"r"(a[1]),"r"(a[2]),"r"(a[3]), "r"(b[0]),"r"(b[1]));
}
__device__ __forceinline__ float prob_from_pos(){
  unsigned int tot = 0;
  #pragma unroll
  for (int i=0;i<BB;i++) tot += g_pos[i];
  float active = (float)tot / (float)BNN;
  return fminf(0.05f/active + 1e-8f, 1.0f);
}

// ---------------- kernels ----------------

__global__ void k_setup(const float* __restrict__ we, const int* __restrict__ itp){
  int tid = blockIdx.x*blockDim.x + threadIdx.x;
  float it = (float)itp[0];
  if (tid < NN_*EDIM){
    int d = tid & 15;
    int pair = d >> 1;
    float arg = (float)((double)(2*pair) * (-9.210340371976184/16.0));
    float div = expf(arg);
    float pe = (d & 1) ? cosf(it*div) : sinf(it*div);
    float e = we[tid] + pe;
    g_E[tid] = e;
    g_Et[d*NN_ + (tid>>4)] = e;
  }
  if (blockIdx.x==0 && threadIdx.x < 2*BB){
    if (threadIdx.x < BB) g_pos[threadIdx.x] = 0u;
    else                  g_kept[threadIdx.x-BB] = 0u;
  }
}

// [0,1024) em+bias, [1024,2048) supports.
__global__ void k_pre(const float* __restrict__ mp,
                      const float* __restrict__ bpr, const float* __restrict__ bpu){
  int g = blockIdx.x;
  if (g < NN_){
    int n = g;
    __shared__ float en[EDIM];
    if (threadIdx.x < EDIM) en[threadIdx.x] = g_E[n*EDIM+threadIdx.x];
    __syncthreads();
    int m0 = threadIdx.x*4;
    float4 a = make_float4(0.f,0.f,0.f,0.f);
    #pragma unroll
    for (int d=0; d<EDIM; d++){
      float4 mv = *(const float4*)&mp[d*NN_+m0];
      float e = en[d];
      a.x += e*mv.x; a.y += e*mv.y; a.z += e*mv.z; a.w += e*mv.w;
    }
    *(float4*)&g_EM[n*NN_+m0] = a;
    int o = threadIdx.x;
    if (o < 128){
      float br = 0.f;
      #pragma unroll
      for (int d=0; d<EDIM; d++) br += en[d]*bpr[d*128+o];
      g_bias_r[n*128+o] = br;
      if (o < 64){
        float bu = 0.f;
        #pragma unroll
        for (int d=0; d<EDIM; d++) bu += en[d]*bpu[d*64+o];
        g_bias_u[n*64+o] = bu;
      }
    }
  } else {
    int n = g - NN_;
    __shared__ float row[NN_];
    __shared__ float red[32];
    float en[EDIM];
    #pragma unroll
    for (int d=0; d<EDIM; d++) en[d] = g_E[n*EDIM+d];
    int m0 = threadIdx.x*4;
    float4 a = make_float4(0.f,0.f,0.f,0.f);
    #pragma unroll
    for (int d=0; d<EDIM; d++){
      float4 ev = *(const float4*)&g_Et[d*NN_+m0];
      float e = en[d];
      a.x += e*ev.x; a.y += e*ev.y; a.z += e*ev.z; a.w += e*ev.w;
    }
    a.x = __expf(fmaxf(a.x,0.f)); a.y = __expf(fmaxf(a.y,0.f));
    a.z = __expf(fmaxf(a.z,0.f)); a.w = __expf(fmaxf(a.w,0.f));
    *(float4*)&row[m0] = a;
    float s = blockSum(a.x+a.y+a.z+a.w, red);
    float inv = 1.0f/s;
    float4 r4 = *(float4*)&row[m0];
    r4.x *= inv; r4.y *= inv; r4.z *= inv; r4.w *= inv;
    *(float4*)&g_supports[n*NN_+m0] = r4;
  }
}

// prep: cat(x,state) -> fp16 hi/lo
__global__ void k_prep(const float* __restrict__ x, const float* __restrict__ st){
  int q = blockIdx.x*256 + threadIdx.x;
  int t4 = q*4;
  int j = t4 & 127; int bn = t4 >> 7;
  float4 v = (j < 64) ? *(const float4*)&x[(size_t)bn*64 + j]
                      : *(const float4*)&st[(size_t)bn*64 + (j-64)];
  __half h0,l0,h1,l1,h2,l2,h3,l3;
  split_h16(v.x,h0,l0); split_h16(v.y,h1,l1);
  split_h16(v.z,h2,l2); split_h16(v.w,h3,l3);
  *(uint2*)&g_xh[t4] = make_uint2(pack_h2(h0,h1), pack_h2(h2,h3));
  *(uint2*)&g_xl[t4] = make_uint2(pack_h2(l0,l1), pack_h2(l2,l3));
}

// Wn[n,i2,o] = sum_d E[n,d] * Wp[d,i2,o] -> fp16 (256 threads)
template<int OC>
__device__ __forceinline__ void wgen_body(const float* __restrict__ Wp, __half* __restrict__ Wn,
                                          int lb, float* Esm){
  constexpr int NQ = OC/4;
  constexpr int NI = 256/NQ;
  int n0 = (lb>>4)*64;
  int i20 = (lb&15)*16;
  int t = threadIdx.x;
  int oq = t % NQ, ig = t / NQ;
  for (int q=t; q<64*EDIM; q+=256)
    Esm[q] = g_E[(n0 + (q>>4))*EDIM + (q&15)];
  __syncthreads();
  for (int ii=ig; ii<16; ii+=NI){
    int i2 = i20+ii;
    float4 w[EDIM];
    #pragma unroll
    for (int d=0; d<EDIM; d++)
      w[d] = *(const float4*)&Wp[((size_t)d*256 + i2)*OC + oq*4];
    #pragma unroll 4
    for (int nn=0; nn<64; nn++){
      float4 a = make_float4(0.f,0.f,0.f,0.f);
      #pragma unroll
      for (int d=0; d<EDIM; d++){
        float e = Esm[nn*EDIM + d];
        a.x += e*w[d].x; a.y += e*w[d].y; a.z += e*w[d].z; a.w += e*w[d].w;
      }
      __half2 h01 = __floats2half2_rn(a.x, a.y);
      __half2 h23 = __floats2half2_rn(a.z, a.w);
      *(uint2*)&Wn[((size_t)(n0+nn)*256 + i2)*OC + oq*4] =
          make_uint2(*(uint32_t*)&h01, *(uint32_t*)&h23);
    }
  }
}

// Combined: every 3rd block wgen (512), rest supmask (1024 blocks x 16 rows, 2 passes).
__global__ void __launch_bounds__(256) k_sup_wgen(
    const float* __restrict__ T, const float* __restrict__ TP,
    const float* __restrict__ gamma, const float* __restrict__ beta,
    float* __restrict__ out_mask,
    const float* __restrict__ Wpr, const float* __restrict__ Wpu){
  __shared__ float Esm[64*EDIM];
  __shared__ float red[8][8];
  __shared__ float inv8[8];
  int bid = blockIdx.x;
  if (bid % 3 == 0){
    int lb = bid/3;
    if (lb < 256) wgen_body<128>(Wpr, g_Wn_r, lb, Esm);
    else          wgen_body<64>(Wpu, g_Wn_u, lb-256, Esm);
    return;
  }
  int id = bid - bid/3 - 1;                 // [0,1024)
  int b = id >> 6;
  int n0base = (id & 63)*16;
  extern __shared__ float sm[];
  float* Tsm = sm;                          // 48 KB
  int tid = threadIdx.x, lane = tid & 31, wrp = tid >> 5;
  {
    const float4* Tg = (const float4*)(T + (size_t)b*WINDOW*NN_);
    float4* T4 = (float4*)Tsm;
    #pragma unroll
    for (int i=0;i<12;i++) T4[tid + i*256] = Tg[tid + i*256];
  }
  __syncthreads();
  int m0 = tid*4;
  const float bni = 1.0f/sqrtf(1.0f + 1e-5f);
  unsigned int cnt = 0;
  #pragma unroll 1
  for (int half=0; half<2; half++){
    int n0 = n0base + half*8;
    float tg[8][4];
    #pragma unroll
    for (int r=0;r<8;r++){ tg[r][0]=0.f; tg[r][1]=0.f; tg[r][2]=0.f; tg[r][3]=0.f; }
    #pragma unroll
    for (int w=0; w<WINDOW; w++){
      float4 tw = *(float4*)&Tsm[w*NN_+m0];
      #pragma unroll
      for (int r=0;r<8;r++){
        float tvs = Tsm[w*NN_ + n0 + r];
        tg[r][0] += tvs*tw.x; tg[r][1] += tvs*tw.y;
        tg[r][2] += tvs*tw.z; tg[r][3] += tvs*tw.w;
      }
    }
    float psum[8];
    #pragma unroll
    for (int r=0;r<8;r++){
      tg[r][0] = __expf(fmaxf(tg[r][0],0.f));
      tg[r][1] = __expf(fmaxf(tg[r][1],0.f));
      tg[r][2] = __expf(fmaxf(tg[r][2],0.f));
      tg[r][3] = __expf(fmaxf(tg[r][3],0.f));
      psum[r] = (tg[r][0]+tg[r][1])+(tg[r][2]+tg[r][3]);
    }
    #pragma unroll
    for (int r=0;r<8;r++) psum[r] = warpSum(psum[r]);
    __syncthreads();
    if (lane==0){
      #pragma unroll
      for (int r=0;r<8;r++) red[r][wrp] = psum[r];
    }
    __syncthreads();
    if (tid < 8){
      float s = 0.f;
      #pragma unroll
      for (int k=0;k<8;k++) s += red[tid][k];
      inv8[tid] = 1.0f/s;
    }
    __syncthreads();
    float rm[8][4];
    #pragma unroll
    for (int r=0;r<8;r++){
      float4 t = *(const float4*)&g_EM[(size_t)(n0+r)*NN_ + m0];
      rm[r][0]=t.x; rm[r][1]=t.y; rm[r][2]=t.z; rm[r][3]=t.w;
    }
    #pragma unroll
    for (int w=0; w<WINDOW; w++){
      float4 tp = __ldg((const float4*)&TP[w*NN_+m0]);
      #pragma unroll
      for (int r=0;r<8;r++){
        float tvs = Tsm[w*NN_ + n0 + r];
        rm[r][0] += tvs*tp.x; rm[r][1] += tvs*tp.y;
        rm[r][2] += tvs*tp.z; rm[r][3] += tvs*tp.w;
      }
    }
    #pragma unroll
    for (int r=0;r<8;r++){
      int n = n0 + r;
      float sc = bni*gamma[n], bt = beta[n];
      float v0 = rm[r][0]*sc + bt, v1 = rm[r][1]*sc + bt;
      float v2 = rm[r][2]*sc + bt, v3 = rm[r][3]*sc + bt;
      uint32_t nib = (v0 > MASK_THR ? 1u:0u) | (v1 > MASK_THR ? 2u:0u)
                   | (v2 > MASK_THR ? 4u:0u) | (v3 > MASK_THR ? 8u:0u);
      float4 mk = make_float4(nib&1u?1.f:0.f, nib&2u?1.f:0.f, nib&4u?1.f:0.f, nib&8u?1.f:0.f);
      size_t idx = (size_t)b*NNSQ + (size_t)n*NN_ + m0;
      *(float4*)&out_mask[idx] = mk;
      float inv = inv8[r];
      float4 sp = *(const float4*)&g_supports[n*NN_+m0];
      sp.x = (sp.x + tg[r][0]*inv)*0.5f*mk.x;
      sp.y = (sp.y + tg[r][1]*inv)*0.5f*mk.y;
      sp.z = (sp.z + tg[r][2]*inv)*0.5f*mk.z;
      sp.w = (sp.w + tg[r][3]*inv)*0.5f*mk.w;
      *(uint2*)&g_sh[idx] = make_uint2(
          pack_h2(__float2half_rn(sp.x), __float2half_rn(sp.y)),
          pack_h2(__float2half_rn(sp.z), __float2half_rn(sp.w)));
      cnt += __popc(nib);
      uint32_t v = nib << ((lane&7)*4);
      v |= __shfl_xor_sync(0xffffffffu, v, 1);
      v |= __shfl_xor_sync(0xffffffffu, v, 2);
      v |= __shfl_xor_sync(0xffffffffu, v, 4);
      if ((lane&7)==0) g_bits[idx>>5] = v;
    }
  }
  __syncthreads();
  float fc = blockSum((float)cnt, (float*)red);
  if (tid==0) atomicAdd(&g_pos[b], (unsigned int)(fc + 0.5f));
}

// kept-count: standalone, overlapped on a forked stream.
__global__ void __launch_bounds__(256) k_kept(){
  __shared__ unsigned int cnt[BB];
  if (threadIdx.x < BB) cnt[threadIdx.x] = 0u;
  __syncthreads();
  float prob = prob_from_pos();
  int lane = threadIdx.x & 31;
  unsigned int base = blockIdx.x*1024u + threadIdx.x;
  #pragma unroll
  for (int k=0;k<4;k++){
    unsigned int t = base + (unsigned)k*256u;
    uint32_t x0 = t, x1 = t + (uint32_t)HALF_BNN;
    threefry2x32(0u, 42u, x0, x1);
    float u0 = __uint_as_float((x0>>9) | 0x3f800000u) - 1.0f;
    float u1 = __uint_as_float((x1>>9) | 0x3f800000u) - 1.0f;
    uint32_t w0 = g_bits[t>>5];
    uint32_t w1 = g_bits[(t + HALF_BNN)>>5];
    int b0 = (int)(t >> 20);
    bool keep0 = ((w0>>lane)&1u) && !(u0 < prob);
    bool keep1 = ((w1>>lane)&1u) && !(u1 < prob);
    unsigned bal0 = __ballot_sync(0xffffffffu, keep0);
    unsigned bal1 = __ballot_sync(0xffffffffu, keep1);
    if (lane==0){
      if (bal0) atomicAdd(&cnt[b0],   __popc(bal0));
      if (bal1) atomicAdd(&cnt[b0+8], __popc(bal1));
    }
  }
  __syncthreads();
  if (threadIdx.x < BB && cnt[threadIdx.x]) atomicAdd(&g_kept[threadIdx.x], cnt[threadIdx.x]);
}

// mma<128>: 512 threads, A=fp16 sup, B=fp16 hi/lo; double-buffered + prefetch.
__global__ void __launch_bounds__(512) k_mma128(const __half* __restrict__ Bh,
                                                const __half* __restrict__ Bl,
                                                float* __restrict__ C){
  constexpr int NO = 128;
  constexpr int BST = NO+8;
  constexpr int APITCH = 40;
  __shared__ __half Ash[2][128*APITCH];
  __shared__ __half Bsh[2][32*BST], Bsl[2][32*BST];
  int b = blockIdx.x >> 3;
  int m0 = (blockIdx.x & 7)*128;
  int w = threadIdx.x>>5, lane = threadIdx.x&31;
  int wm = (w>>1)*16;
  int wn = (w&1)*64;
  float acc[8][4];
  #pragma unroll
  for (int j=0;j<8;j++){ acc[j][0]=0.f; acc[j][1]=0.f; acc[j][2]=0.f; acc[j][3]=0.f; }
  const __half* Ahb = g_sh + (size_t)b*NNSQ;
  const __half* Bhb = Bh + (size_t)b*NN_*NO;
  const __half* Blb = Bl + (size_t)b*NN_*NO;
  int ar = threadIdx.x>>2, ac = threadIdx.x&3;
  int brr = threadIdx.x>>4, bc = threadIdx.x&15;
  uint4 pAh, pBh, pBl;
  auto ldtile = [&](int k0){
    pAh = *(const uint4*)&Ahb[(size_t)(m0+ar)*NN_ + k0 + ac*8];
    pBh = *(const uint4*)&Bhb[(size_t)(k0+brr)*NO + bc*8];
    pBl = *(const uint4*)&Blb[(size_t)(k0+brr)*NO + bc*8];
  };
  auto sttile = [&](int buf){
    *(uint4*)&Ash[buf][ar*APITCH + ac*8] = pAh;
    *(uint4*)&Bsh[buf][brr*BST + bc*8] = pBh;
    *(uint4*)&Bsl[buf][brr*BST + bc*8] = pBl;
  };
  ldtile(0);
  sttile(0);
  __syncthreads();
  #pragma unroll 1
  for (int t=0;t<32;t++){
    if (t+1 < 32) ldtile((t+1)*32);
    int buf = t & 1;
    #pragma unroll
    for (int kk=0; kk<2; kk++){
      uint32_t ah[4];
      int aoff = (wm + (lane&15))*APITCH + kk*16 + (lane>>4)*8;
      ldsm4(ah[0],ah[1],ah[2],ah[3], &Ash[buf][aoff]);
      #pragma unroll
      for (int j=0;j<8;j++){
        uint32_t bh[2], bl[2];
        int boff = (kk*16 + (lane&15))*BST + wn + j*8;
        ldsm2t(bh[0],bh[1], &Bsh[buf][boff]);
        ldsm2t(bl[0],bl[1], &Bsl[buf][boff]);
        mma16816h(acc[j], ah, bh);
        mma16816h(acc[j], ah, bl);
      }
    }
    if (t+1 < 32){
      __syncthreads();
      sttile((t+1)&1);
      __syncthreads();
    }
  }
  #pragma unroll
  for (int j=0;j<8;j++){
    int r0 = m0 + wm + (lane>>2);
    int c0 = wn + j*8 + (lane&3)*2;
    float* Cp = C + ((size_t)b*NN_ + r0)*NO + c0;
    Cp[0] = acc[j][0]; Cp[1] = acc[j][1];
    Cp[(size_t)8*NO] = acc[j][2]; Cp[(size_t)8*NO+1] = acc[j][3];
  }
}

// mma<64>: 256 threads, A=fp16 single, B=fp16 hi/lo.
__global__ void k_mma64(const __half* __restrict__ Bh,
                        const __half* __restrict__ Bl,
                        float* __restrict__ C){
  constexpr int NO = 64;
  constexpr int BST = NO+8;
  __shared__ __half Ash[128*40];
  __shared__ __half Bsh[32*BST], Bsl[32*BST];
  int b = blockIdx.y;
  int m0 = blockIdx.x*128;
  int w = threadIdx.x>>5, lane = threadIdx.x&31;
  int wm = w*16;
  float acc[8][4];
  #pragma unroll
  for (int j=0;j<8;j++){ acc[j][0]=0.f; acc[j][1]=0.f; acc[j][2]=0.f; acc[j][3]=0.f; }
  const __half* Ahb = g_sh + (size_t)b*NNSQ;
  const __half* Bhb = Bh + (size_t)b*NN_*NO;
  const __half* Blb = Bl + (size_t)b*NN_*NO;
  for (int k0=0;k0<NN_;k0+=32){
    #pragma unroll
    for (int i = threadIdx.x; i<512; i+=256){
      int r = i>>2, c = i&3;
      *(uint4*)&Ash[r*40 + c*8] = *(const uint4*)&Ahb[(size_t)(m0+r)*NN_ + k0 + c*8];
    }
    {
      int i = threadIdx.x;
      int r = i>>3, c = i&7;
      *(uint4*)&Bsh[r*BST + c*8] = *(const uint4*)&Bhb[(size_t)(k0+r)*NO + c*8];
      *(uint4*)&Bsl[r*BST + c*8] = *(const uint4*)&Blb[(size_t)(k0+r)*NO + c*8];
    }
    __syncthreads();
    #pragma unroll
    for (int kk=0; kk<2; kk++){
      uint32_t ah[4];
      int aoff = (wm + (lane&15))*40 + kk*16 + (lane>>4)*8;
      ldsm4(ah[0],ah[1],ah[2],ah[3], &Ash[aoff]);
      #pragma unroll
      for (int j=0;j<8;j++){
        uint32_t bh[2], bl[2];
        int boff = (kk*16 + (lane&15))*BST + j*8;
        ldsm2t(bh[0],bh[1], &Bsh[boff]);
        ldsm2t(bl[0],bl[1], &Bsl[boff]);
        mma16816h(acc[j], ah, bh);
        mma16816h(acc[j], ah, bl);
      }
    }
    __syncthreads();
  }
  #pragma unroll
  for (int j=0;j<8;j++){
    int r0 = m0 + wm + (lane>>2);
    int c0 = j*8 + (lane&3)*2;
    float* Cp = C + ((size_t)b*NN_ + r0)*NO + c0;
    Cp[0] = acc[j][0]; Cp[1] = acc[j][1];
    Cp[(size_t)8*NO] = acc[j][2]; Cp[(size_t)8*NO+1] = acc[j][3];
  }
}

// r-gate: 4b x 4o register tile; W fp16; 4-way batched loads (MLP).
__global__ void __launch_bounds__(128) k_gate_r(const float* __restrict__ x,
                                                const float* __restrict__ st){
  int n = blockIdx.x;
  __shared__ float Xg[256*20];
  int t = threadIdx.x;
  for (int q=t; q<4096; q+=128){
    int b = q>>8, i = q&255;
    float v;
    if (i < 64)       v = x[((size_t)b*NN_+n)*64 + i];
    else if (i < 128) v = st[((size_t)b*NN_+n)*64 + (i-64)];
    else              v = g_xb[((size_t)b*NN_+n)*128 + (i-128)];
    Xg[i*20 + b] = v;
  }
  __syncthreads();
  int og = t>>2, bg = t&3;
  int o0 = og*4, b0 = bg*4;
  float acc[4][4] = {};
  const __half* W = g_Wn_r + (size_t)n*256*128 + o0;
  #pragma unroll 1
  for (int i=0;i<256;i+=4){
    uint2 wv[4]; float4 xv[4];
    #pragma unroll
    for (int u=0;u<4;u++){
      wv[u] = *(const uint2*)&W[(size_t)(i+u)*128];
      xv[u] = *(float4*)&Xg[(i+u)*20 + b0];
    }
    #pragma unroll
    for (int u=0;u<4;u++){
      float2 f01 = __half22float2(*(__half2*)&wv[u].x);
      float2 f23 = __half22float2(*(__half2*)&wv[u].y);
      float xs[4] = {xv[u].x,xv[u].y,xv[u].z,xv[u].w};
      float ws[4] = {f01.x,f01.y,f23.x,f23.y};
      #pragma unroll
      for (int bi=0;bi<4;bi++)
        #pragma unroll
        for (int oi=0;oi<4;oi++)
          acc[bi][oi] += xs[bi]*ws[oi];
    }
  }
  float4 bias = *(const float4*)&g_bias_r[n*128 + o0];
  float bs[4] = {bias.x,bias.y,bias.z,bias.w};
  #pragma unroll
  for (int bi=0;bi<4;bi++){
    int b = b0+bi;
    size_t idx = ((size_t)b*NN_+n)*64;
    #pragma unroll
    for (int oi=0;oi<4;oi++){
      int o = o0+oi;
      float g = 1.0f/(1.0f+__expf(-(acc[bi][oi]+bs[oi])));
      if (o < 64){
        float zsv = g * st[idx + o];
        g_zs[idx + o] = zsv;
        __half h, l; split_h16(zsv, h, l);
        g_zh[idx + o] = h; g_zl[idx + o] = l;
      } else {
        g_rb[idx + (o-64)] = g;
      }
    }
  }
}

// u-gate + GRU output; block 1024 computes mask_loss. W fp16; 4-way batched loads.
__global__ void __launch_bounds__(128) k_gate_u(const float* __restrict__ x,
                                                const float* __restrict__ st,
                                                float* __restrict__ out_h,
                                                float* __restrict__ out_loss){
  if (blockIdx.x == NN_){
    if (threadIdx.x < BB){
      unsigned int tot = 0;
      #pragma unroll
      for (int i=0;i<BB;i++) tot += g_pos[i];
      float active = (float)tot / (float)BNN;
      float addend = fmaxf(0.05f/active - 1.0f, 0.0f);
      int b = threadIdx.x;
      out_loss[b] = (float)g_kept[b] / ((float)g_pos[b] + 1e-8f) + addend;
    }
    return;
  }
  int n = blockIdx.x;
  __shared__ float Xg[256*20];
  int t = threadIdx.x;
  for (int q=t; q<4096; q+=128){
    int b = q>>8, i = q&255;
    float v;
    if (i < 64)       v = x[((size_t)b*NN_+n)*64 + i];
    else if (i < 128) v = g_zs[((size_t)b*NN_+n)*64 + (i-64)];
    else if (i < 192) v = g_xb[((size_t)b*NN_+n)*128 + (i-128)];
    else              v = g_c2[((size_t)b*NN_+n)*64 + (i-192)];
    Xg[i*20 + b] = v;
  }
  __syncthreads();
  int og = t>>3, bg = t&7;
  int o0 = og*4, b0 = bg*2;
  float acc[2][4] = {};
  const __half* W = g_Wn_u + (size_t)n*256*64 + o0;
  #pragma unroll 1
  for (int i=0;i<256;i+=4){
    uint2 wv[4]; float2 xv[4];
    #pragma unroll
    for (int u=0;u<4;u++){
      wv[u] = *(const uint2*)&W[(size_t)(i+u)*64];
      xv[u] = *(float2*)&Xg[(i+u)*20 + b0];
    }
    #pragma unroll
    for (int u=0;u<4;u++){
      float2 f01 = __half22float2(*(__half2*)&wv[u].x);
      float2 f23 = __half22float2(*(__half2*)&wv[u].y);
      float xs[2] = {xv[u].x,xv[u].y};
      float ws[4] = {f01.x,f01.y,f23.x,f23.y};
      #pragma unroll
      for (int bi=0;bi<2;bi++)
        #pragma unroll
        for (int oi=0;oi<4;oi++)
          acc[bi][oi] += xs[bi]*ws[oi];
    }
  }
  float4 bias = *(const float4*)&g_bias_u[n*64 + o0];
  float bs[4] = {bias.x,bias.y,bias.z,bias.w};
  #pragma unroll
  for (int bi=0;bi<2;bi++){
    int b = b0+bi;
    size_t idx = ((size_t)b*NN_+n)*64;
    #pragma unroll
    for (int oi=0;oi<4;oi++){
      int o = o0+oi;
      float hc = tanhf(acc[bi][oi]+bs[oi]);
      float r = g_rb[idx + o];
      float sv = st[idx + o];
      out_h[idx + o] = r*sv + (1.0f-r)*hc;
    }
  }
}

// ---------------- launch ----------------
extern "C" void kernel_launch(void* const* d_in, const int* in_sizes, int n_in,
                              void* d_out, int out_size){
  const float* x    = (const float*)d_in[0];
  const float* st   = (const float*)d_in[1];
  const float* we   = (const float*)d_in[2];
  const float* T    = (const float*)d_in[3];
  const float* Wpr  = (const float*)d_in[4];
  const float* bpr  = (const float*)d_in[5];
  const float* Wpu  = (const float*)d_in[6];
  const float* bpu  = (const float*)d_in[7];
  const float* mp   = (const float*)d_in[8];
  const float* tp   = (const float*)d_in[9];
  const float* gmm  = (const float*)d_in[10];
  const float* bta  = (const float*)d_in[11];
  const int*   itp  = (const int*)d_in[12];
  float* out = (float*)d_out;
  float* out_mask = out + OFF_MASK;

  static __half *xh_p=nullptr, *xl_p=nullptr, *zh_p=nullptr, *zl_p=nullptr;
  static float *xb_p=nullptr, *c2_p=nullptr;
  static cudaStream_t s2 = nullptr;
  static cudaEvent_t evFork = nullptr, evJoin = nullptr;
  if (!xh_p){
    cudaGetSymbolAddress((void**)&xh_p, g_xh);
    cudaGetSymbolAddress((void**)&xl_p, g_xl);
    cudaGetSymbolAddress((void**)&zh_p, g_zh);
    cudaGetSymbolAddress((void**)&zl_p, g_zl);
    cudaGetSymbolAddress((void**)&xb_p, g_xb);
    cudaGetSymbolAddress((void**)&c2_p, g_c2);
    size_t smem_sup = (size_t)(WINDOW*NN_)*sizeof(float);   // 48 KB
    cudaFuncSetAttribute(k_sup_wgen, cudaFuncAttributeMaxDynamicSharedMemorySize, (int)smem_sup);
    cudaStreamCreateWithFlags(&s2, cudaStreamNonBlocking);
    cudaEventCreateWithFlags(&evFork, cudaEventDisableTiming);
    cudaEventCreateWithFlags(&evJoin, cudaEventDisableTiming);
  }
  size_t smem_sup = (size_t)(WINDOW*NN_)*sizeof(float);

  k_setup<<<64,256>>>(we, itp);                            // 1
  k_pre<<<2048,256>>>(mp, bpr, bpu);                       // 2
  k_prep<<<2048,256>>>(x, st);                             // 3
  k_sup_wgen<<<1536,256,smem_sup>>>(T, tp, gmm, bta, out_mask, Wpr, Wpu); // 4 (profiled)
  cudaEventRecord(evFork, 0);
  cudaStreamWaitEvent(s2, evFork, 0);
  k_mma128<<<128,512>>>(xh_p, xl_p, xb_p);                 // 5
  k_kept<<<8192,256,0,s2>>>();                             // (s2)
  k_gate_r<<<NN_,128>>>(x, st);                            // 6
  k_mma64<<<dim3(8,16),256>>>(zh_p, zl_p, c2_p);           // 7
  cudaEventRecord(evJoin, s2);
  cudaStreamWaitEvent(0, evJoin, 0);
  k_gate_u<<<NN_+1,128>>>(x, st, out, out + OFF_LOSS);     // 8
}